// round 7
// baseline (speedup 1.0000x reference)
#include <cuda_runtime.h>
#include <math.h>

#define Bc 16
#define Lc 128
#define Dc 8
#define Hc 128
#define NLc 2

// ---------------- scratch (static device globals; no allocation) ----------------
__device__ __align__(16) float g_ts[Bc*Lc];
__device__ __align__(16) float g_h[Bc*Lc*Hc];
__device__ __align__(16) float g_sa[Bc*Lc*Hc];
__device__ __align__(16) float g_da[Bc*Lc*Hc];
__device__ __align__(16) float g_sm[Bc*Lc*Hc];
__device__ __align__(16) float g_aggpre[Bc*Lc*Hc];
__device__ __align__(16) float g_Wca[NLc*Hc*Hc];
__device__ __align__(16) float g_Wcm[NLc*Hc*Hc];
__device__ __align__(16) float g_ba[NLc*Hc];
__device__ __align__(16) float g_bm[NLc*Hc];

// ---------------- packed f32x2 helpers ----------------
__device__ __forceinline__ void fma2(unsigned long long &acc, unsigned long long a, unsigned long long b){
    asm("fma.rn.f32x2 %0, %1, %2, %0;" : "+l"(acc) : "l"(a), "l"(b));
}
__device__ __forceinline__ unsigned long long pack2(float lo, float hi){
    unsigned long long r; asm("mov.b64 %0, {%1,%2};" : "=l"(r) : "f"(lo), "f"(hi)); return r;
}
__device__ __forceinline__ void unpack2(unsigned long long v, float &lo, float &hi){
    asm("mov.b64 {%0,%1}, %2;" : "=f"(lo), "=f"(hi) : "l"(v));
}
__device__ __forceinline__ void cp16(void* dst_smem, const void* src){
    unsigned sdst = (unsigned)__cvta_generic_to_shared(dst_smem);
    asm volatile("cp.async.cg.shared.global [%0], [%1], 16;" :: "r"(sdst), "l"(src));
}
// HW tanh approximation (MUFU.TANH, sm_75+): max abs err ~5e-4, plenty for 1e-3 gate.
__device__ __forceinline__ float tanh_fast(float x){
    float r; asm("tanh.approx.f32 %0, %1;" : "=f"(r) : "f"(x)); return r;
}

// ---------------- cumsum of ts ----------------
__global__ void k_ts(const float* __restrict__ hist){
    int b = threadIdx.x;
    if(b < Bc){
        float c = 0.f;
        for(int t = 0; t < Lc; t++){
            float v = hist[(b*Lc+t)*Dc + 5];
            c += fmaxf(v, 0.f);
            g_ts[b*Lc+t] = c;
        }
    }
}

// ---------------- folded weights: Wc = We2 @ Wa1_e / Wm1_e (plus bias rows) ----------------
__global__ void k_prepwb(const float* __restrict__ We2, const float* __restrict__ be2,
                         const float* __restrict__ Wa1, const float* __restrict__ Wm1,
                         const float* __restrict__ ba1, const float* __restrict__ bm1){
    int l = blockIdx.x / 129, kk = blockIdx.x % 129;
    int c = threadIdx.x;
    __shared__ float ws[Hc];
    if(kk < Hc) ws[c] = We2[l*Hc*Hc + kk*Hc + c];
    else        ws[c] = be2[l*Hc + c];
    __syncthreads();
    const float* wa = Wa1 + l*3*Hc*Hc + 2*Hc*Hc;
    const float* wm = Wm1 + l*2*Hc*Hc + Hc*Hc;
    float sa = 0.f, sm = 0.f;
    #pragma unroll 4
    for(int r = 0; r < Hc; r++){ float w = ws[r]; sa += w*wa[r*Hc + c]; sm += w*wm[r*Hc + c]; }
    if(kk < Hc){
        g_Wca[(l*Hc + kk)*Hc + c] = sa;
        g_Wcm[(l*Hc + kk)*Hc + c] = sm;
    } else {
        g_ba[l*Hc + c] = sa + ba1[l*Hc + c];
        g_bm[l*Hc + c] = sm + bm1[l*Hc + c];
    }
}

// ---------------- h0 (16 rows per block) + sa/da/sm for layer 0 ----------------
__global__ __launch_bounds__(256)
void k_h0s(const float* __restrict__ hist, const float* __restrict__ mask,
           const float* __restrict__ Wp, const float* __restrict__ bp,
           const float* __restrict__ Wa1, const float* __restrict__ Wm1){
    int row0 = blockIdx.x * 16;
    int tid = threadIdx.x;
    int c = tid & 127, ty = tid >> 7;
    __shared__ float xs[16*Dc], hs[16*Hc], vmsh[16];
    if(tid < 128) xs[tid] = hist[(size_t)row0*Dc + tid];
    if(tid < 16)  vmsh[tid] = mask[row0 + tid] > 0.f ? 1.f : 0.f;
    __syncthreads();
    float acc[8];
    #pragma unroll
    for(int p = 0; p < 8; p++) acc[p] = bp[c];
    #pragma unroll
    for(int d = 0; d < Dc; d++){
        float w = Wp[d*Hc + c];
        #pragma unroll
        for(int p = 0; p < 8; p++) acc[p] += xs[(ty*8+p)*Dc + d] * w;
    }
    #pragma unroll
    for(int p = 0; p < 8; p++){
        int r = ty*8 + p;
        float h = acc[p] * vmsh[r];
        hs[r*Hc + c] = h;
        g_h[(size_t)(row0+r)*Hc + c] = h;
    }
    __syncthreads();
    const float* was = Wa1;
    const float* wad = was + Hc*Hc;
    const float* wms = Wm1;
    float aa[8], dd[8], mm[8];
    #pragma unroll
    for(int p = 0; p < 8; p++){ aa[p]=0.f; dd[p]=0.f; mm[p]=0.f; }
    #pragma unroll 4
    for(int k = 0; k < Hc; k++){
        float w1 = was[k*Hc + c], w2 = wad[k*Hc + c], w3 = wms[k*Hc + c];
        #pragma unroll
        for(int p = 0; p < 8; p++){
            float h = hs[(ty*8+p)*Hc + k];
            aa[p] += h*w1; dd[p] += h*w2; mm[p] += h*w3;
        }
    }
    #pragma unroll
    for(int p = 0; p < 8; p++){
        size_t r = (size_t)(row0 + ty*8 + p)*Hc + c;
        g_sa[r] = aa[p]; g_da[r] = dd[p]; g_sm[r] = mm[p];
    }
}

// ---------------- main fused kernel: 1024 threads, 4jx8c register-blocked GEMMs ----------------
extern __shared__ float dsm[];   // Ts 64KB | Wa 64KB | Wm 64KB

__global__ __launch_bounds__(1024, 1)
void k_main6(int l, const float* __restrict__ hist, const float* __restrict__ mask,
             const float* __restrict__ We1, const float* __restrict__ be1,
             const float* __restrict__ wa2, const float* __restrict__ ba2){
    float* Ts = dsm;                 // [k][j]
    float* Wa = dsm + 16384;         // [k][c]
    float* Wm = dsm + 32768;         // [k][c]
    __shared__ float we1s[4*Hc], be1s[Hc], sab[Hc], smb[Hc], wa2s[Hc];
    __shared__ float att[Lc], wsoft[Lc], red[8];

    int bi = blockIdx.x;
    int b = bi >> 7, i = bi & 127;
    int tid = threadIdx.x;
    int j = tid & 127, kg = tid >> 7;   // kg in 0..7

    // async copy both folded W matrices (1024 threads x 16B x 4 passes each)
    const float* gwa = g_Wca + l*Hc*Hc;
    const float* gwm = g_Wcm + l*Hc*Hc;
    #pragma unroll
    for(int q = 0; q < 4; q++){
        cp16(Wa + q*4096 + tid*4, gwa + q*4096 + tid*4);
        cp16(Wm + q*4096 + tid*4, gwm + q*4096 + tid*4);
    }
    asm volatile("cp.async.commit_group;");

    if(tid < 128){
        #pragma unroll
        for(int q = 0; q < 4; q++) we1s[q*Hc + tid] = We1[l*4*Hc + q*Hc + tid];
        be1s[tid] = be1[l*Hc + tid];
        sab[tid]  = g_sa[(size_t)bi*Hc + tid] + g_ba[l*Hc + tid];
        smb[tid]  = g_sm[(size_t)bi*Hc + tid] + g_bm[l*Hc + tid];
        wa2s[tid] = wa2[l*Hc + tid];
    }

    // edge features for this thread's j (j = tid&127)
    const float* hb_ = hist + (size_t)b*Lc*Dc;
    {
        float lat_i = hb_[i*Dc + 0], lon_i = hb_[i*Dc + 1], src_i = hb_[i*Dc + 6];
        float ts_i = g_ts[b*Lc + i];
        float latj = hb_[j*Dc + 0], lonj = hb_[j*Dc + 1], srcj = hb_[j*Dc + 6];
        float tsj = g_ts[b*Lc + j];
        float dl = lat_i - latj, dn = lon_i - lonj;
        float dist = sqrtf(dl*dl + dn*dn + 1e-8f);
        float dtv = fabsf(ts_i - tsj) * (1.f/300.f);
        float ssv = (src_i == srcj) ? 1.f : 0.f;
        float diag = (j == i) ? 1.f : 0.f;
        __syncthreads();   // we1s/be1s ready

        // T build: thread owns column j, kg selects 16 k rows
        #pragma unroll 8
        for(int kk = 0; kk < 16; kk++){
            int k = kg*16 + kk;
            float v = dist*we1s[k] + dtv*we1s[Hc+k] + ssv*we1s[2*Hc+k] + diag*we1s[3*Hc+k] + be1s[k];
            Ts[k*Lc + j] = fmaxf(v, 0.f);
        }
    }
    asm volatile("cp.async.wait_group 0;");
    __syncthreads();   // Ts + W ready

    // GEMM: group g (0=attention/Wa, 1=message/Wm)
    // thread: 4 j (jt..jt+3), 8 c ({ca..ca+3, cb..cb+3})
    int g  = tid >> 9;
    int t  = tid & 511;
    int tx = t & 15, ty = t >> 4;       // ty in 0..31
    int jt = ty*4;
    int ca = tx*4, cb = 64 + tx*4;
    const float* Wg = g ? Wm : Wa;

    unsigned long long acc[16];
    #pragma unroll
    for(int q = 0; q < 16; q++) acc[q] = 0ull;

    #pragma unroll 2
    for(int k = 0; k < Hc; k++){
        float4 t0 = *(const float4*)&Ts[k*Lc + jt];
        const float* wr = &Wg[k*Hc];
        float4 w0 = *(const float4*)(wr + ca);
        float4 w1 = *(const float4*)(wr + cb);
        unsigned long long wp0 = pack2(w0.x,w0.y), wp1 = pack2(w0.z,w0.w);
        unsigned long long wp2 = pack2(w1.x,w1.y), wp3 = pack2(w1.z,w1.w);
        unsigned long long tp;
        tp = pack2(t0.x,t0.x); fma2(acc[0],tp,wp0);  fma2(acc[1],tp,wp1);  fma2(acc[2],tp,wp2);  fma2(acc[3],tp,wp3);
        tp = pack2(t0.y,t0.y); fma2(acc[4],tp,wp0);  fma2(acc[5],tp,wp1);  fma2(acc[6],tp,wp2);  fma2(acc[7],tp,wp3);
        tp = pack2(t0.z,t0.z); fma2(acc[8],tp,wp0);  fma2(acc[9],tp,wp1);  fma2(acc[10],tp,wp2); fma2(acc[11],tp,wp3);
        tp = pack2(t0.w,t0.w); fma2(acc[12],tp,wp0); fma2(acc[13],tp,wp1); fma2(acc[14],tp,wp2); fma2(acc[15],tp,wp3);
    }

    // ---------------- attention epilogue (group 0) ----------------
    if(g == 0){
        const float* dab = g_da + (size_t)b*Lc*Hc;
        #pragma unroll
        for(int jj = 0; jj < 4; jj++){
            int jr = jt + jj;
            float4 d0 = *(const float4*)&dab[(size_t)jr*Hc + ca];
            float4 d1 = *(const float4*)&dab[(size_t)jr*Hc + cb];
            float u0,u1,u2,u3,u4,u5,u6,u7;
            unpack2(acc[jj*4+0], u0, u1); unpack2(acc[jj*4+1], u2, u3);
            unpack2(acc[jj*4+2], u4, u5); unpack2(acc[jj*4+3], u6, u7);
            float s = 0.f;
            s += wa2s[ca+0]*tanh_fast(sab[ca+0] + d0.x + u0);
            s += wa2s[ca+1]*tanh_fast(sab[ca+1] + d0.y + u1);
            s += wa2s[ca+2]*tanh_fast(sab[ca+2] + d0.z + u2);
            s += wa2s[ca+3]*tanh_fast(sab[ca+3] + d0.w + u3);
            s += wa2s[cb+0]*tanh_fast(sab[cb+0] + d1.x + u4);
            s += wa2s[cb+1]*tanh_fast(sab[cb+1] + d1.y + u5);
            s += wa2s[cb+2]*tanh_fast(sab[cb+2] + d1.z + u6);
            s += wa2s[cb+3]*tanh_fast(sab[cb+3] + d1.w + u7);
            #pragma unroll
            for(int m = 8; m > 0; m >>= 1) s += __shfl_xor_sync(0xffffffffu, s, m);
            if(tx == 0) att[jr] = s;
        }
    }
    __syncthreads();

    // ---------------- softmax over j (first 128 threads) ----------------
    const float inv = 0.088388347648318440550f;   // 1/sqrt(128)
    float vldj = (mask[b*Lc + j] > 0.f) ? 1.f : 0.f;
    float vi   = (mask[b*Lc + i] > 0.f) ? 1.f : 0.f;
    float sc = -1e9f, e = 0.f;
    if(tid < 128){
        float a = (att[tid] + ba2[l]) * inv;
        bool ok = (vldj > 0.f) && (vi > 0.f);
        sc = ok ? a : -1e9f;
        float m = sc;
        #pragma unroll
        for(int s2 = 16; s2 > 0; s2 >>= 1) m = fmaxf(m, __shfl_xor_sync(0xffffffffu, m, s2));
        if((tid & 31) == 0) red[tid >> 5] = m;
    }
    __syncthreads();
    float bmax = fmaxf(fmaxf(red[0], red[1]), fmaxf(red[2], red[3]));
    if(tid < 128){
        e = expf(sc - bmax);
        float s2 = e;
        #pragma unroll
        for(int m = 16; m > 0; m >>= 1) s2 += __shfl_xor_sync(0xffffffffu, s2, m);
        if((tid & 31) == 0) red[4 + (tid >> 5)] = s2;
    }
    __syncthreads();
    if(tid < 128){
        float tot = red[4]+red[5]+red[6]+red[7];
        wsoft[tid] = e / tot;
    }
    __syncthreads();

    // ---------------- message epilogue (group 1): weighted relu aggregation ----------------
    float* su = dsm;   // 32 ty-rows x 128 c partials (Ts region is dead now)
    if(g == 1){
        float agA[4], agB[4];
        #pragma unroll
        for(int p = 0; p < 4; p++){ agA[p] = 0.f; agB[p] = 0.f; }
        #pragma unroll
        for(int jj = 0; jj < 4; jj++){
            float wj = wsoft[jt + jj];
            float u0,u1,u2,u3,u4,u5,u6,u7;
            unpack2(acc[jj*4+0], u0, u1); unpack2(acc[jj*4+1], u2, u3);
            unpack2(acc[jj*4+2], u4, u5); unpack2(acc[jj*4+3], u6, u7);
            agA[0] += wj * fmaxf(smb[ca+0] + u0, 0.f);
            agA[1] += wj * fmaxf(smb[ca+1] + u1, 0.f);
            agA[2] += wj * fmaxf(smb[ca+2] + u2, 0.f);
            agA[3] += wj * fmaxf(smb[ca+3] + u3, 0.f);
            agB[0] += wj * fmaxf(smb[cb+0] + u4, 0.f);
            agB[1] += wj * fmaxf(smb[cb+1] + u5, 0.f);
            agB[2] += wj * fmaxf(smb[cb+2] + u6, 0.f);
            agB[3] += wj * fmaxf(smb[cb+3] + u7, 0.f);
        }
        #pragma unroll
        for(int p = 0; p < 4; p++){
            su[ty*Hc + ca + p] = agA[p];
            su[ty*Hc + cb + p] = agB[p];
        }
    }
    __syncthreads();
    if(tid < 128){
        float s = 0.f;
        #pragma unroll 8
        for(int t2 = 0; t2 < 32; t2++) s += su[t2*Hc + tid];
        g_aggpre[(size_t)bi*Hc + tid] = s;
    }
}

// ---------------- epilogue per 16 rows ----------------
__global__ __launch_bounds__(256)
void k_post2(int l, int has_next, const float* __restrict__ mask,
             const float* __restrict__ Wm2, const float* __restrict__ bm2,
             const float* __restrict__ Wo1, const float* __restrict__ bo1,
             const float* __restrict__ Wo2, const float* __restrict__ bo2,
             const float* __restrict__ lng, const float* __restrict__ lnb,
             const float* __restrict__ Wa1, const float* __restrict__ Wm1){
    int row0 = blockIdx.x * 16;
    int tid = threadIdx.x;
    int c = tid & 127, ty = tid >> 7;
    __shared__ float hs[16*Hc], as_[16*Hc], ag[16*Hc], op1[16*Hc];
    __shared__ float mu[16], rsd[16], vmsh[16];

    #pragma unroll
    for(int q = 0; q < 8; q++){
        int idx = q*256 + tid;
        hs[idx]  = g_h[(size_t)row0*Hc + idx];
        as_[idx] = g_aggpre[(size_t)row0*Hc + idx];
    }
    if(tid < 16) vmsh[tid] = mask[row0 + tid] > 0.f ? 1.f : 0.f;
    __syncthreads();

    float acc[8];
    const float* wm2 = Wm2 + l*Hc*Hc;
    #pragma unroll
    for(int p = 0; p < 8; p++) acc[p] = bm2[l*Hc + c];
    #pragma unroll 4
    for(int k = 0; k < Hc; k++){
        float w = wm2[k*Hc + c];
        #pragma unroll
        for(int p = 0; p < 8; p++) acc[p] += as_[(ty*8+p)*Hc + k] * w;
    }
    #pragma unroll
    for(int p = 0; p < 8; p++) ag[(ty*8+p)*Hc + c] = acc[p];
    __syncthreads();

    const float* wo1h = Wo1 + l*2*Hc*Hc;
    const float* wo1a = wo1h + Hc*Hc;
    #pragma unroll
    for(int p = 0; p < 8; p++) acc[p] = bo1[l*Hc + c];
    #pragma unroll 4
    for(int k = 0; k < Hc; k++){
        float w1 = wo1h[k*Hc + c], w2 = wo1a[k*Hc + c];
        #pragma unroll
        for(int p = 0; p < 8; p++)
            acc[p] += hs[(ty*8+p)*Hc + k]*w1 + ag[(ty*8+p)*Hc + k]*w2;
    }
    #pragma unroll
    for(int p = 0; p < 8; p++) op1[(ty*8+p)*Hc + c] = fmaxf(acc[p], 0.f);
    __syncthreads();

    const float* wo2 = Wo2 + l*Hc*Hc;
    #pragma unroll
    for(int p = 0; p < 8; p++) acc[p] = bo2[l*Hc + c];
    #pragma unroll 4
    for(int k = 0; k < Hc; k++){
        float w = wo2[k*Hc + c];
        #pragma unroll
        for(int p = 0; p < 8; p++) acc[p] += op1[(ty*8+p)*Hc + k] * w;
    }
    #pragma unroll
    for(int p = 0; p < 8; p++){
        int r = ty*8 + p;
        ag[r*Hc + c] = hs[r*Hc + c] + acc[p];
    }
    __syncthreads();

    {
        int row = tid >> 4, l16 = tid & 15;
        float s = 0.f, s2 = 0.f;
        #pragma unroll
        for(int q = 0; q < 8; q++){
            float v = ag[row*Hc + l16 + q*16];
            s += v; s2 += v*v;
        }
        #pragma unroll
        for(int m = 8; m > 0; m >>= 1){
            s  += __shfl_xor_sync(0xffffffffu, s, m);
            s2 += __shfl_xor_sync(0xffffffffu, s2, m);
        }
        if(l16 == 0){
            float m_ = s * (1.f/128.f);
            mu[row] = m_;
            rsd[row] = rsqrtf(s2 * (1.f/128.f) - m_*m_ + 1e-5f);
        }
    }
    __syncthreads();
    const float* lg = lng + l*Hc;
    const float* lb = lnb + l*Hc;
    #pragma unroll
    for(int p = 0; p < 8; p++){
        int r = ty*8 + p;
        float x = ag[r*Hc + c];
        float hn = ((x - mu[r]) * rsd[r] * lg[c] + lb[c]) * vmsh[r];
        g_h[(size_t)(row0+r)*Hc + c] = hn;
        hs[r*Hc + c] = hn;
    }

    if(has_next){
        __syncthreads();
        int ln = l + 1;
        const float* was = Wa1 + ln*3*Hc*Hc;
        const float* wad = was + Hc*Hc;
        const float* wms = Wm1 + ln*2*Hc*Hc;
        float aa[8], dd[8], mm[8];
        #pragma unroll
        for(int p = 0; p < 8; p++){ aa[p]=0.f; dd[p]=0.f; mm[p]=0.f; }
        #pragma unroll 4
        for(int k = 0; k < Hc; k++){
            float w1 = was[k*Hc + c], w2 = wad[k*Hc + c], w3 = wms[k*Hc + c];
            #pragma unroll
            for(int p = 0; p < 8; p++){
                float h = hs[(ty*8+p)*Hc + k];
                aa[p] += h*w1; dd[p] += h*w2; mm[p] += h*w3;
            }
        }
        #pragma unroll
        for(int p = 0; p < 8; p++){
            size_t r = (size_t)(row0 + ty*8 + p)*Hc + c;
            g_sa[r] = aa[p]; g_da[r] = dd[p]; g_sm[r] = mm[p];
        }
    }
}

// ---------------- decoder ----------------
__global__ void k_dec(const float* __restrict__ hist, const float* __restrict__ mask,
                      const float* __restrict__ hg, const float* __restrict__ hb,
                      const float* __restrict__ Wh1, const float* __restrict__ bh1,
                      const float* __restrict__ Wh2, const float* __restrict__ bh2,
                      float* __restrict__ out){
    int b = blockIdx.x; int t = threadIdx.x;
    __shared__ float x[136], xn[136], hid[Hc];
    __shared__ float red2[4];
    float mv = mask[b*Lc + t];
    float s = mv;
    #pragma unroll
    for(int sft = 16; sft > 0; sft >>= 1) s += __shfl_xor_sync(0xffffffffu, s, sft);
    if((t & 31) == 0) red2[t >> 5] = s;
    __syncthreads();
    float tot = red2[0]+red2[1]+red2[2]+red2[3];
    int vc = (int)tot;
    vc = min(max(vc, 1), Lc);
    int last = vc - 1;

    if(t < Dc) x[t] = hist[((size_t)b*Lc + last)*Dc + t];
    x[Dc + t] = g_h[((size_t)b*Lc + last)*Hc + t];
    __syncthreads();
    float s1 = x[t] + ((t < 8) ? x[128 + t] : 0.f);
    #pragma unroll
    for(int sft = 16; sft > 0; sft >>= 1) s1 += __shfl_xor_sync(0xffffffffu, s1, sft);
    __syncthreads();
    if((t & 31) == 0) red2[t >> 5] = s1;
    __syncthreads();
    float mu = (red2[0]+red2[1]+red2[2]+red2[3]) * (1.f/136.f);
    float d0 = x[t] - mu;
    float s2 = d0*d0;
    if(t < 8){ float d1 = x[128 + t] - mu; s2 += d1*d1; }
    #pragma unroll
    for(int sft = 16; sft > 0; sft >>= 1) s2 += __shfl_xor_sync(0xffffffffu, s2, sft);
    __syncthreads();
    if((t & 31) == 0) red2[t >> 5] = s2;
    __syncthreads();
    float rs = rsqrtf((red2[0]+red2[1]+red2[2]+red2[3]) * (1.f/136.f) + 1e-5f);
    xn[t] = (x[t] - mu) * rs * hg[t] + hb[t];
    if(t < 8) xn[128 + t] = (x[128 + t] - mu) * rs * hg[128 + t] + hb[128 + t];
    __syncthreads();
    float h_ = bh1[t];
    for(int k = 0; k < 136; k++) h_ += xn[k]*Wh1[k*Hc + t];
    hid[t] = fmaxf(h_, 0.f);
    __syncthreads();
    if(t < 24){
        float p = bh2[t];
        for(int k = 0; k < Hc; k++) p += hid[k]*Wh2[k*24 + t];
        if(isnan(p)) p = 0.f;
        else if(isinf(p)) p = (p > 0.f) ? 1e4f : -1e4f;
        out[b*24 + t] = p;
    }
}

__global__ void k_copyh(float* __restrict__ out){
    int i = blockIdx.x*blockDim.x + threadIdx.x;
    out[384 + i] = g_h[i];
}

// ---------------- launch ----------------
extern "C" void kernel_launch(void* const* d_in, const int* in_sizes, int n_in,
                              void* d_out, int out_size){
    const float* hist = (const float*)d_in[0];
    const float* mask = (const float*)d_in[1];
    const float* Wp   = (const float*)d_in[2];
    const float* bp   = (const float*)d_in[3];
    const float* We1  = (const float*)d_in[4];
    const float* be1  = (const float*)d_in[5];
    const float* We2  = (const float*)d_in[6];
    const float* be2  = (const float*)d_in[7];
    const float* Wa1  = (const float*)d_in[8];
    const float* ba1  = (const float*)d_in[9];
    const float* wa2  = (const float*)d_in[10];
    const float* ba2  = (const float*)d_in[11];
    const float* Wm1  = (const float*)d_in[12];
    const float* bm1  = (const float*)d_in[13];
    const float* Wm2  = (const float*)d_in[14];
    const float* bm2  = (const float*)d_in[15];
    const float* Wo1  = (const float*)d_in[16];
    const float* bo1  = (const float*)d_in[17];
    const float* Wo2  = (const float*)d_in[18];
    const float* bo2  = (const float*)d_in[19];
    const float* lng  = (const float*)d_in[20];
    const float* lnb  = (const float*)d_in[21];
    const float* hg   = (const float*)d_in[22];
    const float* hbv  = (const float*)d_in[23];
    const float* Wh1  = (const float*)d_in[24];
    const float* bh1  = (const float*)d_in[25];
    const float* Wh2  = (const float*)d_in[26];
    const float* bh2  = (const float*)d_in[27];
    float* out = (float*)d_out;

    cudaFuncSetAttribute(k_main6, cudaFuncAttributeMaxDynamicSharedMemorySize, 196608);

    k_ts<<<1, 32>>>(hist);
    k_prepwb<<<NLc*129, Hc>>>(We2, be2, Wa1, Wm1, ba1, bm1);
    k_h0s<<<Bc*Lc/16, 256>>>(hist, mask, Wp, bp, Wa1, Wm1);
    for(int l = 0; l < NLc; l++){
        k_main6<<<Bc*Lc, 1024, 196608>>>(l, hist, mask, We1, be1, wa2, ba2);
        k_post2<<<Bc*Lc/16, 256>>>(l, (l+1 < NLc) ? 1 : 0, mask,
                                   Wm2, bm2, Wo1, bo1, Wo2, bo2, lng, lnb, Wa1, Wm1);
    }
    k_dec<<<Bc, Hc>>>(hist, mask, hg, hbv, Wh1, bh1, Wh2, bh2, out);
    if(out_size >= 384 + Bc*Lc*Hc){
        k_copyh<<<(Bc*Lc*Hc)/256, 256>>>(out);
    }
}

// round 8
// speedup vs baseline: 2.0897x; 2.0897x over previous
#include <cuda_runtime.h>
#include <cuda_bf16.h>
#include <math.h>
#include <stdint.h>

#define Bc 16
#define Lc 128
#define Dc 8
#define Hc 128
#define NLc 2

// bf16 tile geometry: [128 rows][136 cols] bf16, pitch 272B
#define WPITCH 136
#define TILE_ELEMS (128*WPITCH)          // 17408
#define TILE_BYTES (TILE_ELEMS*2)        // 34816

// ---------------- scratch (static device globals; no allocation) ----------------
__device__ __align__(16) float g_ts[Bc*Lc];
__device__ __align__(16) float g_h[Bc*Lc*Hc];
__device__ __align__(16) float g_sa[Bc*Lc*Hc];
__device__ __align__(16) float g_da[Bc*Lc*Hc];
__device__ __align__(16) float g_sm[Bc*Lc*Hc];
__device__ __align__(16) float g_aggpre[Bc*Lc*Hc];
__device__ __align__(16) float g_ba[NLc*Hc];
__device__ __align__(16) float g_bm[NLc*Hc];
// folded weights as bf16 hi/lo, [k][c] rows padded to 136: per layer Wa_hi|Wa_lo|Wm_hi|Wm_lo
__device__ __align__(16) __nv_bfloat16 g_Wbf[NLc*4*TILE_ELEMS];

// ---------------- helpers ----------------
__device__ __forceinline__ uint32_t smem_u32(const void* p){
    uint32_t a;
    asm("{ .reg .u64 t; cvta.to.shared.u64 t, %1; cvt.u32.u64 %0, t; }" : "=r"(a) : "l"(p));
    return a;
}
__device__ __forceinline__ void cp16(void* dst_smem, const void* src){
    unsigned sdst = (unsigned)__cvta_generic_to_shared(dst_smem);
    asm volatile("cp.async.cg.shared.global [%0], [%1], 16;" :: "r"(sdst), "l"(src));
}
__device__ __forceinline__ float tanh_fast(float x){
    float r; asm("tanh.approx.f32 %0, %1;" : "=f"(r) : "f"(x)); return r;
}
__device__ __forceinline__ void ldsm4(uint32_t &r0,uint32_t &r1,uint32_t &r2,uint32_t &r3,uint32_t a){
    asm volatile("ldmatrix.sync.aligned.m8n8.x4.shared.b16 {%0,%1,%2,%3},[%4];"
        : "=r"(r0),"=r"(r1),"=r"(r2),"=r"(r3) : "r"(a));
}
__device__ __forceinline__ void ldsm4t(uint32_t &r0,uint32_t &r1,uint32_t &r2,uint32_t &r3,uint32_t a){
    asm volatile("ldmatrix.sync.aligned.m8n8.x4.trans.shared.b16 {%0,%1,%2,%3},[%4];"
        : "=r"(r0),"=r"(r1),"=r"(r2),"=r"(r3) : "r"(a));
}
__device__ __forceinline__ void mma16816(float* d, uint32_t a0,uint32_t a1,uint32_t a2,uint32_t a3,
                                         uint32_t b0,uint32_t b1){
    asm volatile("mma.sync.aligned.m16n8k16.row.col.f32.bf16.bf16.f32 "
        "{%0,%1,%2,%3},{%4,%5,%6,%7},{%8,%9},{%0,%1,%2,%3};"
        : "+f"(d[0]),"+f"(d[1]),"+f"(d[2]),"+f"(d[3])
        : "r"(a0),"r"(a1),"r"(a2),"r"(a3),"r"(b0),"r"(b1));
}
// pack two floats to bf16x2 (v0 -> low/lower address, v1 -> high)
__device__ __forceinline__ uint32_t packbf2(float v0, float v1){
    uint32_t r; asm("cvt.rn.bf16x2.f32 %0, %1, %2;" : "=r"(r) : "f"(v1), "f"(v0)); return r;
}

// ---------------- cumsum of ts ----------------
__global__ void k_ts(const float* __restrict__ hist){
    int b = threadIdx.x;
    if(b < Bc){
        float c = 0.f;
        for(int t = 0; t < Lc; t++){
            float v = hist[(b*Lc+t)*Dc + 5];
            c += fmaxf(v, 0.f);
            g_ts[b*Lc+t] = c;
        }
    }
}

// ---------------- folded weights -> bf16 hi/lo padded tiles ----------------
__global__ void k_prepwb(const float* __restrict__ We2, const float* __restrict__ be2,
                         const float* __restrict__ Wa1, const float* __restrict__ Wm1,
                         const float* __restrict__ ba1, const float* __restrict__ bm1){
    int l = blockIdx.x / 129, kk = blockIdx.x % 129;
    int c = threadIdx.x;
    __shared__ float ws[Hc];
    if(kk < Hc) ws[c] = We2[l*Hc*Hc + kk*Hc + c];
    else        ws[c] = be2[l*Hc + c];
    __syncthreads();
    const float* wa = Wa1 + l*3*Hc*Hc + 2*Hc*Hc;
    const float* wm = Wm1 + l*2*Hc*Hc + Hc*Hc;
    float sa = 0.f, sm = 0.f;
    #pragma unroll 4
    for(int r = 0; r < Hc; r++){ float w = ws[r]; sa += w*wa[r*Hc + c]; sm += w*wm[r*Hc + c]; }
    if(kk < Hc){
        __nv_bfloat16* base = g_Wbf + (size_t)l*4*TILE_ELEMS;
        __nv_bfloat16 ah = __float2bfloat16(sa);
        __nv_bfloat16 al = __float2bfloat16(sa - __bfloat162float(ah));
        __nv_bfloat16 mh = __float2bfloat16(sm);
        __nv_bfloat16 ml = __float2bfloat16(sm - __bfloat162float(mh));
        base[              kk*WPITCH + c] = ah;
        base[TILE_ELEMS  + kk*WPITCH + c] = al;
        base[2*TILE_ELEMS+ kk*WPITCH + c] = mh;
        base[3*TILE_ELEMS+ kk*WPITCH + c] = ml;
    } else {
        g_ba[l*Hc + c] = sa + ba1[l*Hc + c];
        g_bm[l*Hc + c] = sm + bm1[l*Hc + c];
    }
}

// ---------------- h0 (16 rows per block) + sa/da/sm for layer 0 ----------------
__global__ __launch_bounds__(256)
void k_h0s(const float* __restrict__ hist, const float* __restrict__ mask,
           const float* __restrict__ Wp, const float* __restrict__ bp,
           const float* __restrict__ Wa1, const float* __restrict__ Wm1){
    int row0 = blockIdx.x * 16;
    int tid = threadIdx.x;
    int c = tid & 127, ty = tid >> 7;
    __shared__ float xs[16*Dc], hs[16*Hc], vmsh[16];
    if(tid < 128) xs[tid] = hist[(size_t)row0*Dc + tid];
    if(tid < 16)  vmsh[tid] = mask[row0 + tid] > 0.f ? 1.f : 0.f;
    __syncthreads();
    float acc[8];
    #pragma unroll
    for(int p = 0; p < 8; p++) acc[p] = bp[c];
    #pragma unroll
    for(int d = 0; d < Dc; d++){
        float w = Wp[d*Hc + c];
        #pragma unroll
        for(int p = 0; p < 8; p++) acc[p] += xs[(ty*8+p)*Dc + d] * w;
    }
    #pragma unroll
    for(int p = 0; p < 8; p++){
        int r = ty*8 + p;
        float h = acc[p] * vmsh[r];
        hs[r*Hc + c] = h;
        g_h[(size_t)(row0+r)*Hc + c] = h;
    }
    __syncthreads();
    const float* was = Wa1;
    const float* wad = was + Hc*Hc;
    const float* wms = Wm1;
    float aa[8], dd[8], mm[8];
    #pragma unroll
    for(int p = 0; p < 8; p++){ aa[p]=0.f; dd[p]=0.f; mm[p]=0.f; }
    #pragma unroll 4
    for(int k = 0; k < Hc; k++){
        float w1 = was[k*Hc + c], w2 = wad[k*Hc + c], w3 = wms[k*Hc + c];
        #pragma unroll
        for(int p = 0; p < 8; p++){
            float h = hs[(ty*8+p)*Hc + k];
            aa[p] += h*w1; dd[p] += h*w2; mm[p] += h*w3;
        }
    }
    #pragma unroll
    for(int p = 0; p < 8; p++){
        size_t r = (size_t)(row0 + ty*8 + p)*Hc + c;
        g_sa[r] = aa[p]; g_da[r] = dd[p]; g_sm[r] = mm[p];
    }
}

// ---------------- main fused kernel: HMMA bf16x3 GEMMs + att + softmax + msg agg ----------------
// dynamic SMEM bytes:
//   [0      , 34816 ) T_hi  [j][136] bf16
//   [34816  , 69632 ) T_lo
//   [69632  ,104448 ) Wa_hi [k][136] bf16
//   [104448 ,139264 ) Wa_lo
//   [139264 ,174080 ) Wm_hi
//   [174080 ,208896 ) Wm_lo
// post-MMA, T region reused as f32 msg partial buffer su[64][130]
extern __shared__ char dsmc[];

__global__ __launch_bounds__(512, 1)
void k_main7(int l, const float* __restrict__ hist, const float* __restrict__ mask,
             const float* __restrict__ We1, const float* __restrict__ be1,
             const float* __restrict__ wa2, const float* __restrict__ ba2){
    __shared__ float we1s[4*Hc], be1s[Hc], sab[Hc], smb[Hc], wa2s[Hc];
    __shared__ float att[Lc], wsoft[Lc], red[8], redp[4][Hc];

    int bi = blockIdx.x;
    int b = bi >> 7, i = bi & 127;
    int tid = threadIdx.x;
    int wid = tid >> 5, lane = tid & 31;
    int j = tid & 127;

    // async copy all 4 weight tiles (139264 B = 8704 x 16B; 512 thr x 17)
    {
        const char* wsrc = (const char*)(g_Wbf + (size_t)l*4*TILE_ELEMS);
        char* wdst = dsmc + 2*TILE_BYTES;
        #pragma unroll
        for(int q = 0; q < 17; q++){
            int off = (q*512 + tid)*16;
            cp16(wdst + off, wsrc + off);
        }
        asm volatile("cp.async.commit_group;" ::: "memory");
    }

    if(tid < 128){
        #pragma unroll
        for(int q = 0; q < 4; q++) we1s[q*Hc + tid] = We1[l*4*Hc + q*Hc + tid];
        be1s[tid] = be1[l*Hc + tid];
        sab[tid]  = g_sa[(size_t)bi*Hc + tid] + g_ba[l*Hc + tid];
        smb[tid]  = g_sm[(size_t)bi*Hc + tid] + g_bm[l*Hc + tid];
        wa2s[tid] = wa2[l*Hc + tid];
    }

    // edge features for this thread's j
    const float* hb_ = hist + (size_t)b*Lc*Dc;
    float vldj, vi;
    {
        float lat_i = hb_[i*Dc + 0], lon_i = hb_[i*Dc + 1], src_i = hb_[i*Dc + 6];
        float ts_i = g_ts[b*Lc + i];
        float latj = hb_[j*Dc + 0], lonj = hb_[j*Dc + 1], srcj = hb_[j*Dc + 6];
        float tsj = g_ts[b*Lc + j];
        float dl = lat_i - latj, dn = lon_i - lonj;
        float dist = sqrtf(dl*dl + dn*dn + 1e-8f);
        float dtv = fabsf(ts_i - tsj) * (1.f/300.f);
        float ssv = (src_i == srcj) ? 1.f : 0.f;
        float diag = (j == i) ? 1.f : 0.f;
        vldj = (mask[b*Lc + j] > 0.f) ? 1.f : 0.f;
        vi   = (mask[b*Lc + i] > 0.f) ? 1.f : 0.f;
        __syncthreads();   // we1s/be1s ready

        // T build: thread owns row j, quarter q -> 32 k values (16 bf16x2 pairs)
        int q = tid >> 7;
        char* Th = dsmc + (size_t)j*272;
        char* Tl = Th + TILE_BYTES;
        #pragma unroll
        for(int kk = 0; kk < 16; kk++){
            int k = q*32 + kk*2;
            float v0 = fmaxf(dist*we1s[k]   + dtv*we1s[Hc+k]   + ssv*we1s[2*Hc+k]   + diag*we1s[3*Hc+k]   + be1s[k],   0.f);
            float v1 = fmaxf(dist*we1s[k+1] + dtv*we1s[Hc+k+1] + ssv*we1s[2*Hc+k+1] + diag*we1s[3*Hc+k+1] + be1s[k+1], 0.f);
            uint32_t hp = packbf2(v0, v1);
            __nv_bfloat162 hb2 = *reinterpret_cast<__nv_bfloat162*>(&hp);
            float h0 = __bfloat162float(hb2.x), h1 = __bfloat162float(hb2.y);
            uint32_t lp = packbf2(v0 - h0, v1 - h1);
            *(uint32_t*)(Th + k*2) = hp;
            *(uint32_t*)(Tl + k*2) = lp;
        }
    }
    asm volatile("cp.async.wait_group 0;" ::: "memory");
    __syncthreads();   // T + W ready

    // ---------------- HMMA GEMM ----------------
    // warp group: g_w = wid>>3 (0 = attention/Wa, 1 = message/Wm); jt = (wid&7)*16
    int g_w = wid >> 3;
    int jt = (wid & 7) * 16;
    uint32_t base = smem_u32(dsmc);
    uint32_t aH = base + (uint32_t)((jt + (lane & 15))*272 + ((lane >> 4) << 4));
    uint32_t aL = aH + TILE_BYTES;
    uint32_t wH = base + (uint32_t)(2*TILE_BYTES + (g_w ? 2*TILE_BYTES : 0)
                                    + (lane & 15)*272 + ((lane >> 4) << 4));
    uint32_t wL = wH + TILE_BYTES;

    float acc[64];
    #pragma unroll
    for(int q = 0; q < 64; q++) acc[q] = 0.f;

    #pragma unroll
    for(int ks = 0; ks < 8; ks++){
        uint32_t A0,A1,A2,A3, L0,L1,L2,L3;
        ldsm4(A0,A1,A2,A3, aH + ks*32);
        ldsm4(L0,L1,L2,L3, aL + ks*32);
        uint32_t wb  = wH + ks*4352;
        uint32_t wbl = wL + ks*4352;
        #pragma unroll
        for(int nt2 = 0; nt2 < 8; nt2++){
            uint32_t B0,B1,B2,B3, C0,C1,C2,C3;
            ldsm4t(B0,B1,B2,B3, wb  + nt2*32);
            ldsm4t(C0,C1,C2,C3, wbl + nt2*32);
            float* d0 = acc + nt2*8;
            mma16816(d0,   A0,A1,A2,A3, B0,B1);
            mma16816(d0,   L0,L1,L2,L3, B0,B1);
            mma16816(d0,   A0,A1,A2,A3, C0,C1);
            mma16816(d0+4, A0,A1,A2,A3, B2,B3);
            mma16816(d0+4, L0,L1,L2,L3, B2,B3);
            mma16816(d0+4, A0,A1,A2,A3, C2,C3);
        }
    }

    // d-fragment mapping: tile nt covers cols nt*8..+7; lane (g=lane>>2, tq=lane&3):
    //   acc[nt*4+0] = D[jt+g   ][nt*8+2tq]   acc[nt*4+1] = D[jt+g   ][nt*8+2tq+1]
    //   acc[nt*4+2] = D[jt+g+8 ][nt*8+2tq]   acc[nt*4+3] = D[jt+g+8 ][nt*8+2tq+1]
    int gq = lane >> 2, tq = lane & 3;
    int jA = jt + gq, jB = jA + 8;

    // ---------------- attention epilogue (group 0) ----------------
    if(g_w == 0){
        const float* daA = g_da + ((size_t)(b*Lc + jA))*Hc;
        const float* daB = daA + 8*Hc;
        float sA = 0.f, sB = 0.f;
        #pragma unroll
        for(int nt = 0; nt < 16; nt++){
            int c0 = nt*8 + tq*2;
            float2 dA = *(const float2*)(daA + c0);
            float2 dB = *(const float2*)(daB + c0);
            sA += wa2s[c0]  *tanh_fast(sab[c0]  + dA.x + acc[nt*4+0]);
            sA += wa2s[c0+1]*tanh_fast(sab[c0+1]+ dA.y + acc[nt*4+1]);
            sB += wa2s[c0]  *tanh_fast(sab[c0]  + dB.x + acc[nt*4+2]);
            sB += wa2s[c0+1]*tanh_fast(sab[c0+1]+ dB.y + acc[nt*4+3]);
        }
        sA += __shfl_xor_sync(0xffffffffu, sA, 1);
        sA += __shfl_xor_sync(0xffffffffu, sA, 2);
        sB += __shfl_xor_sync(0xffffffffu, sB, 1);
        sB += __shfl_xor_sync(0xffffffffu, sB, 2);
        if(tq == 0){ att[jA] = sA; att[jB] = sB; }
    }
    __syncthreads();

    // ---------------- softmax over j (first 128 threads) ----------------
    const float inv = 0.088388347648318440550f;   // 1/sqrt(128)
    float sc = -1e9f, e = 0.f;
    if(tid < 128){
        float a = (att[tid] + ba2[l]) * inv;
        bool ok = (vldj > 0.f) && (vi > 0.f);
        sc = ok ? a : -1e9f;
        float m = sc;
        #pragma unroll
        for(int s2 = 16; s2 > 0; s2 >>= 1) m = fmaxf(m, __shfl_xor_sync(0xffffffffu, m, s2));
        if((tid & 31) == 0) red[tid >> 5] = m;
    }
    __syncthreads();
    float bmax = fmaxf(fmaxf(red[0], red[1]), fmaxf(red[2], red[3]));
    if(tid < 128){
        e = expf(sc - bmax);
        float s2 = e;
        #pragma unroll
        for(int m = 16; m > 0; m >>= 1) s2 += __shfl_xor_sync(0xffffffffu, s2, m);
        if((tid & 31) == 0) red[4 + (tid >> 5)] = s2;
    }
    __syncthreads();
    if(tid < 128){
        float tot = red[4]+red[5]+red[6]+red[7];
        wsoft[tid] = e / tot;
    }
    __syncthreads();

    // ---------------- message epilogue (group 1) ----------------
    float* su = (float*)dsmc;   // [64 rows][130 f32] partials (T region dead)
    if(g_w == 1){
        float wA = wsoft[jA], wB = wsoft[jB];
        int p = (wid & 7)*8 + gq;
        #pragma unroll
        for(int nt = 0; nt < 16; nt++){
            int c0 = nt*8 + tq*2;
            float v0 = wA*fmaxf(smb[c0]  + acc[nt*4+0], 0.f) + wB*fmaxf(smb[c0]  + acc[nt*4+2], 0.f);
            float v1 = wA*fmaxf(smb[c0+1]+ acc[nt*4+1], 0.f) + wB*fmaxf(smb[c0+1]+ acc[nt*4+3], 0.f);
            *(float2*)(su + p*130 + c0) = make_float2(v0, v1);
        }
    }
    __syncthreads();
    {
        int q = tid >> 7, c = tid & 127;
        float s = 0.f;
        #pragma unroll 4
        for(int r = 0; r < 16; r++) s += su[(q*16 + r)*130 + c];
        redp[q][c] = s;
    }
    __syncthreads();
    if(tid < 128){
        g_aggpre[(size_t)bi*Hc + tid] = redp[0][tid] + redp[1][tid] + redp[2][tid] + redp[3][tid];
    }
}

// ---------------- epilogue per 16 rows ----------------
__global__ __launch_bounds__(256)
void k_post2(int l, int has_next, const float* __restrict__ mask,
             const float* __restrict__ Wm2, const float* __restrict__ bm2,
             const float* __restrict__ Wo1, const float* __restrict__ bo1,
             const float* __restrict__ Wo2, const float* __restrict__ bo2,
             const float* __restrict__ lng, const float* __restrict__ lnb,
             const float* __restrict__ Wa1, const float* __restrict__ Wm1){
    int row0 = blockIdx.x * 16;
    int tid = threadIdx.x;
    int c = tid & 127, ty = tid >> 7;
    __shared__ float hs[16*Hc], as_[16*Hc], ag[16*Hc], op1[16*Hc];
    __shared__ float mu[16], rsd[16], vmsh[16];

    #pragma unroll
    for(int q = 0; q < 8; q++){
        int idx = q*256 + tid;
        hs[idx]  = g_h[(size_t)row0*Hc + idx];
        as_[idx] = g_aggpre[(size_t)row0*Hc + idx];
    }
    if(tid < 16) vmsh[tid] = mask[row0 + tid] > 0.f ? 1.f : 0.f;
    __syncthreads();

    float acc[8];
    const float* wm2 = Wm2 + l*Hc*Hc;
    #pragma unroll
    for(int p = 0; p < 8; p++) acc[p] = bm2[l*Hc + c];
    #pragma unroll 4
    for(int k = 0; k < Hc; k++){
        float w = wm2[k*Hc + c];
        #pragma unroll
        for(int p = 0; p < 8; p++) acc[p] += as_[(ty*8+p)*Hc + k] * w;
    }
    #pragma unroll
    for(int p = 0; p < 8; p++) ag[(ty*8+p)*Hc + c] = acc[p];
    __syncthreads();

    const float* wo1h = Wo1 + l*2*Hc*Hc;
    const float* wo1a = wo1h + Hc*Hc;
    #pragma unroll
    for(int p = 0; p < 8; p++) acc[p] = bo1[l*Hc + c];
    #pragma unroll 4
    for(int k = 0; k < Hc; k++){
        float w1 = wo1h[k*Hc + c], w2 = wo1a[k*Hc + c];
        #pragma unroll
        for(int p = 0; p < 8; p++)
            acc[p] += hs[(ty*8+p)*Hc + k]*w1 + ag[(ty*8+p)*Hc + k]*w2;
    }
    #pragma unroll
    for(int p = 0; p < 8; p++) op1[(ty*8+p)*Hc + c] = fmaxf(acc[p], 0.f);
    __syncthreads();

    const float* wo2 = Wo2 + l*Hc*Hc;
    #pragma unroll
    for(int p = 0; p < 8; p++) acc[p] = bo2[l*Hc + c];
    #pragma unroll 4
    for(int k = 0; k < Hc; k++){
        float w = wo2[k*Hc + c];
        #pragma unroll
        for(int p = 0; p < 8; p++) acc[p] += op1[(ty*8+p)*Hc + k] * w;
    }
    #pragma unroll
    for(int p = 0; p < 8; p++){
        int r = ty*8 + p;
        ag[r*Hc + c] = hs[r*Hc + c] + acc[p];
    }
    __syncthreads();

    {
        int row = tid >> 4, l16 = tid & 15;
        float s = 0.f, s2 = 0.f;
        #pragma unroll
        for(int q = 0; q < 8; q++){
            float v = ag[row*Hc + l16 + q*16];
            s += v; s2 += v*v;
        }
        #pragma unroll
        for(int m = 8; m > 0; m >>= 1){
            s  += __shfl_xor_sync(0xffffffffu, s, m);
            s2 += __shfl_xor_sync(0xffffffffu, s2, m);
        }
        if(l16 == 0){
            float m_ = s * (1.f/128.f);
            mu[row] = m_;
            rsd[row] = rsqrtf(s2 * (1.f/128.f) - m_*m_ + 1e-5f);
        }
    }
    __syncthreads();
    const float* lg = lng + l*Hc;
    const float* lb = lnb + l*Hc;
    #pragma unroll
    for(int p = 0; p < 8; p++){
        int r = ty*8 + p;
        float x = ag[r*Hc + c];
        float hn = ((x - mu[r]) * rsd[r] * lg[c] + lb[c]) * vmsh[r];
        g_h[(size_t)(row0+r)*Hc + c] = hn;
        hs[r*Hc + c] = hn;
    }

    if(has_next){
        __syncthreads();
        int ln = l + 1;
        const float* was = Wa1 + ln*3*Hc*Hc;
        const float* wad = was + Hc*Hc;
        const float* wms = Wm1 + ln*2*Hc*Hc;
        float aa[8], dd[8], mm[8];
        #pragma unroll
        for(int p = 0; p < 8; p++){ aa[p]=0.f; dd[p]=0.f; mm[p]=0.f; }
        #pragma unroll 4
        for(int k = 0; k < Hc; k++){
            float w1 = was[k*Hc + c], w2 = wad[k*Hc + c], w3 = wms[k*Hc + c];
            #pragma unroll
            for(int p = 0; p < 8; p++){
                float h = hs[(ty*8+p)*Hc + k];
                aa[p] += h*w1; dd[p] += h*w2; mm[p] += h*w3;
            }
        }
        #pragma unroll
        for(int p = 0; p < 8; p++){
            size_t r = (size_t)(row0 + ty*8 + p)*Hc + c;
            g_sa[r] = aa[p]; g_da[r] = dd[p]; g_sm[r] = mm[p];
        }
    }
}

// ---------------- decoder ----------------
__global__ void k_dec(const float* __restrict__ hist, const float* __restrict__ mask,
                      const float* __restrict__ hg, const float* __restrict__ hb,
                      const float* __restrict__ Wh1, const float* __restrict__ bh1,
                      const float* __restrict__ Wh2, const float* __restrict__ bh2,
                      float* __restrict__ out){
    int b = blockIdx.x; int t = threadIdx.x;
    __shared__ float x[136], xn[136], hid[Hc];
    __shared__ float red2[4];
    float mv = mask[b*Lc + t];
    float s = mv;
    #pragma unroll
    for(int sft = 16; sft > 0; sft >>= 1) s += __shfl_xor_sync(0xffffffffu, s, sft);
    if((t & 31) == 0) red2[t >> 5] = s;
    __syncthreads();
    float tot = red2[0]+red2[1]+red2[2]+red2[3];
    int vc = (int)tot;
    vc = min(max(vc, 1), Lc);
    int last = vc - 1;

    if(t < Dc) x[t] = hist[((size_t)b*Lc + last)*Dc + t];
    x[Dc + t] = g_h[((size_t)b*Lc + last)*Hc + t];
    __syncthreads();
    float s1 = x[t] + ((t < 8) ? x[128 + t] : 0.f);
    #pragma unroll
    for(int sft = 16; sft > 0; sft >>= 1) s1 += __shfl_xor_sync(0xffffffffu, s1, sft);
    __syncthreads();
    if((t & 31) == 0) red2[t >> 5] = s1;
    __syncthreads();
    float mu = (red2[0]+red2[1]+red2[2]+red2[3]) * (1.f/136.f);
    float d0 = x[t] - mu;
    float s2 = d0*d0;
    if(t < 8){ float d1 = x[128 + t] - mu; s2 += d1*d1; }
    #pragma unroll
    for(int sft = 16; sft > 0; sft >>= 1) s2 += __shfl_xor_sync(0xffffffffu, s2, sft);
    __syncthreads();
    if((t & 31) == 0) red2[t >> 5] = s2;
    __syncthreads();
    float rs = rsqrtf((red2[0]+red2[1]+red2[2]+red2[3]) * (1.f/136.f) + 1e-5f);
    xn[t] = (x[t] - mu) * rs * hg[t] + hb[t];
    if(t < 8) xn[128 + t] = (x[128 + t] - mu) * rs * hg[128 + t] + hb[128 + t];
    __syncthreads();
    float h_ = bh1[t];
    for(int k = 0; k < 136; k++) h_ += xn[k]*Wh1[k*Hc + t];
    hid[t] = fmaxf(h_, 0.f);
    __syncthreads();
    if(t < 24){
        float p = bh2[t];
        for(int k = 0; k < Hc; k++) p += hid[k]*Wh2[k*24 + t];
        if(isnan(p)) p = 0.f;
        else if(isinf(p)) p = (p > 0.f) ? 1e4f : -1e4f;
        out[b*24 + t] = p;
    }
}

__global__ void k_copyh(float* __restrict__ out){
    int i = blockIdx.x*blockDim.x + threadIdx.x;
    out[384 + i] = g_h[i];
}

// ---------------- launch ----------------
extern "C" void kernel_launch(void* const* d_in, const int* in_sizes, int n_in,
                              void* d_out, int out_size){
    const float* hist = (const float*)d_in[0];
    const float* mask = (const float*)d_in[1];
    const float* Wp   = (const float*)d_in[2];
    const float* bp   = (const float*)d_in[3];
    const float* We1  = (const float*)d_in[4];
    const float* be1  = (const float*)d_in[5];
    const float* We2  = (const float*)d_in[6];
    const float* be2  = (const float*)d_in[7];
    const float* Wa1  = (const float*)d_in[8];
    const float* ba1  = (const float*)d_in[9];
    const float* wa2  = (const float*)d_in[10];
    const float* ba2  = (const float*)d_in[11];
    const float* Wm1  = (const float*)d_in[12];
    const float* bm1  = (const float*)d_in[13];
    const float* Wm2  = (const float*)d_in[14];
    const float* bm2  = (const float*)d_in[15];
    const float* Wo1  = (const float*)d_in[16];
    const float* bo1  = (const float*)d_in[17];
    const float* Wo2  = (const float*)d_in[18];
    const float* bo2  = (const float*)d_in[19];
    const float* lng  = (const float*)d_in[20];
    const float* lnb  = (const float*)d_in[21];
    const float* hg   = (const float*)d_in[22];
    const float* hbv  = (const float*)d_in[23];
    const float* Wh1  = (const float*)d_in[24];
    const float* bh1  = (const float*)d_in[25];
    const float* Wh2  = (const float*)d_in[26];
    const float* bh2  = (const float*)d_in[27];
    float* out = (float*)d_out;

    cudaFuncSetAttribute(k_main7, cudaFuncAttributeMaxDynamicSharedMemorySize, 6*TILE_BYTES);

    k_ts<<<1, 32>>>(hist);
    k_prepwb<<<NLc*129, Hc>>>(We2, be2, Wa1, Wm1, ba1, bm1);
    k_h0s<<<Bc*Lc/16, 256>>>(hist, mask, Wp, bp, Wa1, Wm1);
    for(int l = 0; l < NLc; l++){
        k_main7<<<Bc*Lc, 512, 6*TILE_BYTES>>>(l, hist, mask, We1, be1, wa2, ba2);
        k_post2<<<Bc*Lc/16, 256>>>(l, (l+1 < NLc) ? 1 : 0, mask,
                                   Wm2, bm2, Wo1, bo1, Wo2, bo2, lng, lnb, Wa1, Wm1);
    }
    k_dec<<<Bc, Hc>>>(hist, mask, hg, hbv, Wh1, bh1, Wh2, bh2, out);
    if(out_size >= 384 + Bc*Lc*Hc){
        k_copyh<<<(Bc*Lc*Hc)/256, 256>>>(out);
    }
}

// round 9
// speedup vs baseline: 2.5072x; 1.1998x over previous
#include <cuda_runtime.h>
#include <cuda_bf16.h>
#include <math.h>
#include <stdint.h>

#define Bc 16
#define Lc 128
#define Dc 8
#define Hc 128
#define NLc 2

// bf16 tile geometry: [128 rows][136 cols] bf16, pitch 272B
#define WPITCH 136
#define TILE_ELEMS (128*WPITCH)          // 17408
#define TILE_BYTES (TILE_ELEMS*2)        // 34816

// ---------------- scratch (static device globals; no allocation) ----------------
__device__ __align__(16) float g_ts[Bc*Lc];
__device__ __align__(16) float g_h[Bc*Lc*Hc];
__device__ __align__(16) float g_sa[Bc*Lc*Hc];
__device__ __align__(16) float g_da[Bc*Lc*Hc];
__device__ __align__(16) float g_sm[Bc*Lc*Hc];
__device__ __align__(16) float g_aggpre[Bc*Lc*Hc];
__device__ __align__(16) float g_ba[NLc*Hc];
__device__ __align__(16) float g_bm[NLc*Hc];
// folded weights as bf16 (hi only), [k][c] rows padded to 136: per layer Wa | Wm
__device__ __align__(16) __nv_bfloat16 g_Wbf[NLc*2*TILE_ELEMS];

// ---------------- helpers ----------------
__device__ __forceinline__ uint32_t smem_u32(const void* p){
    uint32_t a;
    asm("{ .reg .u64 t; cvta.to.shared.u64 t, %1; cvt.u32.u64 %0, t; }" : "=r"(a) : "l"(p));
    return a;
}
__device__ __forceinline__ void cp16(void* dst_smem, const void* src){
    unsigned sdst = (unsigned)__cvta_generic_to_shared(dst_smem);
    asm volatile("cp.async.cg.shared.global [%0], [%1], 16;" :: "r"(sdst), "l"(src));
}
__device__ __forceinline__ float tanh_fast(float x){
    float r; asm("tanh.approx.f32 %0, %1;" : "=f"(r) : "f"(x)); return r;
}
__device__ __forceinline__ void ldsm4(uint32_t &r0,uint32_t &r1,uint32_t &r2,uint32_t &r3,uint32_t a){
    asm volatile("ldmatrix.sync.aligned.m8n8.x4.shared.b16 {%0,%1,%2,%3},[%4];"
        : "=r"(r0),"=r"(r1),"=r"(r2),"=r"(r3) : "r"(a));
}
__device__ __forceinline__ void ldsm4t(uint32_t &r0,uint32_t &r1,uint32_t &r2,uint32_t &r3,uint32_t a){
    asm volatile("ldmatrix.sync.aligned.m8n8.x4.trans.shared.b16 {%0,%1,%2,%3},[%4];"
        : "=r"(r0),"=r"(r1),"=r"(r2),"=r"(r3) : "r"(a));
}
__device__ __forceinline__ void mma16816(float* d, uint32_t a0,uint32_t a1,uint32_t a2,uint32_t a3,
                                         uint32_t b0,uint32_t b1){
    asm volatile("mma.sync.aligned.m16n8k16.row.col.f32.bf16.bf16.f32 "
        "{%0,%1,%2,%3},{%4,%5,%6,%7},{%8,%9},{%0,%1,%2,%3};"
        : "+f"(d[0]),"+f"(d[1]),"+f"(d[2]),"+f"(d[3])
        : "r"(a0),"r"(a1),"r"(a2),"r"(a3),"r"(b0),"r"(b1));
}
// pack two floats to bf16x2 (v0 -> low half, v1 -> high)
__device__ __forceinline__ uint32_t packbf2(float v0, float v1){
    uint32_t r; asm("cvt.rn.bf16x2.f32 %0, %1, %2;" : "=r"(r) : "f"(v1), "f"(v0)); return r;
}

// ---------------- cumsum of ts ----------------
__global__ void k_ts(const float* __restrict__ hist){
    int b = threadIdx.x;
    if(b < Bc){
        float c = 0.f;
        for(int t = 0; t < Lc; t++){
            float v = hist[(b*Lc+t)*Dc + 5];
            c += fmaxf(v, 0.f);
            g_ts[b*Lc+t] = c;
        }
    }
}

// ---------------- folded weights -> bf16 padded tiles ----------------
__global__ void k_prepwb(const float* __restrict__ We2, const float* __restrict__ be2,
                         const float* __restrict__ Wa1, const float* __restrict__ Wm1,
                         const float* __restrict__ ba1, const float* __restrict__ bm1){
    int l = blockIdx.x / 129, kk = blockIdx.x % 129;
    int c = threadIdx.x;
    __shared__ float ws[Hc];
    if(kk < Hc) ws[c] = We2[l*Hc*Hc + kk*Hc + c];
    else        ws[c] = be2[l*Hc + c];
    __syncthreads();
    const float* wa = Wa1 + l*3*Hc*Hc + 2*Hc*Hc;
    const float* wm = Wm1 + l*2*Hc*Hc + Hc*Hc;
    float sa = 0.f, sm = 0.f;
    #pragma unroll 4
    for(int r = 0; r < Hc; r++){ float w = ws[r]; sa += w*wa[r*Hc + c]; sm += w*wm[r*Hc + c]; }
    if(kk < Hc){
        __nv_bfloat16* base = g_Wbf + (size_t)l*2*TILE_ELEMS;
        base[             kk*WPITCH + c] = __float2bfloat16(sa);
        base[TILE_ELEMS + kk*WPITCH + c] = __float2bfloat16(sm);
    } else {
        g_ba[l*Hc + c] = sa + ba1[l*Hc + c];
        g_bm[l*Hc + c] = sm + bm1[l*Hc + c];
    }
}

// ---------------- h0 (16 rows per block) + sa/da/sm for layer 0 ----------------
__global__ __launch_bounds__(256)
void k_h0s(const float* __restrict__ hist, const float* __restrict__ mask,
           const float* __restrict__ Wp, const float* __restrict__ bp,
           const float* __restrict__ Wa1, const float* __restrict__ Wm1){
    int row0 = blockIdx.x * 16;
    int tid = threadIdx.x;
    int c = tid & 127, ty = tid >> 7;
    __shared__ float xs[16*Dc], hs[16*Hc], vmsh[16];
    if(tid < 128) xs[tid] = hist[(size_t)row0*Dc + tid];
    if(tid < 16)  vmsh[tid] = mask[row0 + tid] > 0.f ? 1.f : 0.f;
    __syncthreads();
    float acc[8];
    #pragma unroll
    for(int p = 0; p < 8; p++) acc[p] = bp[c];
    #pragma unroll
    for(int d = 0; d < Dc; d++){
        float w = Wp[d*Hc + c];
        #pragma unroll
        for(int p = 0; p < 8; p++) acc[p] += xs[(ty*8+p)*Dc + d] * w;
    }
    #pragma unroll
    for(int p = 0; p < 8; p++){
        int r = ty*8 + p;
        float h = acc[p] * vmsh[r];
        hs[r*Hc + c] = h;
        g_h[(size_t)(row0+r)*Hc + c] = h;
    }
    __syncthreads();
    const float* was = Wa1;
    const float* wad = was + Hc*Hc;
    const float* wms = Wm1;
    float aa[8], dd[8], mm[8];
    #pragma unroll
    for(int p = 0; p < 8; p++){ aa[p]=0.f; dd[p]=0.f; mm[p]=0.f; }
    #pragma unroll 4
    for(int k = 0; k < Hc; k++){
        float w1 = was[k*Hc + c], w2 = wad[k*Hc + c], w3 = wms[k*Hc + c];
        #pragma unroll
        for(int p = 0; p < 8; p++){
            float h = hs[(ty*8+p)*Hc + k];
            aa[p] += h*w1; dd[p] += h*w2; mm[p] += h*w3;
        }
    }
    #pragma unroll
    for(int p = 0; p < 8; p++){
        size_t r = (size_t)(row0 + ty*8 + p)*Hc + c;
        g_sa[r] = aa[p]; g_da[r] = dd[p]; g_sm[r] = mm[p];
    }
}

// ---------------- main fused kernel: HMMA (T hi/lo x W bf16) + att + softmax + msg agg ----------------
// dynamic SMEM bytes:
//   [0      , 34816 ) T_hi  [j][136] bf16
//   [34816  , 69632 ) T_lo
//   [69632  ,104448 ) Wa    [k][136] bf16
//   [104448 ,139264 ) Wm
// post-MMA, T region reused as f32 msg partial buffer su[32][130]
extern __shared__ char dsmc[];

__global__ __launch_bounds__(512, 1)
void k_main8(int l, const float* __restrict__ hist, const float* __restrict__ mask,
             const float* __restrict__ We1, const float* __restrict__ be1,
             const float* __restrict__ wa2, const float* __restrict__ ba2){
    __shared__ float we1s[4*Hc], be1s[Hc], sab[Hc], smb[Hc], wa2s[Hc];
    __shared__ float attp[2][Lc], wsoft[Lc], red[8], redp[4][Hc];

    int bi = blockIdx.x;
    int b = bi >> 7, i = bi & 127;
    int tid = threadIdx.x;
    int wid = tid >> 5, lane = tid & 31;
    int j = tid & 127;

    // async copy both weight tiles (69632 B = 4352 x 16B)
    {
        const char* wsrc = (const char*)(g_Wbf + (size_t)l*2*TILE_ELEMS);
        char* wdst = dsmc + 2*TILE_BYTES;
        #pragma unroll
        for(int q = 0; q < 8; q++){
            int off = (q*512 + tid)*16;
            cp16(wdst + off, wsrc + off);
        }
        if(tid < 256) cp16(wdst + (4096 + tid)*16, wsrc + (4096 + tid)*16);
        asm volatile("cp.async.commit_group;" ::: "memory");
    }

    if(tid < 128){
        #pragma unroll
        for(int q = 0; q < 4; q++) we1s[q*Hc + tid] = We1[l*4*Hc + q*Hc + tid];
        be1s[tid] = be1[l*Hc + tid];
        sab[tid]  = g_sa[(size_t)bi*Hc + tid] + g_ba[l*Hc + tid];
        smb[tid]  = g_sm[(size_t)bi*Hc + tid] + g_bm[l*Hc + tid];
        wa2s[tid] = wa2[l*Hc + tid];
    }

    // edge features for this thread's j
    const float* hb_ = hist + (size_t)b*Lc*Dc;
    float vldj, vi;
    {
        float lat_i = hb_[i*Dc + 0], lon_i = hb_[i*Dc + 1], src_i = hb_[i*Dc + 6];
        float ts_i = g_ts[b*Lc + i];
        float latj = hb_[j*Dc + 0], lonj = hb_[j*Dc + 1], srcj = hb_[j*Dc + 6];
        float tsj = g_ts[b*Lc + j];
        float dl = lat_i - latj, dn = lon_i - lonj;
        float dist = sqrtf(dl*dl + dn*dn + 1e-8f);
        float dtv = fabsf(ts_i - tsj) * (1.f/300.f);
        float ssv = (src_i == srcj) ? 1.f : 0.f;
        float diag = (j == i) ? 1.f : 0.f;
        vldj = (mask[b*Lc + j] > 0.f) ? 1.f : 0.f;
        vi   = (mask[b*Lc + i] > 0.f) ? 1.f : 0.f;
        __syncthreads();   // we1s/be1s ready

        // T build: thread owns row j, quarter q -> 32 k values (16 bf16x2 pairs) hi+lo
        int q = tid >> 7;
        char* Th = dsmc + (size_t)j*272;
        char* Tl = Th + TILE_BYTES;
        #pragma unroll
        for(int kk = 0; kk < 16; kk++){
            int k = q*32 + kk*2;
            float v0 = fmaxf(dist*we1s[k]   + dtv*we1s[Hc+k]   + ssv*we1s[2*Hc+k]   + diag*we1s[3*Hc+k]   + be1s[k],   0.f);
            float v1 = fmaxf(dist*we1s[k+1] + dtv*we1s[Hc+k+1] + ssv*we1s[2*Hc+k+1] + diag*we1s[3*Hc+k+1] + be1s[k+1], 0.f);
            uint32_t hp = packbf2(v0, v1);
            __nv_bfloat162 hb2 = *reinterpret_cast<__nv_bfloat162*>(&hp);
            float h0 = __bfloat162float(hb2.x), h1 = __bfloat162float(hb2.y);
            uint32_t lp = packbf2(v0 - h0, v1 - h1);
            *(uint32_t*)(Th + k*2) = hp;
            *(uint32_t*)(Tl + k*2) = lp;
        }
    }
    asm volatile("cp.async.wait_group 0;" ::: "memory");
    __syncthreads();   // T + W ready

    // ---------------- HMMA GEMM ----------------
    // warp: g_w = wid>>3 (0=att/Wa, 1=msg/Wm); within group: jt = (wl&3)*32, ch = (wl>>2)*64
    int g_w = wid >> 3;
    int wl = wid & 7;
    int jt = (wl & 3) * 32;
    int ch = (wl >> 2) * 64;
    uint32_t base = smem_u32(dsmc);
    uint32_t aH0 = base + (uint32_t)((jt + (lane & 15))*272 + ((lane >> 4) << 4));
    uint32_t aH1 = aH0 + 16*272;
    uint32_t aL0 = aH0 + TILE_BYTES;
    uint32_t aL1 = aH1 + TILE_BYTES;
    uint32_t wB  = base + (uint32_t)(2*TILE_BYTES + (g_w ? TILE_BYTES : 0)
                   + (lane & 15)*272 + ch*2 + ((lane >> 4) << 4));

    // acc layout: [t16][nt][sub][4] -> t16*32 + nt*8 + sub*4
    float acc[64];
    #pragma unroll
    for(int q = 0; q < 64; q++) acc[q] = 0.f;

    #pragma unroll
    for(int ks = 0; ks < 8; ks++){
        uint32_t a0,a1,a2,a3, c0,c1,c2,c3, e0,e1,e2,e3, f0,f1,f2,f3;
        ldsm4(a0,a1,a2,a3, aH0 + ks*32);   // tile0 hi
        ldsm4(c0,c1,c2,c3, aH1 + ks*32);   // tile1 hi
        ldsm4(e0,e1,e2,e3, aL0 + ks*32);   // tile0 lo
        ldsm4(f0,f1,f2,f3, aL1 + ks*32);   // tile1 lo
        uint32_t wrow = wB + ks*4352;
        #pragma unroll
        for(int nt = 0; nt < 4; nt++){
            uint32_t B0,B1,B2,B3;
            ldsm4t(B0,B1,B2,B3, wrow + nt*32);
            float* d00 = acc + nt*8;
            float* d01 = d00 + 4;
            float* d10 = acc + 32 + nt*8;
            float* d11 = d10 + 4;
            mma16816(d00, a0,a1,a2,a3, B0,B1);
            mma16816(d00, e0,e1,e2,e3, B0,B1);
            mma16816(d01, a0,a1,a2,a3, B2,B3);
            mma16816(d01, e0,e1,e2,e3, B2,B3);
            mma16816(d10, c0,c1,c2,c3, B0,B1);
            mma16816(d10, f0,f1,f2,f3, B0,B1);
            mma16816(d11, c0,c1,c2,c3, B2,B3);
            mma16816(d11, f0,f1,f2,f3, B2,B3);
        }
    }

    // d-fragment mapping (per t16/nt/sub tile, cols = ch + nt*16 + sub*8):
    //   lane (gq=lane>>2, tq=lane&3): d[0],d[1] = rows jt+t16*16+gq, cols +2tq,+2tq+1
    //                                 d[2],d[3] = row +8
    int gq = lane >> 2, tq = lane & 3;

    // ---------------- attention epilogue (group 0) ----------------
    if(g_w == 0){
        #pragma unroll
        for(int t16 = 0; t16 < 2; t16++){
            int jA = jt + t16*16 + gq, jB = jA + 8;
            const float* daA = g_da + ((size_t)(b*Lc + jA))*Hc;
            const float* daB = daA + 8*Hc;
            float sA = 0.f, sB = 0.f;
            #pragma unroll
            for(int nt = 0; nt < 4; nt++){
                #pragma unroll
                for(int sub = 0; sub < 2; sub++){
                    int c0 = ch + nt*16 + sub*8 + tq*2;
                    const float* d = acc + t16*32 + nt*8 + sub*4;
                    float2 dA = *(const float2*)(daA + c0);
                    float2 dB = *(const float2*)(daB + c0);
                    sA += wa2s[c0]  *tanh_fast(sab[c0]  + dA.x + d[0]);
                    sA += wa2s[c0+1]*tanh_fast(sab[c0+1]+ dA.y + d[1]);
                    sB += wa2s[c0]  *tanh_fast(sab[c0]  + dB.x + d[2]);
                    sB += wa2s[c0+1]*tanh_fast(sab[c0+1]+ dB.y + d[3]);
                }
            }
            sA += __shfl_xor_sync(0xffffffffu, sA, 1);
            sA += __shfl_xor_sync(0xffffffffu, sA, 2);
            sB += __shfl_xor_sync(0xffffffffu, sB, 1);
            sB += __shfl_xor_sync(0xffffffffu, sB, 2);
            if(tq == 0){ attp[ch >> 6][jA] = sA; attp[ch >> 6][jB] = sB; }
        }
    }
    __syncthreads();

    // ---------------- softmax over j (first 128 threads) ----------------
    const float inv = 0.088388347648318440550f;   // 1/sqrt(128)
    float sc = -1e9f, e = 0.f;
    if(tid < 128){
        float a = (attp[0][tid] + attp[1][tid] + ba2[l]) * inv;
        bool ok = (vldj > 0.f) && (vi > 0.f);
        sc = ok ? a : -1e9f;
        float m = sc;
        #pragma unroll
        for(int s2 = 16; s2 > 0; s2 >>= 1) m = fmaxf(m, __shfl_xor_sync(0xffffffffu, m, s2));
        if((tid & 31) == 0) red[tid >> 5] = m;
    }
    __syncthreads();
    float bmax = fmaxf(fmaxf(red[0], red[1]), fmaxf(red[2], red[3]));
    if(tid < 128){
        e = expf(sc - bmax);
        float s2 = e;
        #pragma unroll
        for(int m = 16; m > 0; m >>= 1) s2 += __shfl_xor_sync(0xffffffffu, s2, m);
        if((tid & 31) == 0) red[4 + (tid >> 5)] = s2;
    }
    __syncthreads();
    if(tid < 128){
        float tot = red[4]+red[5]+red[6]+red[7];
        wsoft[tid] = e / tot;
    }
    __syncthreads();

    // ---------------- message epilogue (group 1) ----------------
    float* su = (float*)dsmc;   // [32 rows][130 f32] partials (T region dead)
    if(g_w == 1){
        float v[16];
        #pragma unroll
        for(int p = 0; p < 16; p++) v[p] = 0.f;
        #pragma unroll
        for(int t16 = 0; t16 < 2; t16++){
            int jA = jt + t16*16 + gq, jB = jA + 8;
            float wA = wsoft[jA], wB2 = wsoft[jB];
            #pragma unroll
            for(int nt = 0; nt < 4; nt++){
                #pragma unroll
                for(int sub = 0; sub < 2; sub++){
                    int c0 = ch + nt*16 + sub*8 + tq*2;
                    const float* d = acc + t16*32 + nt*8 + sub*4;
                    int vi_ = nt*4 + sub*2;
                    v[vi_]   += wA*fmaxf(smb[c0]  + d[0], 0.f) + wB2*fmaxf(smb[c0]  + d[2], 0.f);
                    v[vi_+1] += wA*fmaxf(smb[c0+1]+ d[1], 0.f) + wB2*fmaxf(smb[c0+1]+ d[3], 0.f);
                }
            }
        }
        int p = (wl & 3)*8 + gq;
        #pragma unroll
        for(int nt = 0; nt < 4; nt++){
            #pragma unroll
            for(int sub = 0; sub < 2; sub++){
                int c0 = ch + nt*16 + sub*8 + tq*2;
                *(float2*)(su + p*130 + c0) = make_float2(v[nt*4+sub*2], v[nt*4+sub*2+1]);
            }
        }
    }
    __syncthreads();
    {
        int qq = tid >> 7, c = tid & 127;
        float s = 0.f;
        #pragma unroll
        for(int r = 0; r < 8; r++) s += su[(qq*8 + r)*130 + c];
        redp[qq][c] = s;
    }
    __syncthreads();
    if(tid < 128){
        g_aggpre[(size_t)bi*Hc + tid] = redp[0][tid] + redp[1][tid] + redp[2][tid] + redp[3][tid];
    }
}

// ---------------- epilogue per 16 rows ----------------
__global__ __launch_bounds__(256)
void k_post2(int l, int has_next, const float* __restrict__ mask,
             const float* __restrict__ Wm2, const float* __restrict__ bm2,
             const float* __restrict__ Wo1, const float* __restrict__ bo1,
             const float* __restrict__ Wo2, const float* __restrict__ bo2,
             const float* __restrict__ lng, const float* __restrict__ lnb,
             const float* __restrict__ Wa1, const float* __restrict__ Wm1){
    int row0 = blockIdx.x * 16;
    int tid = threadIdx.x;
    int c = tid & 127, ty = tid >> 7;
    __shared__ float hs[16*Hc], as_[16*Hc], ag[16*Hc], op1[16*Hc];
    __shared__ float mu[16], rsd[16], vmsh[16];

    #pragma unroll
    for(int q = 0; q < 8; q++){
        int idx = q*256 + tid;
        hs[idx]  = g_h[(size_t)row0*Hc + idx];
        as_[idx] = g_aggpre[(size_t)row0*Hc + idx];
    }
    if(tid < 16) vmsh[tid] = mask[row0 + tid] > 0.f ? 1.f : 0.f;
    __syncthreads();

    float acc[8];
    const float* wm2 = Wm2 + l*Hc*Hc;
    #pragma unroll
    for(int p = 0; p < 8; p++) acc[p] = bm2[l*Hc + c];
    #pragma unroll 4
    for(int k = 0; k < Hc; k++){
        float w = wm2[k*Hc + c];
        #pragma unroll
        for(int p = 0; p < 8; p++) acc[p] += as_[(ty*8+p)*Hc + k] * w;
    }
    #pragma unroll
    for(int p = 0; p < 8; p++) ag[(ty*8+p)*Hc + c] = acc[p];
    __syncthreads();

    const float* wo1h = Wo1 + l*2*Hc*Hc;
    const float* wo1a = wo1h + Hc*Hc;
    #pragma unroll
    for(int p = 0; p < 8; p++) acc[p] = bo1[l*Hc + c];
    #pragma unroll 4
    for(int k = 0; k < Hc; k++){
        float w1 = wo1h[k*Hc + c], w2 = wo1a[k*Hc + c];
        #pragma unroll
        for(int p = 0; p < 8; p++)
            acc[p] += hs[(ty*8+p)*Hc + k]*w1 + ag[(ty*8+p)*Hc + k]*w2;
    }
    #pragma unroll
    for(int p = 0; p < 8; p++) op1[(ty*8+p)*Hc + c] = fmaxf(acc[p], 0.f);
    __syncthreads();

    const float* wo2 = Wo2 + l*Hc*Hc;
    #pragma unroll
    for(int p = 0; p < 8; p++) acc[p] = bo2[l*Hc + c];
    #pragma unroll 4
    for(int k = 0; k < Hc; k++){
        float w = wo2[k*Hc + c];
        #pragma unroll
        for(int p = 0; p < 8; p++) acc[p] += op1[(ty*8+p)*Hc + k] * w;
    }
    #pragma unroll
    for(int p = 0; p < 8; p++){
        int r = ty*8 + p;
        ag[r*Hc + c] = hs[r*Hc + c] + acc[p];
    }
    __syncthreads();

    {
        int row = tid >> 4, l16 = tid & 15;
        float s = 0.f, s2 = 0.f;
        #pragma unroll
        for(int q = 0; q < 8; q++){
            float v = ag[row*Hc + l16 + q*16];
            s += v; s2 += v*v;
        }
        #pragma unroll
        for(int m = 8; m > 0; m >>= 1){
            s  += __shfl_xor_sync(0xffffffffu, s, m);
            s2 += __shfl_xor_sync(0xffffffffu, s2, m);
        }
        if(l16 == 0){
            float m_ = s * (1.f/128.f);
            mu[row] = m_;
            rsd[row] = rsqrtf(s2 * (1.f/128.f) - m_*m_ + 1e-5f);
        }
    }
    __syncthreads();
    const float* lg = lng + l*Hc;
    const float* lb = lnb + l*Hc;
    #pragma unroll
    for(int p = 0; p < 8; p++){
        int r = ty*8 + p;
        float x = ag[r*Hc + c];
        float hn = ((x - mu[r]) * rsd[r] * lg[c] + lb[c]) * vmsh[r];
        g_h[(size_t)(row0+r)*Hc + c] = hn;
        hs[r*Hc + c] = hn;
    }

    if(has_next){
        __syncthreads();
        int ln = l + 1;
        const float* was = Wa1 + ln*3*Hc*Hc;
        const float* wad = was + Hc*Hc;
        const float* wms = Wm1 + ln*2*Hc*Hc;
        float aa[8], dd[8], mm[8];
        #pragma unroll
        for(int p = 0; p < 8; p++){ aa[p]=0.f; dd[p]=0.f; mm[p]=0.f; }
        #pragma unroll 4
        for(int k = 0; k < Hc; k++){
            float w1 = was[k*Hc + c], w2 = wad[k*Hc + c], w3 = wms[k*Hc + c];
            #pragma unroll
            for(int p = 0; p < 8; p++){
                float h = hs[(ty*8+p)*Hc + k];
                aa[p] += h*w1; dd[p] += h*w2; mm[p] += h*w3;
            }
        }
        #pragma unroll
        for(int p = 0; p < 8; p++){
            size_t r = (size_t)(row0 + ty*8 + p)*Hc + c;
            g_sa[r] = aa[p]; g_da[r] = dd[p]; g_sm[r] = mm[p];
        }
    }
}

// ---------------- decoder ----------------
__global__ void k_dec(const float* __restrict__ hist, const float* __restrict__ mask,
                      const float* __restrict__ hg, const float* __restrict__ hb,
                      const float* __restrict__ Wh1, const float* __restrict__ bh1,
                      const float* __restrict__ Wh2, const float* __restrict__ bh2,
                      float* __restrict__ out){
    int b = blockIdx.x; int t = threadIdx.x;
    __shared__ float x[136], xn[136], hid[Hc];
    __shared__ float red2[4];
    float mv = mask[b*Lc + t];
    float s = mv;
    #pragma unroll
    for(int sft = 16; sft > 0; sft >>= 1) s += __shfl_xor_sync(0xffffffffu, s, sft);
    if((t & 31) == 0) red2[t >> 5] = s;
    __syncthreads();
    float tot = red2[0]+red2[1]+red2[2]+red2[3];
    int vc = (int)tot;
    vc = min(max(vc, 1), Lc);
    int last = vc - 1;

    if(t < Dc) x[t] = hist[((size_t)b*Lc + last)*Dc + t];
    x[Dc + t] = g_h[((size_t)b*Lc + last)*Hc + t];
    __syncthreads();
    float s1 = x[t] + ((t < 8) ? x[128 + t] : 0.f);
    #pragma unroll
    for(int sft = 16; sft > 0; sft >>= 1) s1 += __shfl_xor_sync(0xffffffffu, s1, sft);
    __syncthreads();
    if((t & 31) == 0) red2[t >> 5] = s1;
    __syncthreads();
    float mu = (red2[0]+red2[1]+red2[2]+red2[3]) * (1.f/136.f);
    float d0 = x[t] - mu;
    float s2 = d0*d0;
    if(t < 8){ float d1 = x[128 + t] - mu; s2 += d1*d1; }
    #pragma unroll
    for(int sft = 16; sft > 0; sft >>= 1) s2 += __shfl_xor_sync(0xffffffffu, s2, sft);
    __syncthreads();
    if((t & 31) == 0) red2[t >> 5] = s2;
    __syncthreads();
    float rs = rsqrtf((red2[0]+red2[1]+red2[2]+red2[3]) * (1.f/136.f) + 1e-5f);
    xn[t] = (x[t] - mu) * rs * hg[t] + hb[t];
    if(t < 8) xn[128 + t] = (x[128 + t] - mu) * rs * hg[128 + t] + hb[128 + t];
    __syncthreads();
    float h_ = bh1[t];
    for(int k = 0; k < 136; k++) h_ += xn[k]*Wh1[k*Hc + t];
    hid[t] = fmaxf(h_, 0.f);
    __syncthreads();
    if(t < 24){
        float p = bh2[t];
        for(int k = 0; k < Hc; k++) p += hid[k]*Wh2[k*24 + t];
        if(isnan(p)) p = 0.f;
        else if(isinf(p)) p = (p > 0.f) ? 1e4f : -1e4f;
        out[b*24 + t] = p;
    }
}

__global__ void k_copyh(float* __restrict__ out){
    int i = blockIdx.x*blockDim.x + threadIdx.x;
    out[384 + i] = g_h[i];
}

// ---------------- launch ----------------
extern "C" void kernel_launch(void* const* d_in, const int* in_sizes, int n_in,
                              void* d_out, int out_size){
    const float* hist = (const float*)d_in[0];
    const float* mask = (const float*)d_in[1];
    const float* Wp   = (const float*)d_in[2];
    const float* bp   = (const float*)d_in[3];
    const float* We1  = (const float*)d_in[4];
    const float* be1  = (const float*)d_in[5];
    const float* We2  = (const float*)d_in[6];
    const float* be2  = (const float*)d_in[7];
    const float* Wa1  = (const float*)d_in[8];
    const float* ba1  = (const float*)d_in[9];
    const float* wa2  = (const float*)d_in[10];
    const float* ba2  = (const float*)d_in[11];
    const float* Wm1  = (const float*)d_in[12];
    const float* bm1  = (const float*)d_in[13];
    const float* Wm2  = (const float*)d_in[14];
    const float* bm2  = (const float*)d_in[15];
    const float* Wo1  = (const float*)d_in[16];
    const float* bo1  = (const float*)d_in[17];
    const float* Wo2  = (const float*)d_in[18];
    const float* bo2  = (const float*)d_in[19];
    const float* lng  = (const float*)d_in[20];
    const float* lnb  = (const float*)d_in[21];
    const float* hg   = (const float*)d_in[22];
    const float* hbv  = (const float*)d_in[23];
    const float* Wh1  = (const float*)d_in[24];
    const float* bh1  = (const float*)d_in[25];
    const float* Wh2  = (const float*)d_in[26];
    const float* bh2  = (const float*)d_in[27];
    float* out = (float*)d_out;

    cudaFuncSetAttribute(k_main8, cudaFuncAttributeMaxDynamicSharedMemorySize, 4*TILE_BYTES);

    k_ts<<<1, 32>>>(hist);
    k_prepwb<<<NLc*129, Hc>>>(We2, be2, Wa1, Wm1, ba1, bm1);
    k_h0s<<<Bc*Lc/16, 256>>>(hist, mask, Wp, bp, Wa1, Wm1);
    for(int l = 0; l < NLc; l++){
        k_main8<<<Bc*Lc, 512, 4*TILE_BYTES>>>(l, hist, mask, We1, be1, wa2, ba2);
        k_post2<<<Bc*Lc/16, 256>>>(l, (l+1 < NLc) ? 1 : 0, mask,
                                   Wm2, bm2, Wo1, bo1, Wo2, bo2, lng, lnb, Wa1, Wm1);
    }
    k_dec<<<Bc, Hc>>>(hist, mask, hg, hbv, Wh1, bh1, Wh2, bh2, out);
    if(out_size >= 384 + Bc*Lc*Hc){
        k_copyh<<<(Bc*Lc*Hc)/256, 256>>>(out);
    }
}

// round 10
// speedup vs baseline: 3.0329x; 1.2097x over previous
#include <cuda_runtime.h>
#include <cuda_bf16.h>
#include <math.h>
#include <stdint.h>

#define Bc 16
#define Lc 128
#define Dc 8
#define Hc 128
#define NLc 2

// bf16 tile geometry: [128 rows][136 cols] bf16, pitch 272B
#define WPITCH 136
#define TILE_ELEMS (128*WPITCH)          // 17408
#define TILE_BYTES (TILE_ELEMS*2)        // 34816

// ---------------- scratch (static device globals; no allocation) ----------------
__device__ __align__(16) float g_ts[Bc*Lc];
__device__ __align__(16) float g_h[Bc*Lc*Hc];
__device__ __align__(16) float g_sa[Bc*Lc*Hc];
__device__ __align__(16) float g_da[Bc*Lc*Hc];
__device__ __align__(16) float g_sm[Bc*Lc*Hc];
__device__ __align__(16) float g_aggpre[Bc*Lc*Hc];
__device__ __align__(16) float g_ba[NLc*Hc];
__device__ __align__(16) float g_bm[NLc*Hc];
// folded weights as bf16, [k][c] rows padded to 136: per layer Wa | Wm
__device__ __align__(16) __nv_bfloat16 g_Wbf[NLc*2*TILE_ELEMS];

// ---------------- helpers ----------------
__device__ __forceinline__ uint32_t smem_u32(const void* p){
    uint32_t a;
    asm("{ .reg .u64 t; cvta.to.shared.u64 t, %1; cvt.u32.u64 %0, t; }" : "=r"(a) : "l"(p));
    return a;
}
__device__ __forceinline__ void cp16(void* dst_smem, const void* src){
    unsigned sdst = (unsigned)__cvta_generic_to_shared(dst_smem);
    asm volatile("cp.async.cg.shared.global [%0], [%1], 16;" :: "r"(sdst), "l"(src));
}
__device__ __forceinline__ float tanh_fast(float x){
    float r; asm("tanh.approx.f32 %0, %1;" : "=f"(r) : "f"(x)); return r;
}
__device__ __forceinline__ void ldsm4(uint32_t &r0,uint32_t &r1,uint32_t &r2,uint32_t &r3,uint32_t a){
    asm volatile("ldmatrix.sync.aligned.m8n8.x4.shared.b16 {%0,%1,%2,%3},[%4];"
        : "=r"(r0),"=r"(r1),"=r"(r2),"=r"(r3) : "r"(a));
}
__device__ __forceinline__ void ldsm4t(uint32_t &r0,uint32_t &r1,uint32_t &r2,uint32_t &r3,uint32_t a){
    asm volatile("ldmatrix.sync.aligned.m8n8.x4.trans.shared.b16 {%0,%1,%2,%3},[%4];"
        : "=r"(r0),"=r"(r1),"=r"(r2),"=r"(r3) : "r"(a));
}
__device__ __forceinline__ void mma16816(float* d, uint32_t a0,uint32_t a1,uint32_t a2,uint32_t a3,
                                         uint32_t b0,uint32_t b1){
    asm volatile("mma.sync.aligned.m16n8k16.row.col.f32.bf16.bf16.f32 "
        "{%0,%1,%2,%3},{%4,%5,%6,%7},{%8,%9},{%0,%1,%2,%3};"
        : "+f"(d[0]),"+f"(d[1]),"+f"(d[2]),"+f"(d[3])
        : "r"(a0),"r"(a1),"r"(a2),"r"(a3),"r"(b0),"r"(b1));
}
// pack two floats to bf16x2 (v0 -> low half, v1 -> high)
__device__ __forceinline__ uint32_t packbf2(float v0, float v1){
    uint32_t r; asm("cvt.rn.bf16x2.f32 %0, %1, %2;" : "=r"(r) : "f"(v1), "f"(v0)); return r;
}

// ---------------- cumsum of ts ----------------
__global__ void k_ts(const float* __restrict__ hist){
    int b = threadIdx.x;
    if(b < Bc){
        float c = 0.f;
        for(int t = 0; t < Lc; t++){
            float v = hist[(b*Lc+t)*Dc + 5];
            c += fmaxf(v, 0.f);
            g_ts[b*Lc+t] = c;
        }
    }
}

// ---------------- folded weights -> bf16 padded tiles ----------------
__global__ void k_prepwb(const float* __restrict__ We2, const float* __restrict__ be2,
                         const float* __restrict__ Wa1, const float* __restrict__ Wm1,
                         const float* __restrict__ ba1, const float* __restrict__ bm1){
    int l = blockIdx.x / 129, kk = blockIdx.x % 129;
    int c = threadIdx.x;
    __shared__ float ws[Hc];
    if(kk < Hc) ws[c] = We2[l*Hc*Hc + kk*Hc + c];
    else        ws[c] = be2[l*Hc + c];
    __syncthreads();
    const float* wa = Wa1 + l*3*Hc*Hc + 2*Hc*Hc;
    const float* wm = Wm1 + l*2*Hc*Hc + Hc*Hc;
    float sa = 0.f, sm = 0.f;
    #pragma unroll 4
    for(int r = 0; r < Hc; r++){ float w = ws[r]; sa += w*wa[r*Hc + c]; sm += w*wm[r*Hc + c]; }
    if(kk < Hc){
        __nv_bfloat16* base = g_Wbf + (size_t)l*2*TILE_ELEMS;
        base[             kk*WPITCH + c] = __float2bfloat16(sa);
        base[TILE_ELEMS + kk*WPITCH + c] = __float2bfloat16(sm);
    } else {
        g_ba[l*Hc + c] = sa + ba1[l*Hc + c];
        g_bm[l*Hc + c] = sm + bm1[l*Hc + c];
    }
}

// ---------------- h0 (16 rows per block) + sa/da/sm for layer 0 ----------------
__global__ __launch_bounds__(256)
void k_h0s(const float* __restrict__ hist, const float* __restrict__ mask,
           const float* __restrict__ Wp, const float* __restrict__ bp,
           const float* __restrict__ Wa1, const float* __restrict__ Wm1){
    int row0 = blockIdx.x * 16;
    int tid = threadIdx.x;
    int c = tid & 127, ty = tid >> 7;
    __shared__ float xs[16*Dc], hs[16*Hc], vmsh[16];
    if(tid < 128) xs[tid] = hist[(size_t)row0*Dc + tid];
    if(tid < 16)  vmsh[tid] = mask[row0 + tid] > 0.f ? 1.f : 0.f;
    __syncthreads();
    float acc[8];
    #pragma unroll
    for(int p = 0; p < 8; p++) acc[p] = bp[c];
    #pragma unroll
    for(int d = 0; d < Dc; d++){
        float w = Wp[d*Hc + c];
        #pragma unroll
        for(int p = 0; p < 8; p++) acc[p] += xs[(ty*8+p)*Dc + d] * w;
    }
    #pragma unroll
    for(int p = 0; p < 8; p++){
        int r = ty*8 + p;
        float h = acc[p] * vmsh[r];
        hs[r*Hc + c] = h;
        g_h[(size_t)(row0+r)*Hc + c] = h;
    }
    __syncthreads();
    const float* was = Wa1;
    const float* wad = was + Hc*Hc;
    const float* wms = Wm1;
    float aa[8], dd[8], mm[8];
    #pragma unroll
    for(int p = 0; p < 8; p++){ aa[p]=0.f; dd[p]=0.f; mm[p]=0.f; }
    #pragma unroll 4
    for(int k = 0; k < Hc; k++){
        float w1 = was[k*Hc + c], w2 = wad[k*Hc + c], w3 = wms[k*Hc + c];
        #pragma unroll
        for(int p = 0; p < 8; p++){
            float h = hs[(ty*8+p)*Hc + k];
            aa[p] += h*w1; dd[p] += h*w2; mm[p] += h*w3;
        }
    }
    #pragma unroll
    for(int p = 0; p < 8; p++){
        size_t r = (size_t)(row0 + ty*8 + p)*Hc + c;
        g_sa[r] = aa[p]; g_da[r] = dd[p]; g_sm[r] = mm[p];
    }
}

// ---------------- main fused kernel: HMMA (T bf16 x W bf16) + att + softmax + msg agg ----------------
// dynamic SMEM bytes:
//   [0      , 34816 ) T     [j][136] bf16
//   [34816  , 69632 ) Wa    [k][136] bf16
//   [69632  ,104448 ) Wm
// post-MMA, T region reused as f32 msg partial buffer su[32][130]
extern __shared__ char dsmc[];

__global__ __launch_bounds__(512, 1)
void k_main9(int l, const float* __restrict__ hist, const float* __restrict__ mask,
             const float* __restrict__ We1, const float* __restrict__ be1,
             const float* __restrict__ wa2, const float* __restrict__ ba2){
    __shared__ float we1s[4*Hc], be1s[Hc], sab[Hc], smb[Hc], wa2s[Hc];
    __shared__ float attp[2][Lc], wsoft[Lc], red[8], redp[4][Hc];

    int bi = blockIdx.x;
    int b = bi >> 7, i = bi & 127;
    int tid = threadIdx.x;
    int wid = tid >> 5, lane = tid & 31;
    int j = tid & 127;

    // async copy both weight tiles (69632 B = 4352 x 16B)
    {
        const char* wsrc = (const char*)(g_Wbf + (size_t)l*2*TILE_ELEMS);
        char* wdst = dsmc + TILE_BYTES;
        #pragma unroll
        for(int q = 0; q < 8; q++){
            int off = (q*512 + tid)*16;
            cp16(wdst + off, wsrc + off);
        }
        if(tid < 256) cp16(wdst + (4096 + tid)*16, wsrc + (4096 + tid)*16);
        asm volatile("cp.async.commit_group;" ::: "memory");
    }

    if(tid < 128){
        #pragma unroll
        for(int q = 0; q < 4; q++) we1s[q*Hc + tid] = We1[l*4*Hc + q*Hc + tid];
        be1s[tid] = be1[l*Hc + tid];
        sab[tid]  = g_sa[(size_t)bi*Hc + tid] + g_ba[l*Hc + tid];
        smb[tid]  = g_sm[(size_t)bi*Hc + tid] + g_bm[l*Hc + tid];
        wa2s[tid] = wa2[l*Hc + tid];
    }

    // edge features for this thread's j
    const float* hb_ = hist + (size_t)b*Lc*Dc;
    float vldj, vi;
    {
        float lat_i = hb_[i*Dc + 0], lon_i = hb_[i*Dc + 1], src_i = hb_[i*Dc + 6];
        float ts_i = g_ts[b*Lc + i];
        float latj = hb_[j*Dc + 0], lonj = hb_[j*Dc + 1], srcj = hb_[j*Dc + 6];
        float tsj = g_ts[b*Lc + j];
        float dl = lat_i - latj, dn = lon_i - lonj;
        float dist = sqrtf(dl*dl + dn*dn + 1e-8f);
        float dtv = fabsf(ts_i - tsj) * (1.f/300.f);
        float ssv = (src_i == srcj) ? 1.f : 0.f;
        float diag = (j == i) ? 1.f : 0.f;
        vldj = (mask[b*Lc + j] > 0.f) ? 1.f : 0.f;
        vi   = (mask[b*Lc + i] > 0.f) ? 1.f : 0.f;
        __syncthreads();   // we1s/be1s ready

        // T build: thread owns row j, quarter q -> 32 k values (16 bf16x2 pairs)
        int q = tid >> 7;
        char* Th = dsmc + (size_t)j*272;
        #pragma unroll
        for(int kk = 0; kk < 16; kk++){
            int k = q*32 + kk*2;
            float v0 = fmaxf(dist*we1s[k]   + dtv*we1s[Hc+k]   + ssv*we1s[2*Hc+k]   + diag*we1s[3*Hc+k]   + be1s[k],   0.f);
            float v1 = fmaxf(dist*we1s[k+1] + dtv*we1s[Hc+k+1] + ssv*we1s[2*Hc+k+1] + diag*we1s[3*Hc+k+1] + be1s[k+1], 0.f);
            *(uint32_t*)(Th + k*2) = packbf2(v0, v1);
        }
    }
    asm volatile("cp.async.wait_group 0;" ::: "memory");
    __syncthreads();   // T + W ready

    // ---------------- HMMA GEMM ----------------
    // warp: g_w = wid>>3 (0=att/Wa, 1=msg/Wm); within group: jt = (wl&3)*32, ch = (wl>>2)*64
    int g_w = wid >> 3;
    int wl = wid & 7;
    int jt = (wl & 3) * 32;
    int ch = (wl >> 2) * 64;
    uint32_t base = smem_u32(dsmc);
    uint32_t aH0 = base + (uint32_t)((jt + (lane & 15))*272 + ((lane >> 4) << 4));
    uint32_t aH1 = aH0 + 16*272;
    uint32_t wB  = base + (uint32_t)(TILE_BYTES + (g_w ? TILE_BYTES : 0)
                   + (lane & 15)*272 + ch*2 + ((lane >> 4) << 4));

    // acc layout: [t16][nt][sub][4] -> t16*32 + nt*8 + sub*4
    float acc[64];
    #pragma unroll
    for(int q = 0; q < 64; q++) acc[q] = 0.f;

    #pragma unroll
    for(int ks = 0; ks < 8; ks++){
        uint32_t a0,a1,a2,a3, c0,c1,c2,c3;
        ldsm4(a0,a1,a2,a3, aH0 + ks*32);   // tile0
        ldsm4(c0,c1,c2,c3, aH1 + ks*32);   // tile1
        uint32_t wrow = wB + ks*4352;
        #pragma unroll
        for(int nt = 0; nt < 4; nt++){
            uint32_t B0,B1,B2,B3;
            ldsm4t(B0,B1,B2,B3, wrow + nt*32);
            float* d00 = acc + nt*8;
            float* d01 = d00 + 4;
            float* d10 = acc + 32 + nt*8;
            float* d11 = d10 + 4;
            mma16816(d00, a0,a1,a2,a3, B0,B1);
            mma16816(d01, a0,a1,a2,a3, B2,B3);
            mma16816(d10, c0,c1,c2,c3, B0,B1);
            mma16816(d11, c0,c1,c2,c3, B2,B3);
        }
    }

    // d-fragment mapping (per t16/nt/sub tile, cols = ch + nt*16 + sub*8):
    //   lane (gq=lane>>2, tq=lane&3): d[0],d[1] = rows jt+t16*16+gq, cols +2tq,+2tq+1
    //                                 d[2],d[3] = row +8
    int gq = lane >> 2, tq = lane & 3;

    // ---------------- attention epilogue (group 0) ----------------
    if(g_w == 0){
        #pragma unroll
        for(int t16 = 0; t16 < 2; t16++){
            int jA = jt + t16*16 + gq, jB = jA + 8;
            const float* daA = g_da + ((size_t)(b*Lc + jA))*Hc;
            const float* daB = daA + 8*Hc;
            float sA = 0.f, sB = 0.f;
            #pragma unroll
            for(int nt = 0; nt < 4; nt++){
                #pragma unroll
                for(int sub = 0; sub < 2; sub++){
                    int c0 = ch + nt*16 + sub*8 + tq*2;
                    const float* d = acc + t16*32 + nt*8 + sub*4;
                    float2 dA = *(const float2*)(daA + c0);
                    float2 dB = *(const float2*)(daB + c0);
                    sA += wa2s[c0]  *tanh_fast(sab[c0]  + dA.x + d[0]);
                    sA += wa2s[c0+1]*tanh_fast(sab[c0+1]+ dA.y + d[1]);
                    sB += wa2s[c0]  *tanh_fast(sab[c0]  + dB.x + d[2]);
                    sB += wa2s[c0+1]*tanh_fast(sab[c0+1]+ dB.y + d[3]);
                }
            }
            sA += __shfl_xor_sync(0xffffffffu, sA, 1);
            sA += __shfl_xor_sync(0xffffffffu, sA, 2);
            sB += __shfl_xor_sync(0xffffffffu, sB, 1);
            sB += __shfl_xor_sync(0xffffffffu, sB, 2);
            if(tq == 0){ attp[ch >> 6][jA] = sA; attp[ch >> 6][jB] = sB; }
        }
    }
    __syncthreads();

    // ---------------- softmax over j (first 128 threads) ----------------
    const float inv = 0.088388347648318440550f;   // 1/sqrt(128)
    float sc = -1e9f, e = 0.f;
    if(tid < 128){
        float a = (attp[0][tid] + attp[1][tid] + ba2[l]) * inv;
        bool ok = (vldj > 0.f) && (vi > 0.f);
        sc = ok ? a : -1e9f;
        float m = sc;
        #pragma unroll
        for(int s2 = 16; s2 > 0; s2 >>= 1) m = fmaxf(m, __shfl_xor_sync(0xffffffffu, m, s2));
        if((tid & 31) == 0) red[tid >> 5] = m;
    }
    __syncthreads();
    float bmax = fmaxf(fmaxf(red[0], red[1]), fmaxf(red[2], red[3]));
    if(tid < 128){
        e = expf(sc - bmax);
        float s2 = e;
        #pragma unroll
        for(int m = 16; m > 0; m >>= 1) s2 += __shfl_xor_sync(0xffffffffu, s2, m);
        if((tid & 31) == 0) red[4 + (tid >> 5)] = s2;
    }
    __syncthreads();
    if(tid < 128){
        float tot = red[4]+red[5]+red[6]+red[7];
        wsoft[tid] = e / tot;
    }
    __syncthreads();

    // ---------------- message epilogue (group 1) ----------------
    float* su = (float*)dsmc;   // [32 rows][130 f32] partials (T region dead)
    if(g_w == 1){
        float v[16];
        #pragma unroll
        for(int p = 0; p < 16; p++) v[p] = 0.f;
        #pragma unroll
        for(int t16 = 0; t16 < 2; t16++){
            int jA = jt + t16*16 + gq, jB = jA + 8;
            float wA = wsoft[jA], wB2 = wsoft[jB];
            #pragma unroll
            for(int nt = 0; nt < 4; nt++){
                #pragma unroll
                for(int sub = 0; sub < 2; sub++){
                    int c0 = ch + nt*16 + sub*8 + tq*2;
                    const float* d = acc + t16*32 + nt*8 + sub*4;
                    int vi_ = nt*4 + sub*2;
                    v[vi_]   += wA*fmaxf(smb[c0]  + d[0], 0.f) + wB2*fmaxf(smb[c0]  + d[2], 0.f);
                    v[vi_+1] += wA*fmaxf(smb[c0+1]+ d[1], 0.f) + wB2*fmaxf(smb[c0+1]+ d[3], 0.f);
                }
            }
        }
        int p = (wl & 3)*8 + gq;
        #pragma unroll
        for(int nt = 0; nt < 4; nt++){
            #pragma unroll
            for(int sub = 0; sub < 2; sub++){
                int c0 = ch + nt*16 + sub*8 + tq*2;
                *(float2*)(su + p*130 + c0) = make_float2(v[nt*4+sub*2], v[nt*4+sub*2+1]);
            }
        }
    }
    __syncthreads();
    {
        int qq = tid >> 7, c = tid & 127;
        float s = 0.f;
        #pragma unroll
        for(int r = 0; r < 8; r++) s += su[(qq*8 + r)*130 + c];
        redp[qq][c] = s;
    }
    __syncthreads();
    if(tid < 128){
        g_aggpre[(size_t)bi*Hc + tid] = redp[0][tid] + redp[1][tid] + redp[2][tid] + redp[3][tid];
    }
}

// ---------------- epilogue per 16 rows ----------------
__global__ __launch_bounds__(256)
void k_post2(int l, int has_next, const float* __restrict__ mask,
             const float* __restrict__ Wm2, const float* __restrict__ bm2,
             const float* __restrict__ Wo1, const float* __restrict__ bo1,
             const float* __restrict__ Wo2, const float* __restrict__ bo2,
             const float* __restrict__ lng, const float* __restrict__ lnb,
             const float* __restrict__ Wa1, const float* __restrict__ Wm1){
    int row0 = blockIdx.x * 16;
    int tid = threadIdx.x;
    int c = tid & 127, ty = tid >> 7;
    __shared__ float hs[16*Hc], as_[16*Hc], ag[16*Hc], op1[16*Hc];
    __shared__ float mu[16], rsd[16], vmsh[16];

    #pragma unroll
    for(int q = 0; q < 8; q++){
        int idx = q*256 + tid;
        hs[idx]  = g_h[(size_t)row0*Hc + idx];
        as_[idx] = g_aggpre[(size_t)row0*Hc + idx];
    }
    if(tid < 16) vmsh[tid] = mask[row0 + tid] > 0.f ? 1.f : 0.f;
    __syncthreads();

    float acc[8];
    const float* wm2 = Wm2 + l*Hc*Hc;
    #pragma unroll
    for(int p = 0; p < 8; p++) acc[p] = bm2[l*Hc + c];
    #pragma unroll 4
    for(int k = 0; k < Hc; k++){
        float w = wm2[k*Hc + c];
        #pragma unroll
        for(int p = 0; p < 8; p++) acc[p] += as_[(ty*8+p)*Hc + k] * w;
    }
    #pragma unroll
    for(int p = 0; p < 8; p++) ag[(ty*8+p)*Hc + c] = acc[p];
    __syncthreads();

    const float* wo1h = Wo1 + l*2*Hc*Hc;
    const float* wo1a = wo1h + Hc*Hc;
    #pragma unroll
    for(int p = 0; p < 8; p++) acc[p] = bo1[l*Hc + c];
    #pragma unroll 4
    for(int k = 0; k < Hc; k++){
        float w1 = wo1h[k*Hc + c], w2 = wo1a[k*Hc + c];
        #pragma unroll
        for(int p = 0; p < 8; p++)
            acc[p] += hs[(ty*8+p)*Hc + k]*w1 + ag[(ty*8+p)*Hc + k]*w2;
    }
    #pragma unroll
    for(int p = 0; p < 8; p++) op1[(ty*8+p)*Hc + c] = fmaxf(acc[p], 0.f);
    __syncthreads();

    const float* wo2 = Wo2 + l*Hc*Hc;
    #pragma unroll
    for(int p = 0; p < 8; p++) acc[p] = bo2[l*Hc + c];
    #pragma unroll 4
    for(int k = 0; k < Hc; k++){
        float w = wo2[k*Hc + c];
        #pragma unroll
        for(int p = 0; p < 8; p++) acc[p] += op1[(ty*8+p)*Hc + k] * w;
    }
    #pragma unroll
    for(int p = 0; p < 8; p++){
        int r = ty*8 + p;
        ag[r*Hc + c] = hs[r*Hc + c] + acc[p];
    }
    __syncthreads();

    {
        int row = tid >> 4, l16 = tid & 15;
        float s = 0.f, s2 = 0.f;
        #pragma unroll
        for(int q = 0; q < 8; q++){
            float v = ag[row*Hc + l16 + q*16];
            s += v; s2 += v*v;
        }
        #pragma unroll
        for(int m = 8; m > 0; m >>= 1){
            s  += __shfl_xor_sync(0xffffffffu, s, m);
            s2 += __shfl_xor_sync(0xffffffffu, s2, m);
        }
        if(l16 == 0){
            float m_ = s * (1.f/128.f);
            mu[row] = m_;
            rsd[row] = rsqrtf(s2 * (1.f/128.f) - m_*m_ + 1e-5f);
        }
    }
    __syncthreads();
    const float* lg = lng + l*Hc;
    const float* lb = lnb + l*Hc;
    #pragma unroll
    for(int p = 0; p < 8; p++){
        int r = ty*8 + p;
        float x = ag[r*Hc + c];
        float hn = ((x - mu[r]) * rsd[r] * lg[c] + lb[c]) * vmsh[r];
        g_h[(size_t)(row0+r)*Hc + c] = hn;
        hs[r*Hc + c] = hn;
    }

    if(has_next){
        __syncthreads();
        int ln = l + 1;
        const float* was = Wa1 + ln*3*Hc*Hc;
        const float* wad = was + Hc*Hc;
        const float* wms = Wm1 + ln*2*Hc*Hc;
        float aa[8], dd[8], mm[8];
        #pragma unroll
        for(int p = 0; p < 8; p++){ aa[p]=0.f; dd[p]=0.f; mm[p]=0.f; }
        #pragma unroll 4
        for(int k = 0; k < Hc; k++){
            float w1 = was[k*Hc + c], w2 = wad[k*Hc + c], w3 = wms[k*Hc + c];
            #pragma unroll
            for(int p = 0; p < 8; p++){
                float h = hs[(ty*8+p)*Hc + k];
                aa[p] += h*w1; dd[p] += h*w2; mm[p] += h*w3;
            }
        }
        #pragma unroll
        for(int p = 0; p < 8; p++){
            size_t r = (size_t)(row0 + ty*8 + p)*Hc + c;
            g_sa[r] = aa[p]; g_da[r] = dd[p]; g_sm[r] = mm[p];
        }
    }
}

// ---------------- decoder ----------------
__global__ void k_dec(const float* __restrict__ hist, const float* __restrict__ mask,
                      const float* __restrict__ hg, const float* __restrict__ hb,
                      const float* __restrict__ Wh1, const float* __restrict__ bh1,
                      const float* __restrict__ Wh2, const float* __restrict__ bh2,
                      float* __restrict__ out){
    int b = blockIdx.x; int t = threadIdx.x;
    __shared__ float x[136], xn[136], hid[Hc];
    __shared__ float red2[4];
    float mv = mask[b*Lc + t];
    float s = mv;
    #pragma unroll
    for(int sft = 16; sft > 0; sft >>= 1) s += __shfl_xor_sync(0xffffffffu, s, sft);
    if((t & 31) == 0) red2[t >> 5] = s;
    __syncthreads();
    float tot = red2[0]+red2[1]+red2[2]+red2[3];
    int vc = (int)tot;
    vc = min(max(vc, 1), Lc);
    int last = vc - 1;

    if(t < Dc) x[t] = hist[((size_t)b*Lc + last)*Dc + t];
    x[Dc + t] = g_h[((size_t)b*Lc + last)*Hc + t];
    __syncthreads();
    float s1 = x[t] + ((t < 8) ? x[128 + t] : 0.f);
    #pragma unroll
    for(int sft = 16; sft > 0; sft >>= 1) s1 += __shfl_xor_sync(0xffffffffu, s1, sft);
    __syncthreads();
    if((t & 31) == 0) red2[t >> 5] = s1;
    __syncthreads();
    float mu = (red2[0]+red2[1]+red2[2]+red2[3]) * (1.f/136.f);
    float d0 = x[t] - mu;
    float s2 = d0*d0;
    if(t < 8){ float d1 = x[128 + t] - mu; s2 += d1*d1; }
    #pragma unroll
    for(int sft = 16; sft > 0; sft >>= 1) s2 += __shfl_xor_sync(0xffffffffu, s2, sft);
    __syncthreads();
    if((t & 31) == 0) red2[t >> 5] = s2;
    __syncthreads();
    float rs = rsqrtf((red2[0]+red2[1]+red2[2]+red2[3]) * (1.f/136.f) + 1e-5f);
    xn[t] = (x[t] - mu) * rs * hg[t] + hb[t];
    if(t < 8) xn[128 + t] = (x[128 + t] - mu) * rs * hg[128 + t] + hb[128 + t];
    __syncthreads();
    float h_ = bh1[t];
    for(int k = 0; k < 136; k++) h_ += xn[k]*Wh1[k*Hc + t];
    hid[t] = fmaxf(h_, 0.f);
    __syncthreads();
    if(t < 24){
        float p = bh2[t];
        for(int k = 0; k < Hc; k++) p += hid[k]*Wh2[k*24 + t];
        if(isnan(p)) p = 0.f;
        else if(isinf(p)) p = (p > 0.f) ? 1e4f : -1e4f;
        out[b*24 + t] = p;
    }
}

__global__ void k_copyh(float* __restrict__ out){
    int i = blockIdx.x*blockDim.x + threadIdx.x;
    out[384 + i] = g_h[i];
}

// ---------------- launch ----------------
extern "C" void kernel_launch(void* const* d_in, const int* in_sizes, int n_in,
                              void* d_out, int out_size){
    const float* hist = (const float*)d_in[0];
    const float* mask = (const float*)d_in[1];
    const float* Wp   = (const float*)d_in[2];
    const float* bp   = (const float*)d_in[3];
    const float* We1  = (const float*)d_in[4];
    const float* be1  = (const float*)d_in[5];
    const float* We2  = (const float*)d_in[6];
    const float* be2  = (const float*)d_in[7];
    const float* Wa1  = (const float*)d_in[8];
    const float* ba1  = (const float*)d_in[9];
    const float* wa2  = (const float*)d_in[10];
    const float* ba2  = (const float*)d_in[11];
    const float* Wm1  = (const float*)d_in[12];
    const float* bm1  = (const float*)d_in[13];
    const float* Wm2  = (const float*)d_in[14];
    const float* bm2  = (const float*)d_in[15];
    const float* Wo1  = (const float*)d_in[16];
    const float* bo1  = (const float*)d_in[17];
    const float* Wo2  = (const float*)d_in[18];
    const float* bo2  = (const float*)d_in[19];
    const float* lng  = (const float*)d_in[20];
    const float* lnb  = (const float*)d_in[21];
    const float* hg   = (const float*)d_in[22];
    const float* hbv  = (const float*)d_in[23];
    const float* Wh1  = (const float*)d_in[24];
    const float* bh1  = (const float*)d_in[25];
    const float* Wh2  = (const float*)d_in[26];
    const float* bh2  = (const float*)d_in[27];
    float* out = (float*)d_out;

    cudaFuncSetAttribute(k_main9, cudaFuncAttributeMaxDynamicSharedMemorySize, 3*TILE_BYTES);

    k_ts<<<1, 32>>>(hist);
    k_prepwb<<<NLc*129, Hc>>>(We2, be2, Wa1, Wm1, ba1, bm1);
    k_h0s<<<Bc*Lc/16, 256>>>(hist, mask, Wp, bp, Wa1, Wm1);
    for(int l = 0; l < NLc; l++){
        k_main9<<<Bc*Lc, 512, 3*TILE_BYTES>>>(l, hist, mask, We1, be1, wa2, ba2);
        k_post2<<<Bc*Lc/16, 256>>>(l, (l+1 < NLc) ? 1 : 0, mask,
                                   Wm2, bm2, Wo1, bo1, Wo2, bo2, lng, lnb, Wa1, Wm1);
    }
    k_dec<<<Bc, Hc>>>(hist, mask, hg, hbv, Wh1, bh1, Wh2, bh2, out);
    if(out_size >= 384 + Bc*Lc*Hc){
        k_copyh<<<(Bc*Lc*Hc)/256, 256>>>(out);
    }
}

// round 11
// speedup vs baseline: 3.2550x; 1.0732x over previous
#include <cuda_runtime.h>
#include <cuda_bf16.h>
#include <math.h>
#include <stdint.h>

#define Bc 16
#define Lc 128
#define Dc 8
#define Hc 128
#define NLc 2

// bf16 tile geometry: [128 rows][136 cols] bf16, pitch 272B
#define WPITCH 136
#define TILE_ELEMS (128*WPITCH)          // 17408
#define TILE_BYTES (TILE_ELEMS*2)        // 34816

// ---------------- scratch (static device globals; no allocation) ----------------
__device__ __align__(16) float g_ts[Bc*Lc];
__device__ __align__(16) float g_h[Bc*Lc*Hc];
__device__ __align__(16) float g_sa[Bc*Lc*Hc];
__device__ __align__(16) float g_da[Bc*Lc*Hc];
__device__ __align__(16) float g_sm[Bc*Lc*Hc];
__device__ __align__(16) float g_aggpre[Bc*Lc*Hc];
__device__ __align__(16) float g_ba[NLc*Hc];
__device__ __align__(16) float g_bm[NLc*Hc];
// folded weights as bf16, [k][c] rows padded to 136: per layer Wa | Wm
__device__ __align__(16) __nv_bfloat16 g_Wbf[NLc*2*TILE_ELEMS];

// ---------------- helpers ----------------
__device__ __forceinline__ uint32_t smem_u32(const void* p){
    uint32_t a;
    asm("{ .reg .u64 t; cvta.to.shared.u64 t, %1; cvt.u32.u64 %0, t; }" : "=r"(a) : "l"(p));
    return a;
}
__device__ __forceinline__ void cp16(void* dst_smem, const void* src){
    unsigned sdst = (unsigned)__cvta_generic_to_shared(dst_smem);
    asm volatile("cp.async.cg.shared.global [%0], [%1], 16;" :: "r"(sdst), "l"(src));
}
__device__ __forceinline__ float tanh_fast(float x){
    float r; asm("tanh.approx.f32 %0, %1;" : "=f"(r) : "f"(x)); return r;
}
__device__ __forceinline__ void ldsm4(uint32_t &r0,uint32_t &r1,uint32_t &r2,uint32_t &r3,uint32_t a){
    asm volatile("ldmatrix.sync.aligned.m8n8.x4.shared.b16 {%0,%1,%2,%3},[%4];"
        : "=r"(r0),"=r"(r1),"=r"(r2),"=r"(r3) : "r"(a));
}
__device__ __forceinline__ void ldsm4t(uint32_t &r0,uint32_t &r1,uint32_t &r2,uint32_t &r3,uint32_t a){
    asm volatile("ldmatrix.sync.aligned.m8n8.x4.trans.shared.b16 {%0,%1,%2,%3},[%4];"
        : "=r"(r0),"=r"(r1),"=r"(r2),"=r"(r3) : "r"(a));
}
__device__ __forceinline__ void mma16816(float* d, uint32_t a0,uint32_t a1,uint32_t a2,uint32_t a3,
                                         uint32_t b0,uint32_t b1){
    asm volatile("mma.sync.aligned.m16n8k16.row.col.f32.bf16.bf16.f32 "
        "{%0,%1,%2,%3},{%4,%5,%6,%7},{%8,%9},{%0,%1,%2,%3};"
        : "+f"(d[0]),"+f"(d[1]),"+f"(d[2]),"+f"(d[3])
        : "r"(a0),"r"(a1),"r"(a2),"r"(a3),"r"(b0),"r"(b1));
}
// pack two floats to bf16x2 (v0 -> low half, v1 -> high)
__device__ __forceinline__ uint32_t packbf2(float v0, float v1){
    uint32_t r; asm("cvt.rn.bf16x2.f32 %0, %1, %2;" : "=r"(r) : "f"(v1), "f"(v0)); return r;
}

// ---------------- cumsum of ts ----------------
__global__ void k_ts(const float* __restrict__ hist){
    int b = threadIdx.x;
    if(b < Bc){
        float c = 0.f;
        for(int t = 0; t < Lc; t++){
            float v = hist[(b*Lc+t)*Dc + 5];
            c += fmaxf(v, 0.f);
            g_ts[b*Lc+t] = c;
        }
    }
}

// ---------------- folded weights -> bf16 padded tiles ----------------
__global__ void k_prepwb(const float* __restrict__ We2, const float* __restrict__ be2,
                         const float* __restrict__ Wa1, const float* __restrict__ Wm1,
                         const float* __restrict__ ba1, const float* __restrict__ bm1){
    int l = blockIdx.x / 129, kk = blockIdx.x % 129;
    int c = threadIdx.x;
    __shared__ float ws[Hc];
    if(kk < Hc) ws[c] = We2[l*Hc*Hc + kk*Hc + c];
    else        ws[c] = be2[l*Hc + c];
    __syncthreads();
    const float* wa = Wa1 + l*3*Hc*Hc + 2*Hc*Hc;
    const float* wm = Wm1 + l*2*Hc*Hc + Hc*Hc;
    float sa = 0.f, sm = 0.f;
    #pragma unroll 4
    for(int r = 0; r < Hc; r++){ float w = ws[r]; sa += w*wa[r*Hc + c]; sm += w*wm[r*Hc + c]; }
    if(kk < Hc){
        __nv_bfloat16* base = g_Wbf + (size_t)l*2*TILE_ELEMS;
        base[             kk*WPITCH + c] = __float2bfloat16(sa);
        base[TILE_ELEMS + kk*WPITCH + c] = __float2bfloat16(sm);
    } else {
        g_ba[l*Hc + c] = sa + ba1[l*Hc + c];
        g_bm[l*Hc + c] = sm + bm1[l*Hc + c];
    }
}

// ---------------- h0 (16 rows per block) + sa/da/sm for layer 0 ----------------
__global__ __launch_bounds__(256)
void k_h0s(const float* __restrict__ hist, const float* __restrict__ mask,
           const float* __restrict__ Wp, const float* __restrict__ bp,
           const float* __restrict__ Wa1, const float* __restrict__ Wm1){
    int row0 = blockIdx.x * 16;
    int tid = threadIdx.x;
    int c = tid & 127, ty = tid >> 7;
    __shared__ float xs[16*Dc], hs[16*Hc], vmsh[16];
    if(tid < 128) xs[tid] = hist[(size_t)row0*Dc + tid];
    if(tid < 16)  vmsh[tid] = mask[row0 + tid] > 0.f ? 1.f : 0.f;
    __syncthreads();
    float acc[8];
    #pragma unroll
    for(int p = 0; p < 8; p++) acc[p] = bp[c];
    #pragma unroll
    for(int d = 0; d < Dc; d++){
        float w = Wp[d*Hc + c];
        #pragma unroll
        for(int p = 0; p < 8; p++) acc[p] += xs[(ty*8+p)*Dc + d] * w;
    }
    #pragma unroll
    for(int p = 0; p < 8; p++){
        int r = ty*8 + p;
        float h = acc[p] * vmsh[r];
        hs[r*Hc + c] = h;
        g_h[(size_t)(row0+r)*Hc + c] = h;
    }
    __syncthreads();
    const float* was = Wa1;
    const float* wad = was + Hc*Hc;
    const float* wms = Wm1;
    float aa[8], dd[8], mm[8];
    #pragma unroll
    for(int p = 0; p < 8; p++){ aa[p]=0.f; dd[p]=0.f; mm[p]=0.f; }
    #pragma unroll 4
    for(int k = 0; k < Hc; k++){
        float w1 = was[k*Hc + c], w2 = wad[k*Hc + c], w3 = wms[k*Hc + c];
        #pragma unroll
        for(int p = 0; p < 8; p++){
            float h = hs[(ty*8+p)*Hc + k];
            aa[p] += h*w1; dd[p] += h*w2; mm[p] += h*w3;
        }
    }
    #pragma unroll
    for(int p = 0; p < 8; p++){
        size_t r = (size_t)(row0 + ty*8 + p)*Hc + c;
        g_sa[r] = aa[p]; g_da[r] = dd[p]; g_sm[r] = mm[p];
    }
}

// ---------------- main fused kernel: two HMMA phases (all 16 warps each), 2 CTAs/SM ----------------
// dynamic SMEM bytes:
//   [0      , 34816 ) T     [j][136] bf16
//   [34816  , 69632 ) Wa    [k][136] bf16
//   [69632  ,104448 ) Wm
// after msg phase, T region reused as f32 msg partial buffer su[64][130]
extern __shared__ char dsmc[];

__global__ __launch_bounds__(512, 2)
void k_main10(int l, const float* __restrict__ hist, const float* __restrict__ mask,
              const float* __restrict__ We1, const float* __restrict__ be1,
              const float* __restrict__ wa2, const float* __restrict__ ba2){
    __shared__ float we1s[4*Hc], be1s[Hc], sab[Hc], smb[Hc], wa2s[Hc];
    __shared__ float attp[2][Lc], wsoft[Lc], red[8], redp[4][Hc];

    int bi = blockIdx.x;
    int b = bi >> 7, i = bi & 127;
    int tid = threadIdx.x;
    int wid = tid >> 5, lane = tid & 31;
    int j = tid & 127;

    // async copy both weight tiles (69632 B = 4352 x 16B)
    {
        const char* wsrc = (const char*)(g_Wbf + (size_t)l*2*TILE_ELEMS);
        char* wdst = dsmc + TILE_BYTES;
        #pragma unroll
        for(int q = 0; q < 8; q++){
            int off = (q*512 + tid)*16;
            cp16(wdst + off, wsrc + off);
        }
        if(tid < 256) cp16(wdst + (4096 + tid)*16, wsrc + (4096 + tid)*16);
        asm volatile("cp.async.commit_group;" ::: "memory");
    }

    if(tid < 128){
        #pragma unroll
        for(int q = 0; q < 4; q++) we1s[q*Hc + tid] = We1[l*4*Hc + q*Hc + tid];
        be1s[tid] = be1[l*Hc + tid];
        sab[tid]  = g_sa[(size_t)bi*Hc + tid] + g_ba[l*Hc + tid];
        smb[tid]  = g_sm[(size_t)bi*Hc + tid] + g_bm[l*Hc + tid];
        wa2s[tid] = wa2[l*Hc + tid];
    }

    // edge features for this thread's j
    const float* hb_ = hist + (size_t)b*Lc*Dc;
    float vldj, vi;
    {
        float lat_i = hb_[i*Dc + 0], lon_i = hb_[i*Dc + 1], src_i = hb_[i*Dc + 6];
        float ts_i = g_ts[b*Lc + i];
        float latj = hb_[j*Dc + 0], lonj = hb_[j*Dc + 1], srcj = hb_[j*Dc + 6];
        float tsj = g_ts[b*Lc + j];
        float dl = lat_i - latj, dn = lon_i - lonj;
        float dist = sqrtf(dl*dl + dn*dn + 1e-8f);
        float dtv = fabsf(ts_i - tsj) * (1.f/300.f);
        float ssv = (src_i == srcj) ? 1.f : 0.f;
        float diag = (j == i) ? 1.f : 0.f;
        vldj = (mask[b*Lc + j] > 0.f) ? 1.f : 0.f;
        vi   = (mask[b*Lc + i] > 0.f) ? 1.f : 0.f;
        __syncthreads();   // we1s/be1s ready

        // T build: thread owns row j, quarter q -> 32 k values (16 bf16x2 pairs)
        int q = tid >> 7;
        char* Th = dsmc + (size_t)j*272;
        #pragma unroll
        for(int kk = 0; kk < 16; kk++){
            int k = q*32 + kk*2;
            float v0 = fmaxf(dist*we1s[k]   + dtv*we1s[Hc+k]   + ssv*we1s[2*Hc+k]   + diag*we1s[3*Hc+k]   + be1s[k],   0.f);
            float v1 = fmaxf(dist*we1s[k+1] + dtv*we1s[Hc+k+1] + ssv*we1s[2*Hc+k+1] + diag*we1s[3*Hc+k+1] + be1s[k+1], 0.f);
            *(uint32_t*)(Th + k*2) = packbf2(v0, v1);
        }
    }
    asm volatile("cp.async.wait_group 0;" ::: "memory");
    __syncthreads();   // T + W ready

    // warp tile (both phases): jt = (wid&7)*16 rows, ch = (wid>>3)*64 cols
    int wl8 = wid & 7;
    int ch = (wid >> 3) * 64;
    int jt = wl8 * 16;
    uint32_t base = smem_u32(dsmc);
    uint32_t aT  = base + (uint32_t)((jt + (lane & 15))*272 + ((lane >> 4) << 4));
    uint32_t wBa = base + (uint32_t)(TILE_BYTES   + (lane & 15)*272 + ch*2 + ((lane >> 4) << 4));
    uint32_t wBm = wBa + (uint32_t)TILE_BYTES;
    int gq = lane >> 2, tq = lane & 3;
    int jA = jt + gq, jB = jA + 8;

    float acc[32];

    // ================ PHASE A: attention GEMM (T @ Wa) ================
    #pragma unroll
    for(int q = 0; q < 32; q++) acc[q] = 0.f;
    #pragma unroll
    for(int ks = 0; ks < 8; ks++){
        uint32_t a0,a1,a2,a3;
        ldsm4(a0,a1,a2,a3, aT + ks*32);
        uint32_t wrow = wBa + ks*4352;
        #pragma unroll
        for(int nt = 0; nt < 4; nt++){
            uint32_t B0,B1,B2,B3;
            ldsm4t(B0,B1,B2,B3, wrow + nt*32);
            mma16816(acc + nt*8,     a0,a1,a2,a3, B0,B1);
            mma16816(acc + nt*8 + 4, a0,a1,a2,a3, B2,B3);
        }
    }
    // attention epilogue: rows jA/jB, cols ch + nt*16 + sub*8 + 2tq
    {
        const float* daA = g_da + ((size_t)(b*Lc + jA))*Hc;
        const float* daB = daA + 8*Hc;
        float sA = 0.f, sB = 0.f;
        #pragma unroll
        for(int nt = 0; nt < 4; nt++){
            #pragma unroll
            for(int sub = 0; sub < 2; sub++){
                int c0 = ch + nt*16 + sub*8 + tq*2;
                const float* d = acc + nt*8 + sub*4;
                float2 dA = *(const float2*)(daA + c0);
                float2 dB = *(const float2*)(daB + c0);
                sA += wa2s[c0]  *tanh_fast(sab[c0]  + dA.x + d[0]);
                sA += wa2s[c0+1]*tanh_fast(sab[c0+1]+ dA.y + d[1]);
                sB += wa2s[c0]  *tanh_fast(sab[c0]  + dB.x + d[2]);
                sB += wa2s[c0+1]*tanh_fast(sab[c0+1]+ dB.y + d[3]);
            }
        }
        sA += __shfl_xor_sync(0xffffffffu, sA, 1);
        sA += __shfl_xor_sync(0xffffffffu, sA, 2);
        sB += __shfl_xor_sync(0xffffffffu, sB, 1);
        sB += __shfl_xor_sync(0xffffffffu, sB, 2);
        if(tq == 0){ attp[ch >> 6][jA] = sA; attp[ch >> 6][jB] = sB; }
    }
    __syncthreads();

    // ================ softmax over j (first 128 threads) ================
    const float inv = 0.088388347648318440550f;   // 1/sqrt(128)
    float sc = -1e9f, e = 0.f;
    if(tid < 128){
        float a = (attp[0][tid] + attp[1][tid] + ba2[l]) * inv;
        bool ok = (vldj > 0.f) && (vi > 0.f);
        sc = ok ? a : -1e9f;
        float m = sc;
        #pragma unroll
        for(int s2 = 16; s2 > 0; s2 >>= 1) m = fmaxf(m, __shfl_xor_sync(0xffffffffu, m, s2));
        if((tid & 31) == 0) red[tid >> 5] = m;
    }
    __syncthreads();
    float bmax = fmaxf(fmaxf(red[0], red[1]), fmaxf(red[2], red[3]));
    if(tid < 128){
        e = expf(sc - bmax);
        float s2 = e;
        #pragma unroll
        for(int m = 16; m > 0; m >>= 1) s2 += __shfl_xor_sync(0xffffffffu, s2, m);
        if((tid & 31) == 0) red[4 + (tid >> 5)] = s2;
    }
    __syncthreads();
    if(tid < 128){
        float tot = red[4]+red[5]+red[6]+red[7];
        wsoft[tid] = e / tot;
    }
    __syncthreads();

    // ================ PHASE B: message GEMM (T @ Wm) ================
    #pragma unroll
    for(int q = 0; q < 32; q++) acc[q] = 0.f;
    #pragma unroll
    for(int ks = 0; ks < 8; ks++){
        uint32_t a0,a1,a2,a3;
        ldsm4(a0,a1,a2,a3, aT + ks*32);
        uint32_t wrow = wBm + ks*4352;
        #pragma unroll
        for(int nt = 0; nt < 4; nt++){
            uint32_t B0,B1,B2,B3;
            ldsm4t(B0,B1,B2,B3, wrow + nt*32);
            mma16816(acc + nt*8,     a0,a1,a2,a3, B0,B1);
            mma16816(acc + nt*8 + 4, a0,a1,a2,a3, B2,B3);
        }
    }
    __syncthreads();   // all T reads done before su overwrites T region

    // message epilogue: weighted relu, direct store into su[64][130]
    float* su = (float*)dsmc;
    {
        float wA = wsoft[jA], wB2 = wsoft[jB];
        int p = wl8*8 + gq;
        #pragma unroll
        for(int nt = 0; nt < 4; nt++){
            #pragma unroll
            for(int sub = 0; sub < 2; sub++){
                int c0 = ch + nt*16 + sub*8 + tq*2;
                const float* d = acc + nt*8 + sub*4;
                float v0 = wA*fmaxf(smb[c0]  + d[0], 0.f) + wB2*fmaxf(smb[c0]  + d[2], 0.f);
                float v1 = wA*fmaxf(smb[c0+1]+ d[1], 0.f) + wB2*fmaxf(smb[c0+1]+ d[3], 0.f);
                *(float2*)(su + p*130 + c0) = make_float2(v0, v1);
            }
        }
    }
    __syncthreads();
    {
        int qq = tid >> 7, c = tid & 127;
        float s = 0.f;
        #pragma unroll
        for(int r = 0; r < 16; r++) s += su[(qq*16 + r)*130 + c];
        redp[qq][c] = s;
    }
    __syncthreads();
    if(tid < 128){
        g_aggpre[(size_t)bi*Hc + tid] = redp[0][tid] + redp[1][tid] + redp[2][tid] + redp[3][tid];
    }
}

// ---------------- epilogue per 16 rows ----------------
__global__ __launch_bounds__(256)
void k_post2(int l, int has_next, const float* __restrict__ mask,
             const float* __restrict__ Wm2, const float* __restrict__ bm2,
             const float* __restrict__ Wo1, const float* __restrict__ bo1,
             const float* __restrict__ Wo2, const float* __restrict__ bo2,
             const float* __restrict__ lng, const float* __restrict__ lnb,
             const float* __restrict__ Wa1, const float* __restrict__ Wm1){
    int row0 = blockIdx.x * 16;
    int tid = threadIdx.x;
    int c = tid & 127, ty = tid >> 7;
    __shared__ float hs[16*Hc], as_[16*Hc], ag[16*Hc], op1[16*Hc];
    __shared__ float mu[16], rsd[16], vmsh[16];

    #pragma unroll
    for(int q = 0; q < 8; q++){
        int idx = q*256 + tid;
        hs[idx]  = g_h[(size_t)row0*Hc + idx];
        as_[idx] = g_aggpre[(size_t)row0*Hc + idx];
    }
    if(tid < 16) vmsh[tid] = mask[row0 + tid] > 0.f ? 1.f : 0.f;
    __syncthreads();

    float acc[8];
    const float* wm2 = Wm2 + l*Hc*Hc;
    #pragma unroll
    for(int p = 0; p < 8; p++) acc[p] = bm2[l*Hc + c];
    #pragma unroll 4
    for(int k = 0; k < Hc; k++){
        float w = wm2[k*Hc + c];
        #pragma unroll
        for(int p = 0; p < 8; p++) acc[p] += as_[(ty*8+p)*Hc + k] * w;
    }
    #pragma unroll
    for(int p = 0; p < 8; p++) ag[(ty*8+p)*Hc + c] = acc[p];
    __syncthreads();

    const float* wo1h = Wo1 + l*2*Hc*Hc;
    const float* wo1a = wo1h + Hc*Hc;
    #pragma unroll
    for(int p = 0; p < 8; p++) acc[p] = bo1[l*Hc + c];
    #pragma unroll 4
    for(int k = 0; k < Hc; k++){
        float w1 = wo1h[k*Hc + c], w2 = wo1a[k*Hc + c];
        #pragma unroll
        for(int p = 0; p < 8; p++)
            acc[p] += hs[(ty*8+p)*Hc + k]*w1 + ag[(ty*8+p)*Hc + k]*w2;
    }
    #pragma unroll
    for(int p = 0; p < 8; p++) op1[(ty*8+p)*Hc + c] = fmaxf(acc[p], 0.f);
    __syncthreads();

    const float* wo2 = Wo2 + l*Hc*Hc;
    #pragma unroll
    for(int p = 0; p < 8; p++) acc[p] = bo2[l*Hc + c];
    #pragma unroll 4
    for(int k = 0; k < Hc; k++){
        float w = wo2[k*Hc + c];
        #pragma unroll
        for(int p = 0; p < 8; p++) acc[p] += op1[(ty*8+p)*Hc + k] * w;
    }
    #pragma unroll
    for(int p = 0; p < 8; p++){
        int r = ty*8 + p;
        ag[r*Hc + c] = hs[r*Hc + c] + acc[p];
    }
    __syncthreads();

    {
        int row = tid >> 4, l16 = tid & 15;
        float s = 0.f, s2 = 0.f;
        #pragma unroll
        for(int q = 0; q < 8; q++){
            float v = ag[row*Hc + l16 + q*16];
            s += v; s2 += v*v;
        }
        #pragma unroll
        for(int m = 8; m > 0; m >>= 1){
            s  += __shfl_xor_sync(0xffffffffu, s, m);
            s2 += __shfl_xor_sync(0xffffffffu, s2, m);
        }
        if(l16 == 0){
            float m_ = s * (1.f/128.f);
            mu[row] = m_;
            rsd[row] = rsqrtf(s2 * (1.f/128.f) - m_*m_ + 1e-5f);
        }
    }
    __syncthreads();
    const float* lg = lng + l*Hc;
    const float* lb = lnb + l*Hc;
    #pragma unroll
    for(int p = 0; p < 8; p++){
        int r = ty*8 + p;
        float x = ag[r*Hc + c];
        float hn = ((x - mu[r]) * rsd[r] * lg[c] + lb[c]) * vmsh[r];
        g_h[(size_t)(row0+r)*Hc + c] = hn;
        hs[r*Hc + c] = hn;
    }

    if(has_next){
        __syncthreads();
        int ln = l + 1;
        const float* was = Wa1 + ln*3*Hc*Hc;
        const float* wad = was + Hc*Hc;
        const float* wms = Wm1 + ln*2*Hc*Hc;
        float aa[8], dd[8], mm[8];
        #pragma unroll
        for(int p = 0; p < 8; p++){ aa[p]=0.f; dd[p]=0.f; mm[p]=0.f; }
        #pragma unroll 4
        for(int k = 0; k < Hc; k++){
            float w1 = was[k*Hc + c], w2 = wad[k*Hc + c], w3 = wms[k*Hc + c];
            #pragma unroll
            for(int p = 0; p < 8; p++){
                float h = hs[(ty*8+p)*Hc + k];
                aa[p] += h*w1; dd[p] += h*w2; mm[p] += h*w3;
            }
        }
        #pragma unroll
        for(int p = 0; p < 8; p++){
            size_t r = (size_t)(row0 + ty*8 + p)*Hc + c;
            g_sa[r] = aa[p]; g_da[r] = dd[p]; g_sm[r] = mm[p];
        }
    }
}

// ---------------- decoder ----------------
__global__ void k_dec(const float* __restrict__ hist, const float* __restrict__ mask,
                      const float* __restrict__ hg, const float* __restrict__ hb,
                      const float* __restrict__ Wh1, const float* __restrict__ bh1,
                      const float* __restrict__ Wh2, const float* __restrict__ bh2,
                      float* __restrict__ out){
    int b = blockIdx.x; int t = threadIdx.x;
    __shared__ float x[136], xn[136], hid[Hc];
    __shared__ float red2[4];
    float mv = mask[b*Lc + t];
    float s = mv;
    #pragma unroll
    for(int sft = 16; sft > 0; sft >>= 1) s += __shfl_xor_sync(0xffffffffu, s, sft);
    if((t & 31) == 0) red2[t >> 5] = s;
    __syncthreads();
    float tot = red2[0]+red2[1]+red2[2]+red2[3];
    int vc = (int)tot;
    vc = min(max(vc, 1), Lc);
    int last = vc - 1;

    if(t < Dc) x[t] = hist[((size_t)b*Lc + last)*Dc + t];
    x[Dc + t] = g_h[((size_t)b*Lc + last)*Hc + t];
    __syncthreads();
    float s1 = x[t] + ((t < 8) ? x[128 + t] : 0.f);
    #pragma unroll
    for(int sft = 16; sft > 0; sft >>= 1) s1 += __shfl_xor_sync(0xffffffffu, s1, sft);
    __syncthreads();
    if((t & 31) == 0) red2[t >> 5] = s1;
    __syncthreads();
    float mu = (red2[0]+red2[1]+red2[2]+red2[3]) * (1.f/136.f);
    float d0 = x[t] - mu;
    float s2 = d0*d0;
    if(t < 8){ float d1 = x[128 + t] - mu; s2 += d1*d1; }
    #pragma unroll
    for(int sft = 16; sft > 0; sft >>= 1) s2 += __shfl_xor_sync(0xffffffffu, s2, sft);
    __syncthreads();
    if((t & 31) == 0) red2[t >> 5] = s2;
    __syncthreads();
    float rs = rsqrtf((red2[0]+red2[1]+red2[2]+red2[3]) * (1.f/136.f) + 1e-5f);
    xn[t] = (x[t] - mu) * rs * hg[t] + hb[t];
    if(t < 8) xn[128 + t] = (x[128 + t] - mu) * rs * hg[128 + t] + hb[128 + t];
    __syncthreads();
    float h_ = bh1[t];
    for(int k = 0; k < 136; k++) h_ += xn[k]*Wh1[k*Hc + t];
    hid[t] = fmaxf(h_, 0.f);
    __syncthreads();
    if(t < 24){
        float p = bh2[t];
        for(int k = 0; k < Hc; k++) p += hid[k]*Wh2[k*24 + t];
        if(isnan(p)) p = 0.f;
        else if(isinf(p)) p = (p > 0.f) ? 1e4f : -1e4f;
        out[b*24 + t] = p;
    }
}

__global__ void k_copyh(float* __restrict__ out){
    int i = blockIdx.x*blockDim.x + threadIdx.x;
    out[384 + i] = g_h[i];
}

// ---------------- launch ----------------
extern "C" void kernel_launch(void* const* d_in, const int* in_sizes, int n_in,
                              void* d_out, int out_size){
    const float* hist = (const float*)d_in[0];
    const float* mask = (const float*)d_in[1];
    const float* Wp   = (const float*)d_in[2];
    const float* bp   = (const float*)d_in[3];
    const float* We1  = (const float*)d_in[4];
    const float* be1  = (const float*)d_in[5];
    const float* We2  = (const float*)d_in[6];
    const float* be2  = (const float*)d_in[7];
    const float* Wa1  = (const float*)d_in[8];
    const float* ba1  = (const float*)d_in[9];
    const float* wa2  = (const float*)d_in[10];
    const float* ba2  = (const float*)d_in[11];
    const float* Wm1  = (const float*)d_in[12];
    const float* bm1  = (const float*)d_in[13];
    const float* Wm2  = (const float*)d_in[14];
    const float* bm2  = (const float*)d_in[15];
    const float* Wo1  = (const float*)d_in[16];
    const float* bo1  = (const float*)d_in[17];
    const float* Wo2  = (const float*)d_in[18];
    const float* bo2  = (const float*)d_in[19];
    const float* lng  = (const float*)d_in[20];
    const float* lnb  = (const float*)d_in[21];
    const float* hg   = (const float*)d_in[22];
    const float* hbv  = (const float*)d_in[23];
    const float* Wh1  = (const float*)d_in[24];
    const float* bh1  = (const float*)d_in[25];
    const float* Wh2  = (const float*)d_in[26];
    const float* bh2  = (const float*)d_in[27];
    float* out = (float*)d_out;

    cudaFuncSetAttribute(k_main10, cudaFuncAttributeMaxDynamicSharedMemorySize, 3*TILE_BYTES);

    k_ts<<<1, 32>>>(hist);
    k_prepwb<<<NLc*129, Hc>>>(We2, be2, Wa1, Wm1, ba1, bm1);
    k_h0s<<<Bc*Lc/16, 256>>>(hist, mask, Wp, bp, Wa1, Wm1);
    for(int l = 0; l < NLc; l++){
        k_main10<<<Bc*Lc, 512, 3*TILE_BYTES>>>(l, hist, mask, We1, be1, wa2, ba2);
        k_post2<<<Bc*Lc/16, 256>>>(l, (l+1 < NLc) ? 1 : 0, mask,
                                   Wm2, bm2, Wo1, bo1, Wo2, bo2, lng, lnb, Wa1, Wm1);
    }
    k_dec<<<Bc, Hc>>>(hist, mask, hg, hbv, Wh1, bh1, Wh2, bh2, out);
    if(out_size >= 384 + Bc*Lc*Hc){
        k_copyh<<<(Bc*Lc*Hc)/256, 256>>>(out);
    }
}

// round 12
// speedup vs baseline: 3.4621x; 1.0636x over previous
#include <cuda_runtime.h>
#include <cuda_bf16.h>
#include <math.h>
#include <stdint.h>

#define Bc 16
#define Lc 128
#define Dc 8
#define Hc 128
#define NLc 2

// bf16 tile geometry: [128 rows][136 cols] bf16, pitch 272B
#define WPITCH 136
#define TILE_ELEMS (128*WPITCH)          // 17408
#define TILE_BYTES (TILE_ELEMS*2)        // 34816

// ---------------- scratch (static device globals; no allocation) ----------------
__device__ __align__(16) float g_ts[Bc*Lc];
__device__ __align__(16) float g_h[Bc*Lc*Hc];
__device__ __align__(16) float g_sa[Bc*Lc*Hc];
__device__ __align__(16) float g_da[Bc*Lc*Hc];
__device__ __align__(16) float g_sm[Bc*Lc*Hc];
__device__ __align__(16) float g_aggpre[Bc*Lc*Hc];
__device__ __align__(16) float g_ba[NLc*Hc];
__device__ __align__(16) float g_bm[NLc*Hc];
// folded weights as bf16, [k][c] rows padded to 136: per layer Wa | Wm
__device__ __align__(16) __nv_bfloat16 g_Wbf[NLc*2*TILE_ELEMS];

// ---------------- helpers ----------------
__device__ __forceinline__ uint32_t smem_u32(const void* p){
    uint32_t a;
    asm("{ .reg .u64 t; cvta.to.shared.u64 t, %1; cvt.u32.u64 %0, t; }" : "=r"(a) : "l"(p));
    return a;
}
__device__ __forceinline__ void cp16(void* dst_smem, const void* src){
    unsigned sdst = (unsigned)__cvta_generic_to_shared(dst_smem);
    asm volatile("cp.async.cg.shared.global [%0], [%1], 16;" :: "r"(sdst), "l"(src));
}
__device__ __forceinline__ float tanh_fast(float x){
    float r; asm("tanh.approx.f32 %0, %1;" : "=f"(r) : "f"(x)); return r;
}
__device__ __forceinline__ void ldsm4(uint32_t &r0,uint32_t &r1,uint32_t &r2,uint32_t &r3,uint32_t a){
    asm volatile("ldmatrix.sync.aligned.m8n8.x4.shared.b16 {%0,%1,%2,%3},[%4];"
        : "=r"(r0),"=r"(r1),"=r"(r2),"=r"(r3) : "r"(a));
}
__device__ __forceinline__ void ldsm4t(uint32_t &r0,uint32_t &r1,uint32_t &r2,uint32_t &r3,uint32_t a){
    asm volatile("ldmatrix.sync.aligned.m8n8.x4.trans.shared.b16 {%0,%1,%2,%3},[%4];"
        : "=r"(r0),"=r"(r1),"=r"(r2),"=r"(r3) : "r"(a));
}
__device__ __forceinline__ void mma16816(float* d, uint32_t a0,uint32_t a1,uint32_t a2,uint32_t a3,
                                         uint32_t b0,uint32_t b1){
    asm volatile("mma.sync.aligned.m16n8k16.row.col.f32.bf16.bf16.f32 "
        "{%0,%1,%2,%3},{%4,%5,%6,%7},{%8,%9},{%0,%1,%2,%3};"
        : "+f"(d[0]),"+f"(d[1]),"+f"(d[2]),"+f"(d[3])
        : "r"(a0),"r"(a1),"r"(a2),"r"(a3),"r"(b0),"r"(b1));
}
// pack two floats to bf16x2 (v0 -> low half, v1 -> high)
__device__ __forceinline__ uint32_t packbf2(float v0, float v1){
    uint32_t r; asm("cvt.rn.bf16x2.f32 %0, %1, %2;" : "=r"(r) : "f"(v1), "f"(v0)); return r;
}

// ---------------- cumsum of ts ----------------
__global__ void k_ts(const float* __restrict__ hist){
    int b = threadIdx.x;
    if(b < Bc){
        float c = 0.f;
        for(int t = 0; t < Lc; t++){
            float v = hist[(b*Lc+t)*Dc + 5];
            c += fmaxf(v, 0.f);
            g_ts[b*Lc+t] = c;
        }
    }
}

// ---------------- folded weights -> bf16 padded tiles ----------------
__global__ void k_prepwb(const float* __restrict__ We2, const float* __restrict__ be2,
                         const float* __restrict__ Wa1, const float* __restrict__ Wm1,
                         const float* __restrict__ ba1, const float* __restrict__ bm1){
    int l = blockIdx.x / 129, kk = blockIdx.x % 129;
    int c = threadIdx.x;
    __shared__ float ws[Hc];
    if(kk < Hc) ws[c] = We2[l*Hc*Hc + kk*Hc + c];
    else        ws[c] = be2[l*Hc + c];
    __syncthreads();
    const float* wa = Wa1 + l*3*Hc*Hc + 2*Hc*Hc;
    const float* wm = Wm1 + l*2*Hc*Hc + Hc*Hc;
    float sa = 0.f, sm = 0.f;
    #pragma unroll 4
    for(int r = 0; r < Hc; r++){ float w = ws[r]; sa += w*wa[r*Hc + c]; sm += w*wm[r*Hc + c]; }
    if(kk < Hc){
        __nv_bfloat16* base = g_Wbf + (size_t)l*2*TILE_ELEMS;
        base[             kk*WPITCH + c] = __float2bfloat16(sa);
        base[TILE_ELEMS + kk*WPITCH + c] = __float2bfloat16(sm);
    } else {
        g_ba[l*Hc + c] = sa + ba1[l*Hc + c];
        g_bm[l*Hc + c] = sm + bm1[l*Hc + c];
    }
}

// ---------------- h0 (16 rows per block) + sa/da/sm for layer 0 ----------------
__global__ __launch_bounds__(256)
void k_h0s(const float* __restrict__ hist, const float* __restrict__ mask,
           const float* __restrict__ Wp, const float* __restrict__ bp,
           const float* __restrict__ Wa1, const float* __restrict__ Wm1){
    int row0 = blockIdx.x * 16;
    int tid = threadIdx.x;
    int c = tid & 127, ty = tid >> 7;
    __shared__ float xs[16*Dc], hs[16*Hc], vmsh[16];
    if(tid < 128) xs[tid] = hist[(size_t)row0*Dc + tid];
    if(tid < 16)  vmsh[tid] = mask[row0 + tid] > 0.f ? 1.f : 0.f;
    __syncthreads();
    float acc[8];
    #pragma unroll
    for(int p = 0; p < 8; p++) acc[p] = bp[c];
    #pragma unroll
    for(int d = 0; d < Dc; d++){
        float w = Wp[d*Hc + c];
        #pragma unroll
        for(int p = 0; p < 8; p++) acc[p] += xs[(ty*8+p)*Dc + d] * w;
    }
    #pragma unroll
    for(int p = 0; p < 8; p++){
        int r = ty*8 + p;
        float h = acc[p] * vmsh[r];
        hs[r*Hc + c] = h;
        g_h[(size_t)(row0+r)*Hc + c] = h;
    }
    __syncthreads();
    const float* was = Wa1;
    const float* wad = was + Hc*Hc;
    const float* wms = Wm1;
    float aa[8], dd[8], mm[8];
    #pragma unroll
    for(int p = 0; p < 8; p++){ aa[p]=0.f; dd[p]=0.f; mm[p]=0.f; }
    #pragma unroll 4
    for(int k = 0; k < Hc; k++){
        float w1 = was[k*Hc + c], w2 = wad[k*Hc + c], w3 = wms[k*Hc + c];
        #pragma unroll
        for(int p = 0; p < 8; p++){
            float h = hs[(ty*8+p)*Hc + k];
            aa[p] += h*w1; dd[p] += h*w2; mm[p] += h*w3;
        }
    }
    #pragma unroll
    for(int p = 0; p < 8; p++){
        size_t r = (size_t)(row0 + ty*8 + p)*Hc + c;
        g_sa[r] = aa[p]; g_da[r] = dd[p]; g_sm[r] = mm[p];
    }
}

// ---------------- main fused kernel: two HMMA phases, 32x32 warp tiles, 2 CTAs/SM ----------------
// dynamic SMEM bytes:
//   [0      , 34816 ) T     [j][136] bf16
//   [34816  , 69632 ) Wa    [k][136] bf16
//   [69632  ,104448 ) Wm
// after msg GEMM, T region reused as f32 msg partial buffer su[32][130]
extern __shared__ char dsmc[];

__global__ __launch_bounds__(512, 2)
void k_main11(int l, const float* __restrict__ hist, const float* __restrict__ mask,
              const float* __restrict__ We1, const float* __restrict__ be1,
              const float* __restrict__ wa2, const float* __restrict__ ba2){
    __shared__ float we1s[4*Hc], be1s[Hc], sab[Hc], smb[Hc], wa2s[Hc];
    __shared__ float attp[4][Lc], wsoft[Lc], red[8], redp[4][Hc];

    int bi = blockIdx.x;
    int b = bi >> 7, i = bi & 127;
    int tid = threadIdx.x;
    int wid = tid >> 5, lane = tid & 31;
    int j = tid & 127;

    // async copy both weight tiles (69632 B = 4352 x 16B)
    {
        const char* wsrc = (const char*)(g_Wbf + (size_t)l*2*TILE_ELEMS);
        char* wdst = dsmc + TILE_BYTES;
        #pragma unroll
        for(int q = 0; q < 8; q++){
            int off = (q*512 + tid)*16;
            cp16(wdst + off, wsrc + off);
        }
        if(tid < 256) cp16(wdst + (4096 + tid)*16, wsrc + (4096 + tid)*16);
        asm volatile("cp.async.commit_group;" ::: "memory");
    }

    if(tid < 128){
        #pragma unroll
        for(int q = 0; q < 4; q++) we1s[q*Hc + tid] = We1[l*4*Hc + q*Hc + tid];
        be1s[tid] = be1[l*Hc + tid];
        sab[tid]  = g_sa[(size_t)bi*Hc + tid] + g_ba[l*Hc + tid];
        smb[tid]  = g_sm[(size_t)bi*Hc + tid] + g_bm[l*Hc + tid];
        wa2s[tid] = wa2[l*Hc + tid];
    }

    // edge features for this thread's j
    const float* hb_ = hist + (size_t)b*Lc*Dc;
    float vldj, vi;
    {
        float lat_i = hb_[i*Dc + 0], lon_i = hb_[i*Dc + 1], src_i = hb_[i*Dc + 6];
        float ts_i = g_ts[b*Lc + i];
        float latj = hb_[j*Dc + 0], lonj = hb_[j*Dc + 1], srcj = hb_[j*Dc + 6];
        float tsj = g_ts[b*Lc + j];
        float dl = lat_i - latj, dn = lon_i - lonj;
        float dist = sqrtf(dl*dl + dn*dn + 1e-8f);
        float dtv = fabsf(ts_i - tsj) * (1.f/300.f);
        float ssv = (src_i == srcj) ? 1.f : 0.f;
        float diag = (j == i) ? 1.f : 0.f;
        vldj = (mask[b*Lc + j] > 0.f) ? 1.f : 0.f;
        vi   = (mask[b*Lc + i] > 0.f) ? 1.f : 0.f;
        __syncthreads();   // we1s/be1s ready

        // T build: thread owns row j, quarter q -> 32 k values (16 bf16x2 pairs)
        int q = tid >> 7;
        char* Th = dsmc + (size_t)j*272;
        #pragma unroll
        for(int kk = 0; kk < 16; kk++){
            int k = q*32 + kk*2;
            float v0 = fmaxf(dist*we1s[k]   + dtv*we1s[Hc+k]   + ssv*we1s[2*Hc+k]   + diag*we1s[3*Hc+k]   + be1s[k],   0.f);
            float v1 = fmaxf(dist*we1s[k+1] + dtv*we1s[Hc+k+1] + ssv*we1s[2*Hc+k+1] + diag*we1s[3*Hc+k+1] + be1s[k+1], 0.f);
            *(uint32_t*)(Th + k*2) = packbf2(v0, v1);
        }
    }
    asm volatile("cp.async.wait_group 0;" ::: "memory");
    __syncthreads();   // T + W ready

    // warp tile: jb = wid&3 -> jt = jb*32 rows; cb = wid>>2 -> ch = cb*32 cols
    int jb = wid & 3, cb = wid >> 2;
    int jt = jb*32, ch = cb*32;
    uint32_t base = smem_u32(dsmc);
    uint32_t aT0 = base + (uint32_t)((jt + (lane & 15))*272 + ((lane >> 4) << 4));
    uint32_t aT1 = aT0 + 16*272;
    uint32_t wBa = base + (uint32_t)(TILE_BYTES   + (lane & 15)*272 + ch*2 + ((lane >> 4) << 4));
    uint32_t wBm = wBa + (uint32_t)TILE_BYTES;
    int gq = lane >> 2, tq = lane & 3;

    // acc layout: [t16][nq][4] -> t16*16 + nq*4 ; cols = ch + nq*8 + 2tq
    float acc[32];

    // ================ PHASE A: attention GEMM (T @ Wa) ================
    #pragma unroll
    for(int q = 0; q < 32; q++) acc[q] = 0.f;
    #pragma unroll
    for(int ks = 0; ks < 8; ks++){
        uint32_t a0,a1,a2,a3, c0,c1,c2,c3;
        ldsm4(a0,a1,a2,a3, aT0 + ks*32);
        ldsm4(c0,c1,c2,c3, aT1 + ks*32);
        uint32_t wrow = wBa + ks*4352;
        uint32_t B0,B1,B2,B3, B4,B5,B6,B7;
        ldsm4t(B0,B1,B2,B3, wrow);
        ldsm4t(B4,B5,B6,B7, wrow + 32);
        mma16816(acc+0,  a0,a1,a2,a3, B0,B1);
        mma16816(acc+4,  a0,a1,a2,a3, B2,B3);
        mma16816(acc+8,  a0,a1,a2,a3, B4,B5);
        mma16816(acc+12, a0,a1,a2,a3, B6,B7);
        mma16816(acc+16, c0,c1,c2,c3, B0,B1);
        mma16816(acc+20, c0,c1,c2,c3, B2,B3);
        mma16816(acc+24, c0,c1,c2,c3, B4,B5);
        mma16816(acc+28, c0,c1,c2,c3, B6,B7);
    }
    // attention epilogue: rows jt + t16*16 + gq (+8), cols ch + nq*8 + 2tq
    #pragma unroll
    for(int t16 = 0; t16 < 2; t16++){
        int jA = jt + t16*16 + gq, jB = jA + 8;
        const float* daA = g_da + ((size_t)(b*Lc + jA))*Hc;
        const float* daB = daA + 8*Hc;
        float sA = 0.f, sB = 0.f;
        #pragma unroll
        for(int nq = 0; nq < 4; nq++){
            int c0 = ch + nq*8 + tq*2;
            const float* d = acc + t16*16 + nq*4;
            float2 dA = *(const float2*)(daA + c0);
            float2 dB = *(const float2*)(daB + c0);
            sA += wa2s[c0]  *tanh_fast(sab[c0]  + dA.x + d[0]);
            sA += wa2s[c0+1]*tanh_fast(sab[c0+1]+ dA.y + d[1]);
            sB += wa2s[c0]  *tanh_fast(sab[c0]  + dB.x + d[2]);
            sB += wa2s[c0+1]*tanh_fast(sab[c0+1]+ dB.y + d[3]);
        }
        sA += __shfl_xor_sync(0xffffffffu, sA, 1);
        sA += __shfl_xor_sync(0xffffffffu, sA, 2);
        sB += __shfl_xor_sync(0xffffffffu, sB, 1);
        sB += __shfl_xor_sync(0xffffffffu, sB, 2);
        if(tq == 0){ attp[cb][jA] = sA; attp[cb][jB] = sB; }
    }

    // ================ PHASE B: message GEMM (T @ Wm) — independent of softmax ================
    #pragma unroll
    for(int q = 0; q < 32; q++) acc[q] = 0.f;
    #pragma unroll
    for(int ks = 0; ks < 8; ks++){
        uint32_t a0,a1,a2,a3, c0,c1,c2,c3;
        ldsm4(a0,a1,a2,a3, aT0 + ks*32);
        ldsm4(c0,c1,c2,c3, aT1 + ks*32);
        uint32_t wrow = wBm + ks*4352;
        uint32_t B0,B1,B2,B3, B4,B5,B6,B7;
        ldsm4t(B0,B1,B2,B3, wrow);
        ldsm4t(B4,B5,B6,B7, wrow + 32);
        mma16816(acc+0,  a0,a1,a2,a3, B0,B1);
        mma16816(acc+4,  a0,a1,a2,a3, B2,B3);
        mma16816(acc+8,  a0,a1,a2,a3, B4,B5);
        mma16816(acc+12, a0,a1,a2,a3, B6,B7);
        mma16816(acc+16, c0,c1,c2,c3, B0,B1);
        mma16816(acc+20, c0,c1,c2,c3, B2,B3);
        mma16816(acc+24, c0,c1,c2,c3, B4,B5);
        mma16816(acc+28, c0,c1,c2,c3, B6,B7);
    }
    __syncthreads();   // attp visible; all T reads done (su can overwrite T later)

    // ================ softmax over j (first 128 threads) ================
    const float inv = 0.088388347648318440550f;   // 1/sqrt(128)
    float sc = -1e9f, e = 0.f;
    if(tid < 128){
        float a = (attp[0][tid] + attp[1][tid] + attp[2][tid] + attp[3][tid] + ba2[l]) * inv;
        bool ok = (vldj > 0.f) && (vi > 0.f);
        sc = ok ? a : -1e9f;
        float m = sc;
        #pragma unroll
        for(int s2 = 16; s2 > 0; s2 >>= 1) m = fmaxf(m, __shfl_xor_sync(0xffffffffu, m, s2));
        if((tid & 31) == 0) red[tid >> 5] = m;
    }
    __syncthreads();
    float bmax = fmaxf(fmaxf(red[0], red[1]), fmaxf(red[2], red[3]));
    if(tid < 128){
        e = expf(sc - bmax);
        float s2 = e;
        #pragma unroll
        for(int m = 16; m > 0; m >>= 1) s2 += __shfl_xor_sync(0xffffffffu, s2, m);
        if((tid & 31) == 0) red[4 + (tid >> 5)] = s2;
    }
    __syncthreads();
    if(tid < 128){
        float tot = red[4]+red[5]+red[6]+red[7];
        wsoft[tid] = e / tot;
    }
    __syncthreads();

    // ================ message epilogue: weighted relu into su[32][130] ================
    float* su = (float*)dsmc;
    {
        float v[8];
        #pragma unroll
        for(int p = 0; p < 8; p++) v[p] = 0.f;
        #pragma unroll
        for(int t16 = 0; t16 < 2; t16++){
            int jA = jt + t16*16 + gq, jB = jA + 8;
            float wA = wsoft[jA], wB2 = wsoft[jB];
            #pragma unroll
            for(int nq = 0; nq < 4; nq++){
                int c0 = ch + nq*8 + tq*2;
                const float* d = acc + t16*16 + nq*4;
                v[nq*2]   += wA*fmaxf(smb[c0]  + d[0], 0.f) + wB2*fmaxf(smb[c0]  + d[2], 0.f);
                v[nq*2+1] += wA*fmaxf(smb[c0+1]+ d[1], 0.f) + wB2*fmaxf(smb[c0+1]+ d[3], 0.f);
            }
        }
        int p = jb*8 + gq;
        #pragma unroll
        for(int nq = 0; nq < 4; nq++){
            int c0 = ch + nq*8 + tq*2;
            *(float2*)(su + p*130 + c0) = make_float2(v[nq*2], v[nq*2+1]);
        }
    }
    __syncthreads();
    {
        int qq = tid >> 7, c = tid & 127;
        float s = 0.f;
        #pragma unroll
        for(int r = 0; r < 8; r++) s += su[(qq*8 + r)*130 + c];
        redp[qq][c] = s;
    }
    __syncthreads();
    if(tid < 128){
        g_aggpre[(size_t)bi*Hc + tid] = redp[0][tid] + redp[1][tid] + redp[2][tid] + redp[3][tid];
    }
}

// ---------------- epilogue per 16 rows ----------------
__global__ __launch_bounds__(256)
void k_post2(int l, int has_next, const float* __restrict__ mask,
             const float* __restrict__ Wm2, const float* __restrict__ bm2,
             const float* __restrict__ Wo1, const float* __restrict__ bo1,
             const float* __restrict__ Wo2, const float* __restrict__ bo2,
             const float* __restrict__ lng, const float* __restrict__ lnb,
             const float* __restrict__ Wa1, const float* __restrict__ Wm1){
    int row0 = blockIdx.x * 16;
    int tid = threadIdx.x;
    int c = tid & 127, ty = tid >> 7;
    __shared__ float hs[16*Hc], as_[16*Hc], ag[16*Hc], op1[16*Hc];
    __shared__ float mu[16], rsd[16], vmsh[16];

    #pragma unroll
    for(int q = 0; q < 8; q++){
        int idx = q*256 + tid;
        hs[idx]  = g_h[(size_t)row0*Hc + idx];
        as_[idx] = g_aggpre[(size_t)row0*Hc + idx];
    }
    if(tid < 16) vmsh[tid] = mask[row0 + tid] > 0.f ? 1.f : 0.f;
    __syncthreads();

    float acc[8];
    const float* wm2 = Wm2 + l*Hc*Hc;
    #pragma unroll
    for(int p = 0; p < 8; p++) acc[p] = bm2[l*Hc + c];
    #pragma unroll 4
    for(int k = 0; k < Hc; k++){
        float w = wm2[k*Hc + c];
        #pragma unroll
        for(int p = 0; p < 8; p++) acc[p] += as_[(ty*8+p)*Hc + k] * w;
    }
    #pragma unroll
    for(int p = 0; p < 8; p++) ag[(ty*8+p)*Hc + c] = acc[p];
    __syncthreads();

    const float* wo1h = Wo1 + l*2*Hc*Hc;
    const float* wo1a = wo1h + Hc*Hc;
    #pragma unroll
    for(int p = 0; p < 8; p++) acc[p] = bo1[l*Hc + c];
    #pragma unroll 4
    for(int k = 0; k < Hc; k++){
        float w1 = wo1h[k*Hc + c], w2 = wo1a[k*Hc + c];
        #pragma unroll
        for(int p = 0; p < 8; p++)
            acc[p] += hs[(ty*8+p)*Hc + k]*w1 + ag[(ty*8+p)*Hc + k]*w2;
    }
    #pragma unroll
    for(int p = 0; p < 8; p++) op1[(ty*8+p)*Hc + c] = fmaxf(acc[p], 0.f);
    __syncthreads();

    const float* wo2 = Wo2 + l*Hc*Hc;
    #pragma unroll
    for(int p = 0; p < 8; p++) acc[p] = bo2[l*Hc + c];
    #pragma unroll 4
    for(int k = 0; k < Hc; k++){
        float w = wo2[k*Hc + c];
        #pragma unroll
        for(int p = 0; p < 8; p++) acc[p] += op1[(ty*8+p)*Hc + k] * w;
    }
    #pragma unroll
    for(int p = 0; p < 8; p++){
        int r = ty*8 + p;
        ag[r*Hc + c] = hs[r*Hc + c] + acc[p];
    }
    __syncthreads();

    {
        int row = tid >> 4, l16 = tid & 15;
        float s = 0.f, s2 = 0.f;
        #pragma unroll
        for(int q = 0; q < 8; q++){
            float v = ag[row*Hc + l16 + q*16];
            s += v; s2 += v*v;
        }
        #pragma unroll
        for(int m = 8; m > 0; m >>= 1){
            s  += __shfl_xor_sync(0xffffffffu, s, m);
            s2 += __shfl_xor_sync(0xffffffffu, s2, m);
        }
        if(l16 == 0){
            float m_ = s * (1.f/128.f);
            mu[row] = m_;
            rsd[row] = rsqrtf(s2 * (1.f/128.f) - m_*m_ + 1e-5f);
        }
    }
    __syncthreads();
    const float* lg = lng + l*Hc;
    const float* lb = lnb + l*Hc;
    #pragma unroll
    for(int p = 0; p < 8; p++){
        int r = ty*8 + p;
        float x = ag[r*Hc + c];
        float hn = ((x - mu[r]) * rsd[r] * lg[c] + lb[c]) * vmsh[r];
        g_h[(size_t)(row0+r)*Hc + c] = hn;
        hs[r*Hc + c] = hn;
    }

    if(has_next){
        __syncthreads();
        int ln = l + 1;
        const float* was = Wa1 + ln*3*Hc*Hc;
        const float* wad = was + Hc*Hc;
        const float* wms = Wm1 + ln*2*Hc*Hc;
        float aa[8], dd[8], mm[8];
        #pragma unroll
        for(int p = 0; p < 8; p++){ aa[p]=0.f; dd[p]=0.f; mm[p]=0.f; }
        #pragma unroll 4
        for(int k = 0; k < Hc; k++){
            float w1 = was[k*Hc + c], w2 = wad[k*Hc + c], w3 = wms[k*Hc + c];
            #pragma unroll
            for(int p = 0; p < 8; p++){
                float h = hs[(ty*8+p)*Hc + k];
                aa[p] += h*w1; dd[p] += h*w2; mm[p] += h*w3;
            }
        }
        #pragma unroll
        for(int p = 0; p < 8; p++){
            size_t r = (size_t)(row0 + ty*8 + p)*Hc + c;
            g_sa[r] = aa[p]; g_da[r] = dd[p]; g_sm[r] = mm[p];
        }
    }
}

// ---------------- decoder ----------------
__global__ void k_dec(const float* __restrict__ hist, const float* __restrict__ mask,
                      const float* __restrict__ hg, const float* __restrict__ hb,
                      const float* __restrict__ Wh1, const float* __restrict__ bh1,
                      const float* __restrict__ Wh2, const float* __restrict__ bh2,
                      float* __restrict__ out){
    int b = blockIdx.x; int t = threadIdx.x;
    __shared__ float x[136], xn[136], hid[Hc];
    __shared__ float red2[4];
    float mv = mask[b*Lc + t];
    float s = mv;
    #pragma unroll
    for(int sft = 16; sft > 0; sft >>= 1) s += __shfl_xor_sync(0xffffffffu, s, sft);
    if((t & 31) == 0) red2[t >> 5] = s;
    __syncthreads();
    float tot = red2[0]+red2[1]+red2[2]+red2[3];
    int vc = (int)tot;
    vc = min(max(vc, 1), Lc);
    int last = vc - 1;

    if(t < Dc) x[t] = hist[((size_t)b*Lc + last)*Dc + t];
    x[Dc + t] = g_h[((size_t)b*Lc + last)*Hc + t];
    __syncthreads();
    float s1 = x[t] + ((t < 8) ? x[128 + t] : 0.f);
    #pragma unroll
    for(int sft = 16; sft > 0; sft >>= 1) s1 += __shfl_xor_sync(0xffffffffu, s1, sft);
    __syncthreads();
    if((t & 31) == 0) red2[t >> 5] = s1;
    __syncthreads();
    float mu = (red2[0]+red2[1]+red2[2]+red2[3]) * (1.f/136.f);
    float d0 = x[t] - mu;
    float s2 = d0*d0;
    if(t < 8){ float d1 = x[128 + t] - mu; s2 += d1*d1; }
    #pragma unroll
    for(int sft = 16; sft > 0; sft >>= 1) s2 += __shfl_xor_sync(0xffffffffu, s2, sft);
    __syncthreads();
    if((t & 31) == 0) red2[t >> 5] = s2;
    __syncthreads();
    float rs = rsqrtf((red2[0]+red2[1]+red2[2]+red2[3]) * (1.f/136.f) + 1e-5f);
    xn[t] = (x[t] - mu) * rs * hg[t] + hb[t];
    if(t < 8) xn[128 + t] = (x[128 + t] - mu) * rs * hg[128 + t] + hb[128 + t];
    __syncthreads();
    float h_ = bh1[t];
    for(int k = 0; k < 136; k++) h_ += xn[k]*Wh1[k*Hc + t];
    hid[t] = fmaxf(h_, 0.f);
    __syncthreads();
    if(t < 24){
        float p = bh2[t];
        for(int k = 0; k < Hc; k++) p += hid[k]*Wh2[k*24 + t];
        if(isnan(p)) p = 0.f;
        else if(isinf(p)) p = (p > 0.f) ? 1e4f : -1e4f;
        out[b*24 + t] = p;
    }
}

__global__ void k_copyh(float* __restrict__ out){
    int i = blockIdx.x*blockDim.x + threadIdx.x;
    out[384 + i] = g_h[i];
}

// ---------------- launch ----------------
extern "C" void kernel_launch(void* const* d_in, const int* in_sizes, int n_in,
                              void* d_out, int out_size){
    const float* hist = (const float*)d_in[0];
    const float* mask = (const float*)d_in[1];
    const float* Wp   = (const float*)d_in[2];
    const float* bp   = (const float*)d_in[3];
    const float* We1  = (const float*)d_in[4];
    const float* be1  = (const float*)d_in[5];
    const float* We2  = (const float*)d_in[6];
    const float* be2  = (const float*)d_in[7];
    const float* Wa1  = (const float*)d_in[8];
    const float* ba1  = (const float*)d_in[9];
    const float* wa2  = (const float*)d_in[10];
    const float* ba2  = (const float*)d_in[11];
    const float* Wm1  = (const float*)d_in[12];
    const float* bm1  = (const float*)d_in[13];
    const float* Wm2  = (const float*)d_in[14];
    const float* bm2  = (const float*)d_in[15];
    const float* Wo1  = (const float*)d_in[16];
    const float* bo1  = (const float*)d_in[17];
    const float* Wo2  = (const float*)d_in[18];
    const float* bo2  = (const float*)d_in[19];
    const float* lng  = (const float*)d_in[20];
    const float* lnb  = (const float*)d_in[21];
    const float* hg   = (const float*)d_in[22];
    const float* hbv  = (const float*)d_in[23];
    const float* Wh1  = (const float*)d_in[24];
    const float* bh1  = (const float*)d_in[25];
    const float* Wh2  = (const float*)d_in[26];
    const float* bh2  = (const float*)d_in[27];
    float* out = (float*)d_out;

    cudaFuncSetAttribute(k_main11, cudaFuncAttributeMaxDynamicSharedMemorySize, 3*TILE_BYTES);

    k_ts<<<1, 32>>>(hist);
    k_prepwb<<<NLc*129, Hc>>>(We2, be2, Wa1, Wm1, ba1, bm1);
    k_h0s<<<Bc*Lc/16, 256>>>(hist, mask, Wp, bp, Wa1, Wm1);
    for(int l = 0; l < NLc; l++){
        k_main11<<<Bc*Lc, 512, 3*TILE_BYTES>>>(l, hist, mask, We1, be1, wa2, ba2);
        k_post2<<<Bc*Lc/16, 256>>>(l, (l+1 < NLc) ? 1 : 0, mask,
                                   Wm2, bm2, Wo1, bo1, Wo2, bo2, lng, lnb, Wa1, Wm1);
    }
    k_dec<<<Bc, Hc>>>(hist, mask, hg, hbv, Wh1, bh1, Wh2, bh2, out);
    if(out_size >= 384 + Bc*Lc*Hc){
        k_copyh<<<(Bc*Lc*Hc)/256, 256>>>(out);
    }
}

// round 13
// speedup vs baseline: 3.4867x; 1.0071x over previous
#include <cuda_runtime.h>
#include <cuda_bf16.h>
#include <math.h>
#include <stdint.h>

#define Bc 16
#define Lc 128
#define Dc 8
#define Hc 128
#define NLc 2

// bf16 tile geometry: [128 rows][136 cols] bf16, pitch 272B
#define WPITCH 136
#define TILE_ELEMS (128*WPITCH)          // 17408
#define TILE_BYTES (TILE_ELEMS*2)        // 34816

// ---------------- scratch (static device globals; no allocation) ----------------
__device__ __align__(16) float g_ts[Bc*Lc];
__device__ __align__(16) float g_h[Bc*Lc*Hc];
__device__ __align__(16) float g_sa[Bc*Lc*Hc];
__device__ __align__(16) float g_da[Bc*Lc*Hc];
__device__ __align__(16) float g_sm[Bc*Lc*Hc];
__device__ __align__(16) float g_aggpre[Bc*Lc*Hc];
__device__ __align__(16) float g_ba[NLc*Hc];
__device__ __align__(16) float g_bm[NLc*Hc];
// folded weights as bf16, [k][c] rows padded to 136: per layer Wa | Wm
__device__ __align__(16) __nv_bfloat16 g_Wbf[NLc*2*TILE_ELEMS];

// ---------------- helpers ----------------
__device__ __forceinline__ uint32_t smem_u32(const void* p){
    uint32_t a;
    asm("{ .reg .u64 t; cvta.to.shared.u64 t, %1; cvt.u32.u64 %0, t; }" : "=r"(a) : "l"(p));
    return a;
}
__device__ __forceinline__ void cp16(void* dst_smem, const void* src){
    unsigned sdst = (unsigned)__cvta_generic_to_shared(dst_smem);
    asm volatile("cp.async.cg.shared.global [%0], [%1], 16;" :: "r"(sdst), "l"(src));
}
__device__ __forceinline__ float tanh_fast(float x){
    float r; asm("tanh.approx.f32 %0, %1;" : "=f"(r) : "f"(x)); return r;
}
__device__ __forceinline__ void ldsm4(uint32_t &r0,uint32_t &r1,uint32_t &r2,uint32_t &r3,uint32_t a){
    asm volatile("ldmatrix.sync.aligned.m8n8.x4.shared.b16 {%0,%1,%2,%3},[%4];"
        : "=r"(r0),"=r"(r1),"=r"(r2),"=r"(r3) : "r"(a));
}
__device__ __forceinline__ void ldsm4t(uint32_t &r0,uint32_t &r1,uint32_t &r2,uint32_t &r3,uint32_t a){
    asm volatile("ldmatrix.sync.aligned.m8n8.x4.trans.shared.b16 {%0,%1,%2,%3},[%4];"
        : "=r"(r0),"=r"(r1),"=r"(r2),"=r"(r3) : "r"(a));
}
__device__ __forceinline__ void mma16816(float* d, uint32_t a0,uint32_t a1,uint32_t a2,uint32_t a3,
                                         uint32_t b0,uint32_t b1){
    asm volatile("mma.sync.aligned.m16n8k16.row.col.f32.bf16.bf16.f32 "
        "{%0,%1,%2,%3},{%4,%5,%6,%7},{%8,%9},{%0,%1,%2,%3};"
        : "+f"(d[0]),"+f"(d[1]),"+f"(d[2]),"+f"(d[3])
        : "r"(a0),"r"(a1),"r"(a2),"r"(a3),"r"(b0),"r"(b1));
}
// pack two floats to bf16x2 (v0 -> low half, v1 -> high)
__device__ __forceinline__ uint32_t packbf2(float v0, float v1){
    uint32_t r; asm("cvt.rn.bf16x2.f32 %0, %1, %2;" : "=r"(r) : "f"(v1), "f"(v0)); return r;
}

// ---------------- parallel cumsum of ts (one block per batch, warp scans) ----------------
__global__ __launch_bounds__(128)
void k_ts2(const float* __restrict__ hist){
    int b = blockIdx.x;
    int t = threadIdx.x;
    int lane = t & 31, w = t >> 5;
    __shared__ float wsum[4];
    float v = fmaxf(hist[(b*Lc + t)*Dc + 5], 0.f);
    // inclusive warp scan
    float s = v;
    #pragma unroll
    for(int d = 1; d < 32; d <<= 1){
        float o = __shfl_up_sync(0xffffffffu, s, d);
        if(lane >= d) s += o;
    }
    if(lane == 31) wsum[w] = s;
    __syncthreads();
    float pre = 0.f;
    #pragma unroll
    for(int q = 0; q < 4; q++) pre += (q < w) ? wsum[q] : 0.f;
    g_ts[b*Lc + t] = s + pre;
}

// ---------------- folded weights -> bf16 padded tiles ----------------
__global__ void k_prepwb(const float* __restrict__ We2, const float* __restrict__ be2,
                         const float* __restrict__ Wa1, const float* __restrict__ Wm1,
                         const float* __restrict__ ba1, const float* __restrict__ bm1){
    int l = blockIdx.x / 129, kk = blockIdx.x % 129;
    int c = threadIdx.x;
    __shared__ float ws[Hc];
    if(kk < Hc) ws[c] = We2[l*Hc*Hc + kk*Hc + c];
    else        ws[c] = be2[l*Hc + c];
    __syncthreads();
    const float* wa = Wa1 + l*3*Hc*Hc + 2*Hc*Hc;
    const float* wm = Wm1 + l*2*Hc*Hc + Hc*Hc;
    float sa = 0.f, sm = 0.f;
    #pragma unroll 4
    for(int r = 0; r < Hc; r++){ float w = ws[r]; sa += w*wa[r*Hc + c]; sm += w*wm[r*Hc + c]; }
    if(kk < Hc){
        __nv_bfloat16* base = g_Wbf + (size_t)l*2*TILE_ELEMS;
        base[             kk*WPITCH + c] = __float2bfloat16(sa);
        base[TILE_ELEMS + kk*WPITCH + c] = __float2bfloat16(sm);
    } else {
        g_ba[l*Hc + c] = sa + ba1[l*Hc + c];
        g_bm[l*Hc + c] = sm + bm1[l*Hc + c];
    }
}

// ---------------- h0 (16 rows per block) + sa/da/sm for layer 0 ----------------
__global__ __launch_bounds__(256)
void k_h0s(const float* __restrict__ hist, const float* __restrict__ mask,
           const float* __restrict__ Wp, const float* __restrict__ bp,
           const float* __restrict__ Wa1, const float* __restrict__ Wm1){
    int row0 = blockIdx.x * 16;
    int tid = threadIdx.x;
    int c = tid & 127, ty = tid >> 7;
    __shared__ float xs[16*Dc], hs[16*Hc], vmsh[16];
    if(tid < 128) xs[tid] = hist[(size_t)row0*Dc + tid];
    if(tid < 16)  vmsh[tid] = mask[row0 + tid] > 0.f ? 1.f : 0.f;
    __syncthreads();
    float acc[8];
    #pragma unroll
    for(int p = 0; p < 8; p++) acc[p] = bp[c];
    #pragma unroll
    for(int d = 0; d < Dc; d++){
        float w = Wp[d*Hc + c];
        #pragma unroll
        for(int p = 0; p < 8; p++) acc[p] += xs[(ty*8+p)*Dc + d] * w;
    }
    #pragma unroll
    for(int p = 0; p < 8; p++){
        int r = ty*8 + p;
        float h = acc[p] * vmsh[r];
        hs[r*Hc + c] = h;
        g_h[(size_t)(row0+r)*Hc + c] = h;
    }
    __syncthreads();
    const float* was = Wa1;
    const float* wad = was + Hc*Hc;
    const float* wms = Wm1;
    float aa[8], dd[8], mm[8];
    #pragma unroll
    for(int p = 0; p < 8; p++){ aa[p]=0.f; dd[p]=0.f; mm[p]=0.f; }
    #pragma unroll 4
    for(int k = 0; k < Hc; k++){
        float w1 = was[k*Hc + c], w2 = wad[k*Hc + c], w3 = wms[k*Hc + c];
        #pragma unroll
        for(int p = 0; p < 8; p++){
            float h = hs[(ty*8+p)*Hc + k];
            aa[p] += h*w1; dd[p] += h*w2; mm[p] += h*w3;
        }
    }
    #pragma unroll
    for(int p = 0; p < 8; p++){
        size_t r = (size_t)(row0 + ty*8 + p)*Hc + c;
        g_sa[r] = aa[p]; g_da[r] = dd[p]; g_sm[r] = mm[p];
    }
}

// ---------------- main fused kernel: two HMMA phases, 32x32 warp tiles, 2 CTAs/SM ----------------
// dynamic SMEM bytes:
//   [0      , 34816 ) T     [j][136] bf16
//   [34816  , 69632 ) Wa    [k][136] bf16
//   [69632  ,104448 ) Wm
// after msg GEMM, T region reused as f32 msg partial buffer su[32][130]
extern __shared__ char dsmc[];

__global__ __launch_bounds__(512, 2)
void k_main11(int l, const float* __restrict__ hist, const float* __restrict__ mask,
              const float* __restrict__ We1, const float* __restrict__ be1,
              const float* __restrict__ wa2, const float* __restrict__ ba2){
    __shared__ float we1s[4*Hc], be1s[Hc], sab[Hc], smb[Hc], wa2s[Hc];
    __shared__ float attp[4][Lc], wsoft[Lc], red[8], redp[4][Hc];

    int bi = blockIdx.x;
    int b = bi >> 7, i = bi & 127;
    int tid = threadIdx.x;
    int wid = tid >> 5, lane = tid & 31;
    int j = tid & 127;

    // async copy both weight tiles (69632 B = 4352 x 16B)
    {
        const char* wsrc = (const char*)(g_Wbf + (size_t)l*2*TILE_ELEMS);
        char* wdst = dsmc + TILE_BYTES;
        #pragma unroll
        for(int q = 0; q < 8; q++){
            int off = (q*512 + tid)*16;
            cp16(wdst + off, wsrc + off);
        }
        if(tid < 256) cp16(wdst + (4096 + tid)*16, wsrc + (4096 + tid)*16);
        asm volatile("cp.async.commit_group;" ::: "memory");
    }

    if(tid < 128){
        #pragma unroll
        for(int q = 0; q < 4; q++) we1s[q*Hc + tid] = We1[l*4*Hc + q*Hc + tid];
        be1s[tid] = be1[l*Hc + tid];
        sab[tid]  = g_sa[(size_t)bi*Hc + tid] + g_ba[l*Hc + tid];
        smb[tid]  = g_sm[(size_t)bi*Hc + tid] + g_bm[l*Hc + tid];
        wa2s[tid] = wa2[l*Hc + tid];
    }

    // edge features for this thread's j
    const float* hb_ = hist + (size_t)b*Lc*Dc;
    float vldj, vi;
    {
        float lat_i = hb_[i*Dc + 0], lon_i = hb_[i*Dc + 1], src_i = hb_[i*Dc + 6];
        float ts_i = g_ts[b*Lc + i];
        float latj = hb_[j*Dc + 0], lonj = hb_[j*Dc + 1], srcj = hb_[j*Dc + 6];
        float tsj = g_ts[b*Lc + j];
        float dl = lat_i - latj, dn = lon_i - lonj;
        float dist = sqrtf(dl*dl + dn*dn + 1e-8f);
        float dtv = fabsf(ts_i - tsj) * (1.f/300.f);
        float ssv = (src_i == srcj) ? 1.f : 0.f;
        float diag = (j == i) ? 1.f : 0.f;
        vldj = (mask[b*Lc + j] > 0.f) ? 1.f : 0.f;
        vi   = (mask[b*Lc + i] > 0.f) ? 1.f : 0.f;
        __syncthreads();   // we1s/be1s ready

        // T build: thread owns row j, quarter q -> 32 k values (16 bf16x2 pairs)
        int q = tid >> 7;
        char* Th = dsmc + (size_t)j*272;
        #pragma unroll
        for(int kk = 0; kk < 16; kk++){
            int k = q*32 + kk*2;
            float v0 = fmaxf(dist*we1s[k]   + dtv*we1s[Hc+k]   + ssv*we1s[2*Hc+k]   + diag*we1s[3*Hc+k]   + be1s[k],   0.f);
            float v1 = fmaxf(dist*we1s[k+1] + dtv*we1s[Hc+k+1] + ssv*we1s[2*Hc+k+1] + diag*we1s[3*Hc+k+1] + be1s[k+1], 0.f);
            *(uint32_t*)(Th + k*2) = packbf2(v0, v1);
        }
    }
    asm volatile("cp.async.wait_group 0;" ::: "memory");
    __syncthreads();   // T + W ready

    // warp tile: jb = wid&3 -> jt = jb*32 rows; cb = wid>>2 -> ch = cb*32 cols
    int jb = wid & 3, cb = wid >> 2;
    int jt = jb*32, ch = cb*32;
    uint32_t base = smem_u32(dsmc);
    uint32_t aT0 = base + (uint32_t)((jt + (lane & 15))*272 + ((lane >> 4) << 4));
    uint32_t aT1 = aT0 + 16*272;
    uint32_t wBa = base + (uint32_t)(TILE_BYTES   + (lane & 15)*272 + ch*2 + ((lane >> 4) << 4));
    uint32_t wBm = wBa + (uint32_t)TILE_BYTES;
    int gq = lane >> 2, tq = lane & 3;

    // acc layout: [t16][nq][4] -> t16*16 + nq*4 ; cols = ch + nq*8 + 2tq
    float acc[32];

    // ================ PHASE A: attention GEMM (T @ Wa) ================
    #pragma unroll
    for(int q = 0; q < 32; q++) acc[q] = 0.f;
    #pragma unroll
    for(int ks = 0; ks < 8; ks++){
        uint32_t a0,a1,a2,a3, c0,c1,c2,c3;
        ldsm4(a0,a1,a2,a3, aT0 + ks*32);
        ldsm4(c0,c1,c2,c3, aT1 + ks*32);
        uint32_t wrow = wBa + ks*4352;
        uint32_t B0,B1,B2,B3, B4,B5,B6,B7;
        ldsm4t(B0,B1,B2,B3, wrow);
        ldsm4t(B4,B5,B6,B7, wrow + 32);
        mma16816(acc+0,  a0,a1,a2,a3, B0,B1);
        mma16816(acc+4,  a0,a1,a2,a3, B2,B3);
        mma16816(acc+8,  a0,a1,a2,a3, B4,B5);
        mma16816(acc+12, a0,a1,a2,a3, B6,B7);
        mma16816(acc+16, c0,c1,c2,c3, B0,B1);
        mma16816(acc+20, c0,c1,c2,c3, B2,B3);
        mma16816(acc+24, c0,c1,c2,c3, B4,B5);
        mma16816(acc+28, c0,c1,c2,c3, B6,B7);
    }
    // attention epilogue: rows jt + t16*16 + gq (+8), cols ch + nq*8 + 2tq
    #pragma unroll
    for(int t16 = 0; t16 < 2; t16++){
        int jA = jt + t16*16 + gq, jB = jA + 8;
        const float* daA = g_da + ((size_t)(b*Lc + jA))*Hc;
        const float* daB = daA + 8*Hc;
        float sA = 0.f, sB = 0.f;
        #pragma unroll
        for(int nq = 0; nq < 4; nq++){
            int c0 = ch + nq*8 + tq*2;
            const float* d = acc + t16*16 + nq*4;
            float2 dA = *(const float2*)(daA + c0);
            float2 dB = *(const float2*)(daB + c0);
            sA += wa2s[c0]  *tanh_fast(sab[c0]  + dA.x + d[0]);
            sA += wa2s[c0+1]*tanh_fast(sab[c0+1]+ dA.y + d[1]);
            sB += wa2s[c0]  *tanh_fast(sab[c0]  + dB.x + d[2]);
            sB += wa2s[c0+1]*tanh_fast(sab[c0+1]+ dB.y + d[3]);
        }
        sA += __shfl_xor_sync(0xffffffffu, sA, 1);
        sA += __shfl_xor_sync(0xffffffffu, sA, 2);
        sB += __shfl_xor_sync(0xffffffffu, sB, 1);
        sB += __shfl_xor_sync(0xffffffffu, sB, 2);
        if(tq == 0){ attp[cb][jA] = sA; attp[cb][jB] = sB; }
    }

    // ================ PHASE B: message GEMM (T @ Wm) — independent of softmax ================
    #pragma unroll
    for(int q = 0; q < 32; q++) acc[q] = 0.f;
    #pragma unroll
    for(int ks = 0; ks < 8; ks++){
        uint32_t a0,a1,a2,a3, c0,c1,c2,c3;
        ldsm4(a0,a1,a2,a3, aT0 + ks*32);
        ldsm4(c0,c1,c2,c3, aT1 + ks*32);
        uint32_t wrow = wBm + ks*4352;
        uint32_t B0,B1,B2,B3, B4,B5,B6,B7;
        ldsm4t(B0,B1,B2,B3, wrow);
        ldsm4t(B4,B5,B6,B7, wrow + 32);
        mma16816(acc+0,  a0,a1,a2,a3, B0,B1);
        mma16816(acc+4,  a0,a1,a2,a3, B2,B3);
        mma16816(acc+8,  a0,a1,a2,a3, B4,B5);
        mma16816(acc+12, a0,a1,a2,a3, B6,B7);
        mma16816(acc+16, c0,c1,c2,c3, B0,B1);
        mma16816(acc+20, c0,c1,c2,c3, B2,B3);
        mma16816(acc+24, c0,c1,c2,c3, B4,B5);
        mma16816(acc+28, c0,c1,c2,c3, B6,B7);
    }
    __syncthreads();   // attp visible; all T reads done (su can overwrite T later)

    // ================ softmax over j (first 128 threads) ================
    const float inv = 0.088388347648318440550f;   // 1/sqrt(128)
    float sc = -1e9f, e = 0.f;
    if(tid < 128){
        float a = (attp[0][tid] + attp[1][tid] + attp[2][tid] + attp[3][tid] + ba2[l]) * inv;
        bool ok = (vldj > 0.f) && (vi > 0.f);
        sc = ok ? a : -1e9f;
        float m = sc;
        #pragma unroll
        for(int s2 = 16; s2 > 0; s2 >>= 1) m = fmaxf(m, __shfl_xor_sync(0xffffffffu, m, s2));
        if((tid & 31) == 0) red[tid >> 5] = m;
    }
    __syncthreads();
    float bmax = fmaxf(fmaxf(red[0], red[1]), fmaxf(red[2], red[3]));
    if(tid < 128){
        e = expf(sc - bmax);
        float s2 = e;
        #pragma unroll
        for(int m = 16; m > 0; m >>= 1) s2 += __shfl_xor_sync(0xffffffffu, s2, m);
        if((tid & 31) == 0) red[4 + (tid >> 5)] = s2;
    }
    __syncthreads();
    if(tid < 128){
        float tot = red[4]+red[5]+red[6]+red[7];
        wsoft[tid] = e / tot;
    }
    __syncthreads();

    // ================ message epilogue: weighted relu into su[32][130] ================
    float* su = (float*)dsmc;
    {
        float v[8];
        #pragma unroll
        for(int p = 0; p < 8; p++) v[p] = 0.f;
        #pragma unroll
        for(int t16 = 0; t16 < 2; t16++){
            int jA = jt + t16*16 + gq, jB = jA + 8;
            float wA = wsoft[jA], wB2 = wsoft[jB];
            #pragma unroll
            for(int nq = 0; nq < 4; nq++){
                int c0 = ch + nq*8 + tq*2;
                const float* d = acc + t16*16 + nq*4;
                v[nq*2]   += wA*fmaxf(smb[c0]  + d[0], 0.f) + wB2*fmaxf(smb[c0]  + d[2], 0.f);
                v[nq*2+1] += wA*fmaxf(smb[c0+1]+ d[1], 0.f) + wB2*fmaxf(smb[c0+1]+ d[3], 0.f);
            }
        }
        int p = jb*8 + gq;
        #pragma unroll
        for(int nq = 0; nq < 4; nq++){
            int c0 = ch + nq*8 + tq*2;
            *(float2*)(su + p*130 + c0) = make_float2(v[nq*2], v[nq*2+1]);
        }
    }
    __syncthreads();
    {
        int qq = tid >> 7, c = tid & 127;
        float s = 0.f;
        #pragma unroll
        for(int r = 0; r < 8; r++) s += su[(qq*8 + r)*130 + c];
        redp[qq][c] = s;
    }
    __syncthreads();
    if(tid < 128){
        g_aggpre[(size_t)bi*Hc + tid] = redp[0][tid] + redp[1][tid] + redp[2][tid] + redp[3][tid];
    }
}

// ---------------- epilogue per 16 rows ----------------
__global__ __launch_bounds__(256)
void k_post2(int l, int has_next, const float* __restrict__ mask,
             const float* __restrict__ Wm2, const float* __restrict__ bm2,
             const float* __restrict__ Wo1, const float* __restrict__ bo1,
             const float* __restrict__ Wo2, const float* __restrict__ bo2,
             const float* __restrict__ lng, const float* __restrict__ lnb,
             const float* __restrict__ Wa1, const float* __restrict__ Wm1){
    int row0 = blockIdx.x * 16;
    int tid = threadIdx.x;
    int c = tid & 127, ty = tid >> 7;
    __shared__ float hs[16*Hc], as_[16*Hc], ag[16*Hc], op1[16*Hc];
    __shared__ float mu[16], rsd[16], vmsh[16];

    #pragma unroll
    for(int q = 0; q < 8; q++){
        int idx = q*256 + tid;
        hs[idx]  = g_h[(size_t)row0*Hc + idx];
        as_[idx] = g_aggpre[(size_t)row0*Hc + idx];
    }
    if(tid < 16) vmsh[tid] = mask[row0 + tid] > 0.f ? 1.f : 0.f;
    __syncthreads();

    float acc[8];
    const float* wm2 = Wm2 + l*Hc*Hc;
    #pragma unroll
    for(int p = 0; p < 8; p++) acc[p] = bm2[l*Hc + c];
    #pragma unroll 4
    for(int k = 0; k < Hc; k++){
        float w = wm2[k*Hc + c];
        #pragma unroll
        for(int p = 0; p < 8; p++) acc[p] += as_[(ty*8+p)*Hc + k] * w;
    }
    #pragma unroll
    for(int p = 0; p < 8; p++) ag[(ty*8+p)*Hc + c] = acc[p];
    __syncthreads();

    const float* wo1h = Wo1 + l*2*Hc*Hc;
    const float* wo1a = wo1h + Hc*Hc;
    #pragma unroll
    for(int p = 0; p < 8; p++) acc[p] = bo1[l*Hc + c];
    #pragma unroll 4
    for(int k = 0; k < Hc; k++){
        float w1 = wo1h[k*Hc + c], w2 = wo1a[k*Hc + c];
        #pragma unroll
        for(int p = 0; p < 8; p++)
            acc[p] += hs[(ty*8+p)*Hc + k]*w1 + ag[(ty*8+p)*Hc + k]*w2;
    }
    #pragma unroll
    for(int p = 0; p < 8; p++) op1[(ty*8+p)*Hc + c] = fmaxf(acc[p], 0.f);
    __syncthreads();

    const float* wo2 = Wo2 + l*Hc*Hc;
    #pragma unroll
    for(int p = 0; p < 8; p++) acc[p] = bo2[l*Hc + c];
    #pragma unroll 4
    for(int k = 0; k < Hc; k++){
        float w = wo2[k*Hc + c];
        #pragma unroll
        for(int p = 0; p < 8; p++) acc[p] += op1[(ty*8+p)*Hc + k] * w;
    }
    #pragma unroll
    for(int p = 0; p < 8; p++){
        int r = ty*8 + p;
        ag[r*Hc + c] = hs[r*Hc + c] + acc[p];
    }
    __syncthreads();

    {
        int row = tid >> 4, l16 = tid & 15;
        float s = 0.f, s2 = 0.f;
        #pragma unroll
        for(int q = 0; q < 8; q++){
            float v = ag[row*Hc + l16 + q*16];
            s += v; s2 += v*v;
        }
        #pragma unroll
        for(int m = 8; m > 0; m >>= 1){
            s  += __shfl_xor_sync(0xffffffffu, s, m);
            s2 += __shfl_xor_sync(0xffffffffu, s2, m);
        }
        if(l16 == 0){
            float m_ = s * (1.f/128.f);
            mu[row] = m_;
            rsd[row] = rsqrtf(s2 * (1.f/128.f) - m_*m_ + 1e-5f);
        }
    }
    __syncthreads();
    const float* lg = lng + l*Hc;
    const float* lb = lnb + l*Hc;
    #pragma unroll
    for(int p = 0; p < 8; p++){
        int r = ty*8 + p;
        float x = ag[r*Hc + c];
        float hn = ((x - mu[r]) * rsd[r] * lg[c] + lb[c]) * vmsh[r];
        g_h[(size_t)(row0+r)*Hc + c] = hn;
        hs[r*Hc + c] = hn;
    }

    if(has_next){
        __syncthreads();
        int ln = l + 1;
        const float* was = Wa1 + ln*3*Hc*Hc;
        const float* wad = was + Hc*Hc;
        const float* wms = Wm1 + ln*2*Hc*Hc;
        float aa[8], dd[8], mm[8];
        #pragma unroll
        for(int p = 0; p < 8; p++){ aa[p]=0.f; dd[p]=0.f; mm[p]=0.f; }
        #pragma unroll 4
        for(int k = 0; k < Hc; k++){
            float w1 = was[k*Hc + c], w2 = wad[k*Hc + c], w3 = wms[k*Hc + c];
            #pragma unroll
            for(int p = 0; p < 8; p++){
                float h = hs[(ty*8+p)*Hc + k];
                aa[p] += h*w1; dd[p] += h*w2; mm[p] += h*w3;
            }
        }
        #pragma unroll
        for(int p = 0; p < 8; p++){
            size_t r = (size_t)(row0 + ty*8 + p)*Hc + c;
            g_sa[r] = aa[p]; g_da[r] = dd[p]; g_sm[r] = mm[p];
        }
    }
}

// ---------------- decoder ----------------
__global__ void k_dec(const float* __restrict__ hist, const float* __restrict__ mask,
                      const float* __restrict__ hg, const float* __restrict__ hb,
                      const float* __restrict__ Wh1, const float* __restrict__ bh1,
                      const float* __restrict__ Wh2, const float* __restrict__ bh2,
                      float* __restrict__ out){
    int b = blockIdx.x; int t = threadIdx.x;
    __shared__ float x[136], xn[136], hid[Hc];
    __shared__ float red2[4];
    float mv = mask[b*Lc + t];
    float s = mv;
    #pragma unroll
    for(int sft = 16; sft > 0; sft >>= 1) s += __shfl_xor_sync(0xffffffffu, s, sft);
    if((t & 31) == 0) red2[t >> 5] = s;
    __syncthreads();
    float tot = red2[0]+red2[1]+red2[2]+red2[3];
    int vc = (int)tot;
    vc = min(max(vc, 1), Lc);
    int last = vc - 1;

    if(t < Dc) x[t] = hist[((size_t)b*Lc + last)*Dc + t];
    x[Dc + t] = g_h[((size_t)b*Lc + last)*Hc + t];
    __syncthreads();
    float s1 = x[t] + ((t < 8) ? x[128 + t] : 0.f);
    #pragma unroll
    for(int sft = 16; sft > 0; sft >>= 1) s1 += __shfl_xor_sync(0xffffffffu, s1, sft);
    __syncthreads();
    if((t & 31) == 0) red2[t >> 5] = s1;
    __syncthreads();
    float mu = (red2[0]+red2[1]+red2[2]+red2[3]) * (1.f/136.f);
    float d0 = x[t] - mu;
    float s2 = d0*d0;
    if(t < 8){ float d1 = x[128 + t] - mu; s2 += d1*d1; }
    #pragma unroll
    for(int sft = 16; sft > 0; sft >>= 1) s2 += __shfl_xor_sync(0xffffffffu, s2, sft);
    __syncthreads();
    if((t & 31) == 0) red2[t >> 5] = s2;
    __syncthreads();
    float rs = rsqrtf((red2[0]+red2[1]+red2[2]+red2[3]) * (1.f/136.f) + 1e-5f);
    xn[t] = (x[t] - mu) * rs * hg[t] + hb[t];
    if(t < 8) xn[128 + t] = (x[128 + t] - mu) * rs * hg[128 + t] + hb[128 + t];
    __syncthreads();
    float h_ = bh1[t];
    for(int k = 0; k < 136; k++) h_ += xn[k]*Wh1[k*Hc + t];
    hid[t] = fmaxf(h_, 0.f);
    __syncthreads();
    if(t < 24){
        float p = bh2[t];
        for(int k = 0; k < Hc; k++) p += hid[k]*Wh2[k*24 + t];
        if(isnan(p)) p = 0.f;
        else if(isinf(p)) p = (p > 0.f) ? 1e4f : -1e4f;
        out[b*24 + t] = p;
    }
}

__global__ void k_copyh(float* __restrict__ out){
    int i = blockIdx.x*blockDim.x + threadIdx.x;
    out[384 + i] = g_h[i];
}

// ---------------- launch ----------------
extern "C" void kernel_launch(void* const* d_in, const int* in_sizes, int n_in,
                              void* d_out, int out_size){
    const float* hist = (const float*)d_in[0];
    const float* mask = (const float*)d_in[1];
    const float* Wp   = (const float*)d_in[2];
    const float* bp   = (const float*)d_in[3];
    const float* We1  = (const float*)d_in[4];
    const float* be1  = (const float*)d_in[5];
    const float* We2  = (const float*)d_in[6];
    const float* be2  = (const float*)d_in[7];
    const float* Wa1  = (const float*)d_in[8];
    const float* ba1  = (const float*)d_in[9];
    const float* wa2  = (const float*)d_in[10];
    const float* ba2  = (const float*)d_in[11];
    const float* Wm1  = (const float*)d_in[12];
    const float* bm1  = (const float*)d_in[13];
    const float* Wm2  = (const float*)d_in[14];
    const float* bm2  = (const float*)d_in[15];
    const float* Wo1  = (const float*)d_in[16];
    const float* bo1  = (const float*)d_in[17];
    const float* Wo2  = (const float*)d_in[18];
    const float* bo2  = (const float*)d_in[19];
    const float* lng  = (const float*)d_in[20];
    const float* lnb  = (const float*)d_in[21];
    const float* hg   = (const float*)d_in[22];
    const float* hbv  = (const float*)d_in[23];
    const float* Wh1  = (const float*)d_in[24];
    const float* bh1  = (const float*)d_in[25];
    const float* Wh2  = (const float*)d_in[26];
    const float* bh2  = (const float*)d_in[27];
    float* out = (float*)d_out;

    cudaFuncSetAttribute(k_main11, cudaFuncAttributeMaxDynamicSharedMemorySize, 3*TILE_BYTES);

    k_ts2<<<Bc, 128>>>(hist);
    k_prepwb<<<NLc*129, Hc>>>(We2, be2, Wa1, Wm1, ba1, bm1);
    k_h0s<<<Bc*Lc/16, 256>>>(hist, mask, Wp, bp, Wa1, Wm1);
    for(int l = 0; l < NLc; l++){
        k_main11<<<Bc*Lc, 512, 3*TILE_BYTES>>>(l, hist, mask, We1, be1, wa2, ba2);
        k_post2<<<Bc*Lc/16, 256>>>(l, (l+1 < NLc) ? 1 : 0, mask,
                                   Wm2, bm2, Wo1, bo1, Wo2, bo2, lng, lnb, Wa1, Wm1);
    }
    k_dec<<<Bc, Hc>>>(hist, mask, hg, hbv, Wh1, bh1, Wh2, bh2, out);
    if(out_size >= 384 + Bc*Lc*Hc){
        k_copyh<<<(Bc*Lc*Hc)/256, 256>>>(out);
    }
}